// round 7
// baseline (speedup 1.0000x reference)
#include <cuda_runtime.h>
#include <cuda_bf16.h>
#include <math.h>
#include <stdint.h>

#define BB   2
#define NSEQ 2048
#define DMOD 1024
#define NH   16
#define HDIM 64
#define NC   4
#define BH   (BB * NH)

// ---------------- scratch (device globals; no allocation allowed) ----------------
__device__ float g_v[(size_t)BB * NH * NSEQ * HDIM];
__device__ float g_bias[(size_t)BB * NSEQ * NSEQ];

// bf16 split operands, pre-swizzled 128x64 SW128 tiles (16KB each)
__device__ __nv_bfloat16 gXh[(size_t)4096 * 1024];
__device__ __nv_bfloat16 gXl[(size_t)4096 * 1024];
__device__ __nv_bfloat16 gWqh[(size_t)3072 * 1024];
__device__ __nv_bfloat16 gWql[(size_t)3072 * 1024];
__device__ __nv_bfloat16 gWoh[(size_t)1024 * 1024];
__device__ __nv_bfloat16 gWol[(size_t)1024 * 1024];
__device__ __nv_bfloat16 gAh2[(size_t)4096 * 1024];
__device__ __nv_bfloat16 gAl2[(size_t)4096 * 1024];

// attention operands
__device__ __nv_bfloat16 gQh[(size_t)BH * NSEQ * HDIM];
__device__ __nv_bfloat16 gQl[(size_t)BH * NSEQ * HDIM];
__device__ __nv_bfloat16 gKh[(size_t)BH * NSEQ * HDIM];
__device__ __nv_bfloat16 gKl[(size_t)BH * NSEQ * HDIM];
__device__ __nv_bfloat16 gVth[(size_t)BH * NSEQ * HDIM];
__device__ __nv_bfloat16 gVtl[(size_t)BH * NSEQ * HDIM];

// ---------------- PTX helpers (base sm_103-legal only) ----------------
__device__ __forceinline__ uint32_t smem_u32(const void* p) {
    uint32_t a;
    asm("{ .reg .u64 t; cvta.to.shared.u64 t, %1; cvt.u32.u64 %0, t; }" : "=r"(a) : "l"(p));
    return a;
}

#define CP_ASYNC16(dst, src) \
    asm volatile("cp.async.cg.shared.global [%0], [%1], 16;" :: "r"(dst), "l"(src) : "memory")
#define CP_COMMIT() asm volatile("cp.async.commit_group;" ::: "memory")
#define CP_WAIT0()  asm volatile("cp.async.wait_group 0;" ::: "memory")

#define LDMX4(r, a) \
    asm volatile("ldmatrix.sync.aligned.m8n8.x4.shared.b16 {%0,%1,%2,%3}, [%4];" \
        : "=r"((r)[0]), "=r"((r)[1]), "=r"((r)[2]), "=r"((r)[3]) : "r"(a))

__device__ __forceinline__ void mma_bf16(float* d, uint32_t a0, uint32_t a1,
                                         uint32_t a2, uint32_t a3,
                                         uint32_t b0, uint32_t b1) {
    asm volatile(
        "mma.sync.aligned.m16n8k16.row.col.f32.bf16.bf16.f32 "
        "{%0,%1,%2,%3},{%4,%5,%6,%7},{%8,%9},{%0,%1,%2,%3};"
        : "+f"(d[0]), "+f"(d[1]), "+f"(d[2]), "+f"(d[3])
        : "r"(a0), "r"(a1), "r"(a2), "r"(a3), "r"(b0), "r"(b1));
}

__device__ __forceinline__ uint32_t pack2_bf16(float lo, float hi) {
    uint32_t r;
    asm("cvt.rn.bf16x2.f32 %0, %1, %2;" : "=r"(r) : "f"(hi), "f"(lo));
    return r;
}
__device__ __forceinline__ uint32_t pack2_hi(uint32_t u0, uint32_t u1) {
    uint32_t r;
    asm("prmt.b32 %0, %1, %2, 0x7632;" : "=r"(r) : "r"(u0), "r"(u1));
    return r;
}
__device__ __forceinline__ float ex2f(float x) {
    float r;
    asm("ex2.approx.f32 %0, %1;" : "=f"(r) : "f"(x));
    return r;
}

// ---------------- split-conversion: fp32 row-major -> blocked swizzled bf16 hi/lo ----------------
__global__ void __launch_bounds__(256)
conv_split_kernel(const float* __restrict__ src, __nv_bfloat16* __restrict__ dh,
                  __nv_bfloat16* __restrict__ dl, int K)
{
    size_t idx = ((size_t)blockIdx.x * 256 + threadIdx.x) * 8;
    int r  = (int)(idx / K);
    int c0 = (int)(idx % K);
    float4 v0 = *(const float4*)(src + idx);
    float4 v1 = *(const float4*)(src + idx + 4);
    float f[8] = {v0.x, v0.y, v0.z, v0.w, v1.x, v1.y, v1.z, v1.w};
    __nv_bfloat16 h[8], l[8];
#pragma unroll
    for (int i = 0; i < 8; i++) {
        h[i] = __float2bfloat16(f[i]);
        l[i] = __float2bfloat16(f[i] - __bfloat162float(h[i]));
    }
    int rt = r >> 7, lr = r & 127, ch = c0 >> 6, lc = c0 & 63;
    size_t tile = (size_t)rt * (K >> 6) + ch;
    uint32_t off = lr * 128 + lc * 2;
    uint32_t sw = off ^ ((off >> 3) & 0x70);
    size_t db = tile * 16384 + sw;
    *(uint4*)((char*)dh + db) = *(uint4*)h;
    *(uint4*)((char*)dl + db) = *(uint4*)l;
}

// ---------------- HMMA GEMM: 512 threads, 16 warps (8m x 2n), warp tile 16x64 ----------------
// Single-sync double-buffered smem pipeline + register fragment double-buffering.
#define GEMM_SMEM (2 * 4 * 16384)

template <int MODE>
__global__ void __launch_bounds__(512)
gemm_hmma(const char* __restrict__ Ah, const char* __restrict__ Al,
          const char* __restrict__ Bh, const char* __restrict__ Bl,
          float* __restrict__ Cout, int KC, int Nt,
          const float* __restrict__ qw, const float* __restrict__ kw)
{
    extern __shared__ char smraw[];
    const uint32_t smemS = smem_u32(smraw);
    const int tid  = threadIdx.x;
    const int lane = tid & 31;
    const int warp = tid >> 5;
    const int wm = warp & 7;
    const int wn = warp >> 3;

    const size_t tA0 = (size_t)blockIdx.y * KC * 16384;
    const size_t tB0 = (size_t)blockIdx.x * KC * 16384;

    float acc[8][4];
#pragma unroll
    for (int j = 0; j < 8; j++)
#pragma unroll
        for (int t = 0; t < 4; t++) acc[j][t] = 0.f;

    const int lrow = lane & 15;
    const int cb   = (lane >> 4) << 4;

    // prologue: chunk 0 into buffer 0
    {
        const char* s0 = Ah + tA0 + tid * 16;
        const char* s1 = Al + tA0 + tid * 16;
        const char* s2 = Bh + tB0 + tid * 16;
        const char* s3 = Bl + tB0 + tid * 16;
        uint32_t d0 = smemS + tid * 16;
#pragma unroll
        for (int i = 0; i < 2; i++) {
            CP_ASYNC16(d0 + 0 * 16384 + i * 8192, s0 + i * 8192);
            CP_ASYNC16(d0 + 1 * 16384 + i * 8192, s1 + i * 8192);
            CP_ASYNC16(d0 + 2 * 16384 + i * 8192, s2 + i * 8192);
            CP_ASYNC16(d0 + 3 * 16384 + i * 8192, s3 + i * 8192);
        }
        CP_COMMIT();
    }

    const int arow = wm * 16 + lrow;
    const uint32_t aswz = (uint32_t)((arow & 7) << 4);
    const uint32_t abase = arow * 128 + cb;
    const int brow0 = wn * 64 + lrow;

    for (int kc = 0; kc < KC; kc++) {
        CP_WAIT0();
        __syncthreads();
        if (kc + 1 < KC) {
            size_t go = (size_t)(kc + 1) * 16384;
            const char* s0 = Ah + tA0 + go + tid * 16;
            const char* s1 = Al + tA0 + go + tid * 16;
            const char* s2 = Bh + tB0 + go + tid * 16;
            const char* s3 = Bl + tB0 + go + tid * 16;
            uint32_t d0 = smemS + ((kc + 1) & 1) * 65536 + tid * 16;
#pragma unroll
            for (int i = 0; i < 2; i++) {
                CP_ASYNC16(d0 + 0 * 16384 + i * 8192, s0 + i * 8192);
                CP_ASYNC16(d0 + 1 * 16384 + i * 8192, s1 + i * 8192);
                CP_ASYNC16(d0 + 2 * 16384 + i * 8192, s2 + i * 8192);
                CP_ASYNC16(d0 + 3 * 16384 + i * 8192, s3 + i * 8192);
            }
            CP_COMMIT();
        }

        uint32_t buf = smemS + (kc & 1) * 65536;
        const uint32_t aHs = buf, aLs = buf + 16384, bHs = buf + 32768, bLs = buf + 49152;

        uint32_t ah[2][4], al[2][4], bh[2][4], bl[2][4];
        {
            uint32_t sw = abase ^ aswz;
            LDMX4(ah[0], aHs + sw);
            LDMX4(al[0], aLs + sw);
        }
        {
            uint32_t sw = (uint32_t)(brow0 * 128 + cb) ^ ((brow0 & 7) << 4);
            LDMX4(bh[0], bHs + sw);
            LDMX4(bl[0], bLs + sw);
        }

#pragma unroll
        for (int ks = 0; ks < 4; ks++) {
#pragma unroll
            for (int nf2 = 0; nf2 < 4; nf2++) {
                const int cur = (ks * 4 + nf2) & 1, nxt = cur ^ 1;
                if (nf2 < 3) {
                    int row = wn * 64 + (nf2 + 1) * 16 + lrow;
                    uint32_t sw = (uint32_t)(row * 128 + ks * 32 + cb) ^ ((row & 7) << 4);
                    LDMX4(bh[nxt], bHs + sw);
                    LDMX4(bl[nxt], bLs + sw);
                } else if (ks < 3) {
                    uint32_t swA = (abase + (ks + 1) * 32) ^ aswz;
                    LDMX4(ah[(ks + 1) & 1], aHs + swA);
                    LDMX4(al[(ks + 1) & 1], aLs + swA);
                    uint32_t sw = (uint32_t)(brow0 * 128 + (ks + 1) * 32 + cb) ^ ((brow0 & 7) << 4);
                    LDMX4(bh[nxt], bHs + sw);
                    LDMX4(bl[nxt], bLs + sw);
                }
                const int ka = ks & 1;
                float* d0 = acc[2 * nf2];
                float* d1 = acc[2 * nf2 + 1];
                mma_bf16(d0, ah[ka][0], ah[ka][1], ah[ka][2], ah[ka][3], bh[cur][0], bh[cur][2]);
                mma_bf16(d0, ah[ka][0], ah[ka][1], ah[ka][2], ah[ka][3], bl[cur][0], bl[cur][2]);
                mma_bf16(d0, al[ka][0], al[ka][1], al[ka][2], al[ka][3], bh[cur][0], bh[cur][2]);
                mma_bf16(d1, ah[ka][0], ah[ka][1], ah[ka][2], ah[ka][3], bh[cur][1], bh[cur][3]);
                mma_bf16(d1, ah[ka][0], ah[ka][1], ah[ka][2], ah[ka][3], bl[cur][1], bl[cur][3]);
                mma_bf16(d1, al[ka][0], al[ka][1], al[ka][2], al[ka][3], bh[cur][1], bh[cur][3]);
            }
        }
    }

    const int r0l = lane >> 2;
    const int c2  = (lane & 3) * 2;

    if (MODE == 0) {
        const int m0 = blockIdx.y * 128 + wm * 16 + r0l;
        const int n0 = blockIdx.x * 128 + wn * 64;
#pragma unroll
        for (int nf = 0; nf < 8; nf++) {
            int n = n0 + nf * 8 + c2;
            *(float2*)(Cout + (size_t)m0 * Nt + n)       = make_float2(acc[nf][0], acc[nf][1]);
            *(float2*)(Cout + (size_t)(m0 + 8) * Nt + n) = make_float2(acc[nf][2], acc[nf][3]);
        }
    } else {
        const int j = blockIdx.x * 2 + wn;
        const int which = j >> 4;
        const int h = j & 15;
        const int m0 = blockIdx.y * 128 + wm * 16 + r0l;
        const int m1 = m0 + 8;
        const int b0i = m0 >> 11, n0i = m0 & 2047;
        const int b1i = m1 >> 11, n1i = m1 & 2047;

        if (which == 2) {
            float* vb = g_v;
#pragma unroll
            for (int nf = 0; nf < 8; nf++) {
                int dd = nf * 8 + c2;
                *(float2*)&vb[(((size_t)(b0i * NH + h)) * NSEQ + n0i) * HDIM + dd] =
                    make_float2(acc[nf][0], acc[nf][1]);
                *(float2*)&vb[(((size_t)(b1i * NH + h)) * NSEQ + n1i) * HDIM + dd] =
                    make_float2(acc[nf][2], acc[nf][3]);
            }
        } else {
            const float* w = (which == 0) ? qw : kw;
            char* dh = (which == 0) ? (char*)gQh : (char*)gKh;
            char* dl = (which == 0) ? (char*)gQl : (char*)gKl;
            float ss0 = 0.f, ss1 = 0.f;
#pragma unroll
            for (int nf = 0; nf < 8; nf++) {
                ss0 += acc[nf][0] * acc[nf][0] + acc[nf][1] * acc[nf][1];
                ss1 += acc[nf][2] * acc[nf][2] + acc[nf][3] * acc[nf][3];
            }
            ss0 += __shfl_xor_sync(0xffffffffu, ss0, 1);
            ss0 += __shfl_xor_sync(0xffffffffu, ss0, 2);
            ss1 += __shfl_xor_sync(0xffffffffu, ss1, 1);
            ss1 += __shfl_xor_sync(0xffffffffu, ss1, 2);
            float r0 = rsqrtf(ss0 * (1.0f / HDIM) + 1e-6f);
            float r1 = rsqrtf(ss1 * (1.0f / HDIM) + 1e-6f);

            size_t tb0 = (((size_t)(b0i * NH + h)) * 16 + (n0i >> 7)) * 16384;
            size_t tb1 = (((size_t)(b1i * NH + h)) * 16 + (n1i >> 7)) * 16384;
            int lr0 = n0i & 127, lr1 = n1i & 127;
            uint32_t x0 = (lr0 & 7) << 4, x1 = (lr1 & 7) << 4;
#pragma unroll
            for (int nf = 0; nf < 8; nf++) {
                int dd = nf * 8 + c2;
                float2 wv = *(const float2*)(w + dd);
                float v0 = acc[nf][0] * r0 * wv.x;
                float v1 = acc[nf][1] * r0 * wv.y;
                float v2 = acc[nf][2] * r1 * wv.x;
                float v3 = acc[nf][3] * r1 * wv.y;
                uint32_t u0 = __float_as_uint(v0), u1 = __float_as_uint(v1);
                uint32_t u2 = __float_as_uint(v2), u3 = __float_as_uint(v3);
                uint32_t o0 = (lr0 * 128 + dd * 2) ^ x0;
                uint32_t o1 = (lr1 * 128 + dd * 2) ^ x1;
                *(uint32_t*)(dh + tb0 + o0) = pack2_hi(u0, u1);
                *(uint32_t*)(dh + tb1 + o1) = pack2_hi(u2, u3);
                *(uint32_t*)(dl + tb0 + o0) =
                    pack2_bf16(v0 - __uint_as_float(u0 & 0xFFFF0000u),
                               v1 - __uint_as_float(u1 & 0xFFFF0000u));
                *(uint32_t*)(dl + tb1 + o1) =
                    pack2_bf16(v2 - __uint_as_float(u2 & 0xFFFF0000u),
                               v3 - __uint_as_float(u3 & 0xFFFF0000u));
            }
        }
    }
}

// ---------------- V transpose + split ----------------
__global__ void __launch_bounds__(256)
vsplit_kernel()
{
    __shared__ float stg[64][65];
    const int kt = blockIdx.x, bh = blockIdx.y;
    const int tid = threadIdx.x;
    {
        int s = tid >> 2, d0 = (tid & 3) * 16;
        const float* vp = g_v + ((size_t)bh * NSEQ + kt * 64 + s) * HDIM + d0;
#pragma unroll
        for (int i = 0; i < 4; i++) {
            float4 v = *(const float4*)(vp + i * 4);
            stg[s][d0 + i * 4 + 0] = v.x;
            stg[s][d0 + i * 4 + 1] = v.y;
            stg[s][d0 + i * 4 + 2] = v.z;
            stg[s][d0 + i * 4 + 3] = v.w;
        }
    }
    __syncthreads();
    {
        int dR = tid >> 2, c0 = (tid & 3) * 16;
        uint32_t hw[8], lw[8];
#pragma unroll
        for (int j = 0; j < 8; j++) {
            float f0 = stg[c0 + 2 * j][dR];
            float f1 = stg[c0 + 2 * j + 1][dR];
            uint32_t u0 = __float_as_uint(f0), u1 = __float_as_uint(f1);
            hw[j] = pack2_hi(u0, u1);
            float l0 = f0 - __uint_as_float(u0 & 0xFFFF0000u);
            float l1 = f1 - __uint_as_float(u1 & 0xFFFF0000u);
            lw[j] = pack2_bf16(l0, l1);
        }
        size_t tb = ((size_t)bh * 32 + kt) * 8192;
        uint32_t off0 = dR * 128 + c0 * 2;
        uint32_t x = (dR & 7) << 4;
        *(uint4*)((char*)gVth + tb + (off0 ^ x))        = make_uint4(hw[0], hw[1], hw[2], hw[3]);
        *(uint4*)((char*)gVth + tb + ((off0 + 16) ^ x)) = make_uint4(hw[4], hw[5], hw[6], hw[7]);
        *(uint4*)((char*)gVtl + tb + (off0 ^ x))        = make_uint4(lw[0], lw[1], lw[2], lw[3]);
        *(uint4*)((char*)gVtl + tb + ((off0 + 16) ^ x)) = make_uint4(lw[4], lw[5], lw[6], lw[7]);
    }
}

// ---------------- bias precompute ----------------
__global__ void __launch_bounds__(256)
bias_kernel(const float* __restrict__ cm, const float* __restrict__ im)
{
    int bq = blockIdx.x;
    int b = bq / NSEQ, q = bq % NSEQ;
    const float* cmb = cm + (size_t)b * NC * NSEQ;
    float c0 = cmb[q], c1 = cmb[NSEQ + q], c2 = cmb[2 * NSEQ + q], c3 = cmb[3 * NSEQ + q];

    float mx = 0.f;
    for (int k = threadIdx.x; k < NSEQ; k += 256) {
        float s = c0 * cmb[k] + c1 * cmb[NSEQ + k] + c2 * cmb[2 * NSEQ + k] + c3 * cmb[3 * NSEQ + k];
        mx = fmaxf(mx, s);
    }
    __shared__ float red[8];
#pragma unroll
    for (int o = 16; o > 0; o >>= 1) mx = fmaxf(mx, __shfl_xor_sync(0xffffffffu, mx, o));
    if ((threadIdx.x & 31) == 0) red[threadIdx.x >> 5] = mx;
    __syncthreads();
    if (threadIdx.x == 0) {
        float m = red[0];
#pragma unroll
        for (int wN = 1; wN < 8; wN++) m = fmaxf(m, red[wN]);
        red[0] = fmaxf(m, 1e-6f);
    }
    __syncthreads();
    float inv = 1.f / red[0];
    const float* imr = im + (size_t)bq * NSEQ;
    float* br = g_bias + (size_t)bq * NSEQ;
    for (int k = threadIdx.x; k < NSEQ; k += 256) {
        float s = c0 * cmb[k] + c1 * cmb[NSEQ + k] + c2 * cmb[2 * NSEQ + k] + c3 * cmb[3 * NSEQ + k];
        br[k] = 2.f * s * inv - 1.f + 0.3f * imr[k];
    }
}

// ---------------- HMMA flash attention (single-sync pipeline, frag double-buffering, ex2) ----------------
#define ATTN2_SMEM 98304

__global__ void __launch_bounds__(256)
attn2_kernel(const float* __restrict__ gate)
{
    extern __shared__ char smraw[];
    const uint32_t S = smem_u32(smraw);
    const int tid = threadIdx.x, lane = tid & 31, warp = tid >> 5;
    const int bh = blockIdx.y, b = bh >> 4, h = bh & 15;
    const int qt = blockIdx.x, q0 = qt * 128;
    const float LOG2E = 1.44269504f;
    const float g32 = 3.f * fminf(fmaxf(gate[h], 0.f), 1.f) * LOG2E;
    const float SC = 0.125f * LOG2E;
    const int lrow = lane & 15, cb = (lane >> 4) << 4;
    const int wrow = warp * 16;

    // prologue: one commit group = Q tiles + KV tile 0
    {
        size_t qoff = ((size_t)(bh * 16 + qt)) * 16384 + tid * 16;
        uint32_t d = S + tid * 16;
#pragma unroll
        for (int i = 0; i < 4; i++) {
            CP_ASYNC16(d + i * 4096,         (const char*)gQh + qoff + i * 4096);
            CP_ASYNC16(d + 16384 + i * 4096, (const char*)gQl + qoff + i * 4096);
        }
        size_t koff = ((size_t)(bh * 16)) * 16384 + tid * 16;
        size_t voff = ((size_t)(bh * 32)) * 8192 + tid * 16;
        uint32_t dk = S + 32768 + tid * 16;
#pragma unroll
        for (int i = 0; i < 2; i++) {
            CP_ASYNC16(dk + 0     + i * 4096, (const char*)gKh  + koff + i * 4096);
            CP_ASYNC16(dk + 8192  + i * 4096, (const char*)gKl  + koff + i * 4096);
            CP_ASYNC16(dk + 16384 + i * 4096, (const char*)gVth + voff + i * 4096);
            CP_ASYNC16(dk + 24576 + i * 4096, (const char*)gVtl + voff + i * 4096);
        }
        CP_COMMIT();
    }

    uint32_t qh[4][4], ql[4][4];
    float o[8][4];
#pragma unroll
    for (int nf = 0; nf < 8; nf++)
#pragma unroll
        for (int t = 0; t < 4; t++) o[nf][t] = 0.f;
    float m0r = -1e30f, m1r = -1e30f, l0r = 0.f, l1r = 0.f;

    const int r0l = lane >> 2;
    const float* bias0 = g_bias + ((size_t)(b * NSEQ + q0 + wrow + r0l)) * NSEQ;
    const float* bias1 = bias0 + 8 * NSEQ;
    const uint32_t lswz = (uint32_t)((lrow & 7) << 4);

    for (int kt = 0; kt < 32; kt++) {
        CP_WAIT0();
        __syncthreads();
        if (kt + 1 < 32) {
            int k2 = kt + 1;
            size_t koff = ((size_t)(bh * 16 + (k2 >> 1))) * 16384 + (size_t)(k2 & 1) * 8192 + tid * 16;
            size_t voff = ((size_t)(bh * 32 + k2)) * 8192 + tid * 16;
            uint32_t d = S + 32768 + (k2 & 1) * 32768 + tid * 16;
#pragma unroll
            for (int i = 0; i < 2; i++) {
                CP_ASYNC16(d + 0     + i * 4096, (const char*)gKh  + koff + i * 4096);
                CP_ASYNC16(d + 8192  + i * 4096, (const char*)gKl  + koff + i * 4096);
                CP_ASYNC16(d + 16384 + i * 4096, (const char*)gVth + voff + i * 4096);
                CP_ASYNC16(d + 24576 + i * 4096, (const char*)gVtl + voff + i * 4096);
            }
            CP_COMMIT();
        }

        if (kt == 0) {
#pragma unroll
            for (int ks = 0; ks < 4; ks++) {
                uint32_t off = (wrow + lrow) * 128 + ks * 32 + cb;
                uint32_t sw = off ^ (((wrow + lrow) & 7) << 4);
                LDMX4(qh[ks], S + sw);
                LDMX4(ql[ks], S + 16384 + sw);
            }
        }

        uint32_t buf = S + 32768 + (kt & 1) * 32768;

        // --- S = Q K^T (3-term split, frag double-buffered) ---
        float sf[8][4];
#pragma unroll
        for (int nf = 0; nf < 8; nf++)
#pragma unroll
            for (int t = 0; t < 4; t++) sf[nf][t] = 0.f;

        uint32_t kh2[2][4], kl2[2][4];
        {
            uint32_t sw = (uint32_t)(lrow * 128 + cb) ^ lswz;
            LDMX4(kh2[0], buf + sw);
            LDMX4(kl2[0], buf + 8192 + sw);
        }
#pragma unroll
        for (int ks = 0; ks < 4; ks++) {
#pragma unroll
            for (int nf2 = 0; nf2 < 4; nf2++) {
                const int cur = (ks * 4 + nf2) & 1, nxt = cur ^ 1;
                if (nf2 < 3) {
                    int row = (nf2 + 1) * 16 + lrow;
                    uint32_t sw = (uint32_t)(row * 128 + ks * 32 + cb) ^ ((row & 7) << 4);
                    LDMX4(kh2[nxt], buf + sw);
                    LDMX4(kl2[nxt], buf + 8192 + sw);
                } else if (ks < 3) {
                    uint32_t sw = (uint32_t)(lrow * 128 + (ks + 1) * 32 + cb) ^ lswz;
                    LDMX4(kh2[nxt], buf + sw);
                    LDMX4(kl2[nxt], buf + 8192 + sw);
                }
                float* d0 = sf[2 * nf2];
                float* d1 = sf[2 * nf2 + 1];
                mma_bf16(d0, qh[ks][0], qh[ks][1], qh[ks][2], qh[ks][3], kh2[cur][0], kh2[cur][2]);
                mma_bf16(d0, qh[ks][0], qh[ks][1], qh[ks][2], qh[ks][3], kl2[cur][0], kl2[cur][2]);
                mma_bf16(d0, ql[ks][0], ql[ks][1], ql[ks][2], ql[ks][3], kh2[cur][0], kh2[cur][2]);
                mma_bf16(d1, qh[ks][0], qh[ks][1], qh[ks][2], qh[ks][3], kh2[cur][1], kh2[cur][3]);
                mma_bf16(d1, qh[ks][0], qh[ks][1], qh[ks][2], qh[ks][3], kl2[cur][1], kl2[cur][3]);
                mma_bf16(d1, ql[ks][0], ql[ks][1], ql[ks][2], ql[ks][3], kh2[cur][1], kh2[cur][3]);
            }
        }

        // --- scale + gated bias + online softmax (log2 domain) ---
        int colbase = kt * 64 + 2 * (lane & 3);
        float rm0 = -1e30f, rm1 = -1e30f;
#pragma unroll
        for (int nf = 0; nf < 8; nf++) {
            float2 bb0 = *(const float2*)(bias0 + colbase + nf * 8);
            float2 bb1 = *(const float2*)(bias1 + colbase + nf * 8);
            sf[nf][0] = fmaf(sf[nf][0], SC, g32 * bb0.x);
            sf[nf][1] = fmaf(sf[nf][1], SC, g32 * bb0.y);
            sf[nf][2] = fmaf(sf[nf][2], SC, g32 * bb1.x);
            sf[nf][3] = fmaf(sf[nf][3], SC, g32 * bb1.y);
            rm0 = fmaxf(rm0, fmaxf(sf[nf][0], sf[nf][1]));
            rm1 = fmaxf(rm1, fmaxf(sf[nf][2], sf[nf][3]));
        }
        rm0 = fmaxf(rm0, __shfl_xor_sync(0xffffffffu, rm0, 1));
        rm0 = fmaxf(rm0, __shfl_xor_sync(0xffffffffu, rm0, 2));
        rm1 = fmaxf(rm1, __shfl_xor_sync(0xffffffffu, rm1, 1));
        rm1 = fmaxf(rm1, __shfl_xor_sync(0xffffffffu, rm1, 2));

        float mn0 = fmaxf(m0r, rm0), mn1 = fmaxf(m1r, rm1);
        float al0 = ex2f(m0r - mn0), al1 = ex2f(m1r - mn1);
        m0r = mn0; m1r = mn1;
        float rs0 = 0.f, rs1 = 0.f;
#pragma unroll
        for (int nf = 0; nf < 8; nf++) {
            sf[nf][0] = ex2f(sf[nf][0] - mn0);
            sf[nf][1] = ex2f(sf[nf][1] - mn0);
            sf[nf][2] = ex2f(sf[nf][2] - mn1);
            sf[nf][3] = ex2f(sf[nf][3] - mn1);
            rs0 += sf[nf][0] + sf[nf][1];
            rs1 += sf[nf][2] + sf[nf][3];
        }
        rs0 += __shfl_xor_sync(0xffffffffu, rs0, 1);
        rs0 += __shfl_xor_sync(0xffffffffu, rs0, 2);
        rs1 += __shfl_xor_sync(0xffffffffu, rs1, 1);
        rs1 += __shfl_xor_sync(0xffffffffu, rs1, 2);
        l0r = l0r * al0 + rs0;
        l1r = l1r * al1 + rs1;
#pragma unroll
        for (int nf = 0; nf < 8; nf++) {
            o[nf][0] *= al0; o[nf][1] *= al0;
            o[nf][2] *= al1; o[nf][3] *= al1;
        }

        // --- O += P V (P in regs, V frags double-buffered) ---
        const uint32_t vHs = buf + 16384, vLs = buf + 24576;
        uint32_t vh2[2][4], vl2[2][4];
        {
            uint32_t sw = (uint32_t)(lrow * 128 + cb) ^ lswz;
            LDMX4(vh2[0], vHs + sw);
            LDMX4(vl2[0], vLs + sw);
        }
#pragma unroll
        for (int kk = 0; kk < 4; kk++) {
            const int na = 2 * kk, nb = 2 * kk + 1;
            uint32_t u0 = __float_as_uint(sf[na][0]), u1 = __float_as_uint(sf[na][1]);
            uint32_t u2 = __float_as_uint(sf[na][2]), u3 = __float_as_uint(sf[na][3]);
            uint32_t w0 = __float_as_uint(sf[nb][0]), w1 = __float_as_uint(sf[nb][1]);
            uint32_t w2 = __float_as_uint(sf[nb][2]), w3 = __float_as_uint(sf[nb][3]);
            uint32_t ph_[4], pl_[4];
            ph_[0] = pack2_hi(u0, u1);
            ph_[1] = pack2_hi(u2, u3);
            ph_[2] = pack2_hi(w0, w1);
            ph_[3] = pack2_hi(w2, w3);
            pl_[0] = pack2_bf16(sf[na][0] - __uint_as_float(u0 & 0xFFFF0000u),
                                sf[na][1] - __uint_as_float(u1 & 0xFFFF0000u));
            pl_[1] = pack2_bf16(sf[na][2] - __uint_as_float(u2 & 0xFFFF0000u),
                                sf[na][3] - __uint_as_float(u3 & 0xFFFF0000u));
            pl_[2] = pack2_bf16(sf[nb][0] - __uint_as_float(w0 & 0xFFFF0000u),
                                sf[nb][1] - __uint_as_float(w1 & 0xFFFF0000u));
            pl_[3] = pack2_bf16(sf[nb][2] - __uint_as_float(w2 & 0xFFFF0000u),
                                sf[nb][3] - __uint_as_float(w3 & 0xFFFF0000u));
#pragma unroll
            for (int nf2 = 0; nf2 < 4; nf2++) {
                const int cur = (kk * 4 + nf2) & 1, nxt = cur ^ 1;
                if (nf2 < 3) {
                    int row = (nf2 + 1) * 16 + lrow;
                    uint32_t sw = (uint32_t)(row * 128 + kk * 32 + cb) ^ ((row & 7) << 4);
                    LDMX4(vh2[nxt], vHs + sw);
                    LDMX4(vl2[nxt], vLs + sw);
                } else if (kk < 3) {
                    uint32_t sw = (uint32_t)(lrow * 128 + (kk + 1) * 32 + cb) ^ lswz;
                    LDMX4(vh2[nxt], vHs + sw);
                    LDMX4(vl2[nxt], vLs + sw);
                }
                float* d0 = o[2 * nf2];
                float* d1 = o[2 * nf2 + 1];
                mma_bf16(d0, ph_[0], ph_[1], ph_[2], ph_[3], vh2[cur][0], vh2[cur][2]);
                mma_bf16(d0, ph_[0], ph_[1], ph_[2], ph_[3], vl2[cur][0], vl2[cur][2]);
                mma_bf16(d0, pl_[0], pl_[1], pl_[2], pl_[3], vh2[cur][0], vh2[cur][2]);
                mma_bf16(d1, ph_[0], ph_[1], ph_[2], ph_[3], vh2[cur][1], vh2[cur][3]);
                mma_bf16(d1, ph_[0], ph_[1], ph_[2], ph_[3], vl2[cur][1], vl2[cur][3]);
                mma_bf16(d1, pl_[0], pl_[1], pl_[2], pl_[3], vh2[cur][1], vh2[cur][3]);
            }
        }
    }

    // epilogue: normalize + write bf16 hi/lo swizzled A-tile for the out-projection
    float i0 = 1.f / l0r, i1 = 1.f / l1r;
    size_t tb = (((size_t)(b * 16 + qt)) * 16 + h) * 16384;
    int lr0 = wrow + r0l, lr1 = lr0 + 8;
    uint32_t x0 = (lr0 & 7) << 4, x1 = (lr1 & 7) << 4;
#pragma unroll
    for (int nf = 0; nf < 8; nf++) {
        int dd = nf * 8 + 2 * (lane & 3);
        float v0 = o[nf][0] * i0, v1 = o[nf][1] * i0;
        float v2 = o[nf][2] * i1, v3 = o[nf][3] * i1;
        uint32_t u0 = __float_as_uint(v0), u1 = __float_as_uint(v1);
        uint32_t u2 = __float_as_uint(v2), u3 = __float_as_uint(v3);
        uint32_t o0 = (lr0 * 128 + dd * 2) ^ x0;
        uint32_t o1 = (lr1 * 128 + dd * 2) ^ x1;
        *(uint32_t*)((char*)gAh2 + tb + o0) = pack2_hi(u0, u1);
        *(uint32_t*)((char*)gAh2 + tb + o1) = pack2_hi(u2, u3);
        *(uint32_t*)((char*)gAl2 + tb + o0) =
            pack2_bf16(v0 - __uint_as_float(u0 & 0xFFFF0000u),
                       v1 - __uint_as_float(u1 & 0xFFFF0000u));
        *(uint32_t*)((char*)gAl2 + tb + o1) =
            pack2_bf16(v2 - __uint_as_float(u2 & 0xFFFF0000u),
                       v3 - __uint_as_float(u3 & 0xFFFF0000u));
    }
}

// ---------------- launch ----------------
extern "C" void kernel_launch(void* const* d_in, const int* in_sizes, int n_in,
                              void* d_out, int out_size)
{
    (void)in_sizes; (void)n_in; (void)out_size;
    const float* x    = (const float*)d_in[0];
    const float* cm   = (const float*)d_in[1];
    const float* im   = (const float*)d_in[2];
    const float* wqkv = (const float*)d_in[3];
    const float* wout = (const float*)d_in[4];
    const float* qnw  = (const float*)d_in[5];
    const float* knw  = (const float*)d_in[6];
    const float* gate = (const float*)d_in[7];
    float* out = (float*)d_out;

    void *xh, *xl, *wqh, *wql, *woh, *wol, *ah2, *al2;
    cudaGetSymbolAddress(&xh, gXh);   cudaGetSymbolAddress(&xl, gXl);
    cudaGetSymbolAddress(&wqh, gWqh); cudaGetSymbolAddress(&wql, gWql);
    cudaGetSymbolAddress(&woh, gWoh); cudaGetSymbolAddress(&wol, gWol);
    cudaGetSymbolAddress(&ah2, gAh2); cudaGetSymbolAddress(&al2, gAl2);

    cudaFuncSetAttribute(attn2_kernel, cudaFuncAttributeMaxDynamicSharedMemorySize, ATTN2_SMEM);
    cudaFuncSetAttribute(gemm_hmma<0>, cudaFuncAttributeMaxDynamicSharedMemorySize, GEMM_SMEM);
    cudaFuncSetAttribute(gemm_hmma<1>, cudaFuncAttributeMaxDynamicSharedMemorySize, GEMM_SMEM);

    const int M = BB * NSEQ;   // 4096

    // 1) split-convert inputs
    conv_split_kernel<<<(4096 * 1024 / 8) / 256, 256>>>(x,    (__nv_bfloat16*)xh,  (__nv_bfloat16*)xl,  1024);
    conv_split_kernel<<<(3072 * 1024 / 8) / 256, 256>>>(wqkv, (__nv_bfloat16*)wqh, (__nv_bfloat16*)wql, 1024);
    conv_split_kernel<<<(1024 * 1024 / 8) / 256, 256>>>(wout, (__nv_bfloat16*)woh, (__nv_bfloat16*)wol, 1024);

    // 2) QKV projection (HMMA) with fused RMSNorm + split epilogue
    gemm_hmma<1><<<dim3(3 * DMOD / 128, M / 128), 512, GEMM_SMEM>>>(
        (const char*)xh, (const char*)xl, (const char*)wqh, (const char*)wql,
        nullptr, 1024 / 64, 3 * DMOD, qnw, knw);

    // 3) V -> transposed bf16 hi/lo tiles
    vsplit_kernel<<<dim3(NSEQ / 64, BH), 256>>>();

    // 4) bias precompute
    bias_kernel<<<BB * NSEQ, 256>>>(cm, im);

    // 5) HMMA flash attention (writes split A-tiles for out-proj directly)
    attn2_kernel<<<dim3(NSEQ / 128, BH), 256, ATTN2_SMEM>>>(gate);

    // 6) out-projection straight into d_out
    gemm_hmma<0><<<dim3(DMOD / 128, M / 128), 512, GEMM_SMEM>>>(
        (const char*)ah2, (const char*)al2, (const char*)woh, (const char*)wol,
        out, 1024 / 64, DMOD, nullptr, nullptr);
}

// round 8
// speedup vs baseline: 1.5000x; 1.5000x over previous
#include <cuda_runtime.h>
#include <cuda_bf16.h>
#include <math.h>
#include <stdint.h>

#define BB   2
#define NSEQ 2048
#define DMOD 1024
#define NH   16
#define HDIM 64
#define NC   4
#define BH   (BB * NH)

// ---------------- scratch (device globals; no allocation allowed) ----------------
__device__ float g_v[(size_t)BB * NH * NSEQ * HDIM];
__device__ float g_bias[(size_t)BB * NSEQ * NSEQ];

// bf16 split operands, pre-swizzled 128x64 SW128 tiles (16KB each)
__device__ __nv_bfloat16 gXh[(size_t)4096 * 1024];
__device__ __nv_bfloat16 gXl[(size_t)4096 * 1024];
__device__ __nv_bfloat16 gWqh[(size_t)3072 * 1024];
__device__ __nv_bfloat16 gWql[(size_t)3072 * 1024];
__device__ __nv_bfloat16 gWoh[(size_t)1024 * 1024];
__device__ __nv_bfloat16 gWol[(size_t)1024 * 1024];
__device__ __nv_bfloat16 gAh2[(size_t)4096 * 1024];
__device__ __nv_bfloat16 gAl2[(size_t)4096 * 1024];

// attention operands
__device__ __nv_bfloat16 gQh[(size_t)BH * NSEQ * HDIM];
__device__ __nv_bfloat16 gQl[(size_t)BH * NSEQ * HDIM];
__device__ __nv_bfloat16 gKh[(size_t)BH * NSEQ * HDIM];
__device__ __nv_bfloat16 gKl[(size_t)BH * NSEQ * HDIM];
__device__ __nv_bfloat16 gVth[(size_t)BH * NSEQ * HDIM];
__device__ __nv_bfloat16 gVtl[(size_t)BH * NSEQ * HDIM];

// ---------------- PTX helpers (base sm_103-legal only) ----------------
__device__ __forceinline__ uint32_t smem_u32(const void* p) {
    uint32_t a;
    asm("{ .reg .u64 t; cvta.to.shared.u64 t, %1; cvt.u32.u64 %0, t; }" : "=r"(a) : "l"(p));
    return a;
}

#define CP_ASYNC16(dst, src) \
    asm volatile("cp.async.cg.shared.global [%0], [%1], 16;" :: "r"(dst), "l"(src) : "memory")
#define CP_COMMIT() asm volatile("cp.async.commit_group;" ::: "memory")
#define CP_WAIT0()  asm volatile("cp.async.wait_group 0;" ::: "memory")
#define CP_WAIT1()  asm volatile("cp.async.wait_group 1;" ::: "memory")

#define LDMX4(r, a) \
    asm volatile("ldmatrix.sync.aligned.m8n8.x4.shared.b16 {%0,%1,%2,%3}, [%4];" \
        : "=r"((r)[0]), "=r"((r)[1]), "=r"((r)[2]), "=r"((r)[3]) : "r"(a))

__device__ __forceinline__ void mma_bf16(float* d, uint32_t a0, uint32_t a1,
                                         uint32_t a2, uint32_t a3,
                                         uint32_t b0, uint32_t b1) {
    asm volatile(
        "mma.sync.aligned.m16n8k16.row.col.f32.bf16.bf16.f32 "
        "{%0,%1,%2,%3},{%4,%5,%6,%7},{%8,%9},{%0,%1,%2,%3};"
        : "+f"(d[0]), "+f"(d[1]), "+f"(d[2]), "+f"(d[3])
        : "r"(a0), "r"(a1), "r"(a2), "r"(a3), "r"(b0), "r"(b1));
}

__device__ __forceinline__ uint32_t pack2_bf16(float lo, float hi) {
    uint32_t r;
    asm("cvt.rn.bf16x2.f32 %0, %1, %2;" : "=r"(r) : "f"(hi), "f"(lo));
    return r;
}
__device__ __forceinline__ uint32_t pack2_hi(uint32_t u0, uint32_t u1) {
    uint32_t r;
    asm("prmt.b32 %0, %1, %2, 0x7632;" : "=r"(r) : "r"(u0), "r"(u1));
    return r;
}
__device__ __forceinline__ float ex2f(float x) {
    float r;
    asm("ex2.approx.f32 %0, %1;" : "=f"(r) : "f"(x));
    return r;
}

// ---------------- split-conversion: fp32 row-major -> blocked swizzled bf16 hi/lo ----------------
__global__ void __launch_bounds__(256)
conv_split_kernel(const float* __restrict__ src, __nv_bfloat16* __restrict__ dh,
                  __nv_bfloat16* __restrict__ dl, int K)
{
    size_t idx = ((size_t)blockIdx.x * 256 + threadIdx.x) * 8;
    int r  = (int)(idx / K);
    int c0 = (int)(idx % K);
    float4 v0 = *(const float4*)(src + idx);
    float4 v1 = *(const float4*)(src + idx + 4);
    float f[8] = {v0.x, v0.y, v0.z, v0.w, v1.x, v1.y, v1.z, v1.w};
    __nv_bfloat16 h[8], l[8];
#pragma unroll
    for (int i = 0; i < 8; i++) {
        h[i] = __float2bfloat16(f[i]);
        l[i] = __float2bfloat16(f[i] - __bfloat162float(h[i]));
    }
    int rt = r >> 7, lr = r & 127, ch = c0 >> 6, lc = c0 & 63;
    size_t tile = (size_t)rt * (K >> 6) + ch;
    uint32_t off = lr * 128 + lc * 2;
    uint32_t sw = off ^ ((off >> 3) & 0x70);
    size_t db = tile * 16384 + sw;
    *(uint4*)((char*)dh + db) = *(uint4*)h;
    *(uint4*)((char*)dl + db) = *(uint4*)l;
}

// ---------------- HMMA GEMM: 512 threads, 16 warps (8m x 2n), warp tile 16x64 ----------------
// Double-buffered cp.async pipeline (commit-next THEN wait_group 1) + register frag double-buffering.
#define GEMM_SMEM (2 * 4 * 16384)

template <int MODE>
__global__ void __launch_bounds__(512)
gemm_hmma(const char* __restrict__ Ah, const char* __restrict__ Al,
          const char* __restrict__ Bh, const char* __restrict__ Bl,
          float* __restrict__ Cout, int KC, int Nt,
          const float* __restrict__ qw, const float* __restrict__ kw)
{
    extern __shared__ char smraw[];
    const uint32_t smemS = smem_u32(smraw);
    const int tid  = threadIdx.x;
    const int lane = tid & 31;
    const int warp = tid >> 5;
    const int wm = warp & 7;
    const int wn = warp >> 3;

    const size_t tA0 = (size_t)blockIdx.y * KC * 16384;
    const size_t tB0 = (size_t)blockIdx.x * KC * 16384;

    float acc[8][4];
#pragma unroll
    for (int j = 0; j < 8; j++)
#pragma unroll
        for (int t = 0; t < 4; t++) acc[j][t] = 0.f;

    const int lrow = lane & 15;
    const int cb   = (lane >> 4) << 4;

    // prologue: chunk 0 into buffer 0
    {
        const char* s0 = Ah + tA0 + tid * 16;
        const char* s1 = Al + tA0 + tid * 16;
        const char* s2 = Bh + tB0 + tid * 16;
        const char* s3 = Bl + tB0 + tid * 16;
        uint32_t d0 = smemS + tid * 16;
#pragma unroll
        for (int i = 0; i < 2; i++) {
            CP_ASYNC16(d0 + 0 * 16384 + i * 8192, s0 + i * 8192);
            CP_ASYNC16(d0 + 1 * 16384 + i * 8192, s1 + i * 8192);
            CP_ASYNC16(d0 + 2 * 16384 + i * 8192, s2 + i * 8192);
            CP_ASYNC16(d0 + 3 * 16384 + i * 8192, s3 + i * 8192);
        }
        CP_COMMIT();
    }

    const int arow = wm * 16 + lrow;
    const uint32_t aswz = (uint32_t)((arow & 7) << 4);
    const uint32_t abase = arow * 128 + cb;
    const int brow0 = wn * 64 + lrow;
    const uint32_t bswz0 = (uint32_t)((brow0 & 7) << 4);

    for (int kc = 0; kc < KC; kc++) {
        __syncthreads();   // all warps done with the buffer about to be refilled
        if (kc + 1 < KC) {
            size_t go = (size_t)(kc + 1) * 16384;
            const char* s0 = Ah + tA0 + go + tid * 16;
            const char* s1 = Al + tA0 + go + tid * 16;
            const char* s2 = Bh + tB0 + go + tid * 16;
            const char* s3 = Bl + tB0 + go + tid * 16;
            uint32_t d0 = smemS + ((kc + 1) & 1) * 65536 + tid * 16;
#pragma unroll
            for (int i = 0; i < 2; i++) {
                CP_ASYNC16(d0 + 0 * 16384 + i * 8192, s0 + i * 8192);
                CP_ASYNC16(d0 + 1 * 16384 + i * 8192, s1 + i * 8192);
                CP_ASYNC16(d0 + 2 * 16384 + i * 8192, s2 + i * 8192);
                CP_ASYNC16(d0 + 3 * 16384 + i * 8192, s3 + i * 8192);
            }
            CP_COMMIT();
            CP_WAIT1();    // current chunk resident; next still in flight
        } else {
            CP_WAIT0();
        }
        __syncthreads();

        uint32_t buf = smemS + (kc & 1) * 65536;
        const uint32_t aHs = buf, aLs = buf + 16384, bHs = buf + 32768, bLs = buf + 49152;

        uint32_t ah[2][4], al[2][4], bh[2][4], bl[2][4];
        {
            uint32_t sw = abase ^ aswz;
            LDMX4(ah[0], aHs + sw);
            LDMX4(al[0], aLs + sw);
        }
        {
            uint32_t sw = (uint32_t)(brow0 * 128 + cb) ^ bswz0;
            LDMX4(bh[0], bHs + sw);
            LDMX4(bl[0], bLs + sw);
        }

#pragma unroll
        for (int ks = 0; ks < 4; ks++) {
#pragma unroll
            for (int nf2 = 0; nf2 < 4; nf2++) {
                const int cur = (ks * 4 + nf2) & 1, nxt = cur ^ 1;
                if (nf2 < 3) {
                    int row = wn * 64 + (nf2 + 1) * 16 + lrow;
                    uint32_t sw = (uint32_t)(row * 128 + ks * 32 + cb) ^ ((row & 7) << 4);
                    LDMX4(bh[nxt], bHs + sw);
                    LDMX4(bl[nxt], bLs + sw);
                } else if (ks < 3) {
                    uint32_t swA = (abase + (ks + 1) * 32) ^ aswz;
                    LDMX4(ah[(ks + 1) & 1], aHs + swA);
                    LDMX4(al[(ks + 1) & 1], aLs + swA);
                    uint32_t sw = (uint32_t)(brow0 * 128 + (ks + 1) * 32 + cb) ^ bswz0;
                    LDMX4(bh[nxt], bHs + sw);
                    LDMX4(bl[nxt], bLs + sw);
                }
                const int ka = ks & 1;
                float* d0 = acc[2 * nf2];
                float* d1 = acc[2 * nf2 + 1];
                mma_bf16(d0, ah[ka][0], ah[ka][1], ah[ka][2], ah[ka][3], bh[cur][0], bh[cur][2]);
                mma_bf16(d0, ah[ka][0], ah[ka][1], ah[ka][2], ah[ka][3], bl[cur][0], bl[cur][2]);
                mma_bf16(d0, al[ka][0], al[ka][1], al[ka][2], al[ka][3], bh[cur][0], bh[cur][2]);
                mma_bf16(d1, ah[ka][0], ah[ka][1], ah[ka][2], ah[ka][3], bh[cur][1], bh[cur][3]);
                mma_bf16(d1, ah[ka][0], ah[ka][1], ah[ka][2], ah[ka][3], bl[cur][1], bl[cur][3]);
                mma_bf16(d1, al[ka][0], al[ka][1], al[ka][2], al[ka][3], bh[cur][1], bh[cur][3]);
            }
        }
    }

    const int r0l = lane >> 2;
    const int c2  = (lane & 3) * 2;

    if (MODE == 0) {
        const int m0 = blockIdx.y * 128 + wm * 16 + r0l;
        const int n0 = blockIdx.x * 128 + wn * 64;
#pragma unroll
        for (int nf = 0; nf < 8; nf++) {
            int n = n0 + nf * 8 + c2;
            *(float2*)(Cout + (size_t)m0 * Nt + n)       = make_float2(acc[nf][0], acc[nf][1]);
            *(float2*)(Cout + (size_t)(m0 + 8) * Nt + n) = make_float2(acc[nf][2], acc[nf][3]);
        }
    } else {
        const int j = blockIdx.x * 2 + wn;
        const int which = j >> 4;
        const int h = j & 15;
        const int m0 = blockIdx.y * 128 + wm * 16 + r0l;
        const int m1 = m0 + 8;
        const int b0i = m0 >> 11, n0i = m0 & 2047;
        const int b1i = m1 >> 11, n1i = m1 & 2047;

        if (which == 2) {
            float* vb = g_v;
#pragma unroll
            for (int nf = 0; nf < 8; nf++) {
                int dd = nf * 8 + c2;
                *(float2*)&vb[(((size_t)(b0i * NH + h)) * NSEQ + n0i) * HDIM + dd] =
                    make_float2(acc[nf][0], acc[nf][1]);
                *(float2*)&vb[(((size_t)(b1i * NH + h)) * NSEQ + n1i) * HDIM + dd] =
                    make_float2(acc[nf][2], acc[nf][3]);
            }
        } else {
            const float* w = (which == 0) ? qw : kw;
            char* dh = (which == 0) ? (char*)gQh : (char*)gKh;
            char* dl = (which == 0) ? (char*)gQl : (char*)gKl;
            float ss0 = 0.f, ss1 = 0.f;
#pragma unroll
            for (int nf = 0; nf < 8; nf++) {
                ss0 += acc[nf][0] * acc[nf][0] + acc[nf][1] * acc[nf][1];
                ss1 += acc[nf][2] * acc[nf][2] + acc[nf][3] * acc[nf][3];
            }
            ss0 += __shfl_xor_sync(0xffffffffu, ss0, 1);
            ss0 += __shfl_xor_sync(0xffffffffu, ss0, 2);
            ss1 += __shfl_xor_sync(0xffffffffu, ss1, 1);
            ss1 += __shfl_xor_sync(0xffffffffu, ss1, 2);
            float r0 = rsqrtf(ss0 * (1.0f / HDIM) + 1e-6f);
            float r1 = rsqrtf(ss1 * (1.0f / HDIM) + 1e-6f);

            size_t tb0 = (((size_t)(b0i * NH + h)) * 16 + (n0i >> 7)) * 16384;
            size_t tb1 = (((size_t)(b1i * NH + h)) * 16 + (n1i >> 7)) * 16384;
            int lr0 = n0i & 127, lr1 = n1i & 127;
            uint32_t x0 = (lr0 & 7) << 4, x1 = (lr1 & 7) << 4;
#pragma unroll
            for (int nf = 0; nf < 8; nf++) {
                int dd = nf * 8 + c2;
                float2 wv = *(const float2*)(w + dd);
                float v0 = acc[nf][0] * r0 * wv.x;
                float v1 = acc[nf][1] * r0 * wv.y;
                float v2 = acc[nf][2] * r1 * wv.x;
                float v3 = acc[nf][3] * r1 * wv.y;
                uint32_t u0 = __float_as_uint(v0), u1 = __float_as_uint(v1);
                uint32_t u2 = __float_as_uint(v2), u3 = __float_as_uint(v3);
                uint32_t o0 = (lr0 * 128 + dd * 2) ^ x0;
                uint32_t o1 = (lr1 * 128 + dd * 2) ^ x1;
                *(uint32_t*)(dh + tb0 + o0) = pack2_hi(u0, u1);
                *(uint32_t*)(dh + tb1 + o1) = pack2_hi(u2, u3);
                *(uint32_t*)(dl + tb0 + o0) =
                    pack2_bf16(v0 - __uint_as_float(u0 & 0xFFFF0000u),
                               v1 - __uint_as_float(u1 & 0xFFFF0000u));
                *(uint32_t*)(dl + tb1 + o1) =
                    pack2_bf16(v2 - __uint_as_float(u2 & 0xFFFF0000u),
                               v3 - __uint_as_float(u3 & 0xFFFF0000u));
            }
        }
    }
}

// ---------------- V transpose + split ----------------
__global__ void __launch_bounds__(256)
vsplit_kernel()
{
    __shared__ float stg[64][65];
    const int kt = blockIdx.x, bh = blockIdx.y;
    const int tid = threadIdx.x;
    {
        int s = tid >> 2, d0 = (tid & 3) * 16;
        const float* vp = g_v + ((size_t)bh * NSEQ + kt * 64 + s) * HDIM + d0;
#pragma unroll
        for (int i = 0; i < 4; i++) {
            float4 v = *(const float4*)(vp + i * 4);
            stg[s][d0 + i * 4 + 0] = v.x;
            stg[s][d0 + i * 4 + 1] = v.y;
            stg[s][d0 + i * 4 + 2] = v.z;
            stg[s][d0 + i * 4 + 3] = v.w;
        }
    }
    __syncthreads();
    {
        int dR = tid >> 2, c0 = (tid & 3) * 16;
        uint32_t hw[8], lw[8];
#pragma unroll
        for (int j = 0; j < 8; j++) {
            float f0 = stg[c0 + 2 * j][dR];
            float f1 = stg[c0 + 2 * j + 1][dR];
            uint32_t u0 = __float_as_uint(f0), u1 = __float_as_uint(f1);
            hw[j] = pack2_hi(u0, u1);
            float l0 = f0 - __uint_as_float(u0 & 0xFFFF0000u);
            float l1 = f1 - __uint_as_float(u1 & 0xFFFF0000u);
            lw[j] = pack2_bf16(l0, l1);
        }
        size_t tb = ((size_t)bh * 32 + kt) * 8192;
        uint32_t off0 = dR * 128 + c0 * 2;
        uint32_t x = (dR & 7) << 4;
        *(uint4*)((char*)gVth + tb + (off0 ^ x))        = make_uint4(hw[0], hw[1], hw[2], hw[3]);
        *(uint4*)((char*)gVth + tb + ((off0 + 16) ^ x)) = make_uint4(hw[4], hw[5], hw[6], hw[7]);
        *(uint4*)((char*)gVtl + tb + (off0 ^ x))        = make_uint4(lw[0], lw[1], lw[2], lw[3]);
        *(uint4*)((char*)gVtl + tb + ((off0 + 16) ^ x)) = make_uint4(lw[4], lw[5], lw[6], lw[7]);
    }
}

// ---------------- bias precompute ----------------
__global__ void __launch_bounds__(256)
bias_kernel(const float* __restrict__ cm, const float* __restrict__ im)
{
    int bq = blockIdx.x;
    int b = bq / NSEQ, q = bq % NSEQ;
    const float* cmb = cm + (size_t)b * NC * NSEQ;
    float c0 = cmb[q], c1 = cmb[NSEQ + q], c2 = cmb[2 * NSEQ + q], c3 = cmb[3 * NSEQ + q];

    float mx = 0.f;
    for (int k = threadIdx.x; k < NSEQ; k += 256) {
        float s = c0 * cmb[k] + c1 * cmb[NSEQ + k] + c2 * cmb[2 * NSEQ + k] + c3 * cmb[3 * NSEQ + k];
        mx = fmaxf(mx, s);
    }
    __shared__ float red[8];
#pragma unroll
    for (int o = 16; o > 0; o >>= 1) mx = fmaxf(mx, __shfl_xor_sync(0xffffffffu, mx, o));
    if ((threadIdx.x & 31) == 0) red[threadIdx.x >> 5] = mx;
    __syncthreads();
    if (threadIdx.x == 0) {
        float m = red[0];
#pragma unroll
        for (int wN = 1; wN < 8; wN++) m = fmaxf(m, red[wN]);
        red[0] = fmaxf(m, 1e-6f);
    }
    __syncthreads();
    float inv = 1.f / red[0];
    const float* imr = im + (size_t)bq * NSEQ;
    float* br = g_bias + (size_t)bq * NSEQ;
    for (int k = threadIdx.x; k < NSEQ; k += 256) {
        float s = c0 * cmb[k] + c1 * cmb[NSEQ + k] + c2 * cmb[2 * NSEQ + k] + c3 * cmb[3 * NSEQ + k];
        br[k] = 2.f * s * inv - 1.f + 0.3f * imr[k];
    }
}

// ---------------- HMMA flash attention (correct pipeline + frag double-buffering + ex2) ----------------
#define ATTN2_SMEM 98304

__global__ void __launch_bounds__(256)
attn2_kernel(const float* __restrict__ gate)
{
    extern __shared__ char smraw[];
    const uint32_t S = smem_u32(smraw);
    const int tid = threadIdx.x, lane = tid & 31, warp = tid >> 5;
    const int bh = blockIdx.y, b = bh >> 4, h = bh & 15;
    const int qt = blockIdx.x, q0 = qt * 128;
    const float LOG2E = 1.44269504f;
    const float g32 = 3.f * fminf(fmaxf(gate[h], 0.f), 1.f) * LOG2E;
    const float SC = 0.125f * LOG2E;
    const int lrow = lane & 15, cb = (lane >> 4) << 4;
    const int wrow = warp * 16;

    // prologue: Q tiles (group 0)
    {
        size_t qoff = ((size_t)(bh * 16 + qt)) * 16384 + tid * 16;
        uint32_t d = S + tid * 16;
#pragma unroll
        for (int i = 0; i < 4; i++) {
            CP_ASYNC16(d + i * 4096,         (const char*)gQh + qoff + i * 4096);
            CP_ASYNC16(d + 16384 + i * 4096, (const char*)gQl + qoff + i * 4096);
        }
        CP_COMMIT();
    }
    // prologue: KV tile 0 (group 1)
    {
        size_t koff = ((size_t)(bh * 16)) * 16384 + tid * 16;
        size_t voff = ((size_t)(bh * 32)) * 8192 + tid * 16;
        uint32_t dk = S + 32768 + tid * 16;
#pragma unroll
        for (int i = 0; i < 2; i++) {
            CP_ASYNC16(dk + 0     + i * 4096, (const char*)gKh  + koff + i * 4096);
            CP_ASYNC16(dk + 8192  + i * 4096, (const char*)gKl  + koff + i * 4096);
            CP_ASYNC16(dk + 16384 + i * 4096, (const char*)gVth + voff + i * 4096);
            CP_ASYNC16(dk + 24576 + i * 4096, (const char*)gVtl + voff + i * 4096);
        }
        CP_COMMIT();
    }

    uint32_t qh[4][4], ql[4][4];
    float o[8][4];
#pragma unroll
    for (int nf = 0; nf < 8; nf++)
#pragma unroll
        for (int t = 0; t < 4; t++) o[nf][t] = 0.f;
    float m0r = -1e30f, m1r = -1e30f, l0r = 0.f, l1r = 0.f;

    const int r0l = lane >> 2;
    const float* bias0 = g_bias + ((size_t)(b * NSEQ + q0 + wrow + r0l)) * NSEQ;
    const float* bias1 = bias0 + 8 * NSEQ;
    const uint32_t lswz = (uint32_t)((lrow & 7) << 4);

    for (int kt = 0; kt < 32; kt++) {
        __syncthreads();   // all warps done with the buffer about to be refilled
        if (kt + 1 < 32) {
            int k2 = kt + 1;
            size_t koff = ((size_t)(bh * 16 + (k2 >> 1))) * 16384 + (size_t)(k2 & 1) * 8192 + tid * 16;
            size_t voff = ((size_t)(bh * 32 + k2)) * 8192 + tid * 16;
            uint32_t d = S + 32768 + (k2 & 1) * 32768 + tid * 16;
#pragma unroll
            for (int i = 0; i < 2; i++) {
                CP_ASYNC16(d + 0     + i * 4096, (const char*)gKh  + koff + i * 4096);
                CP_ASYNC16(d + 8192  + i * 4096, (const char*)gKl  + koff + i * 4096);
                CP_ASYNC16(d + 16384 + i * 4096, (const char*)gVth + voff + i * 4096);
                CP_ASYNC16(d + 24576 + i * 4096, (const char*)gVtl + voff + i * 4096);
            }
            CP_COMMIT();
            CP_WAIT1();    // current KV resident; next in flight
        } else {
            CP_WAIT0();
        }
        __syncthreads();

        if (kt == 0) {
#pragma unroll
            for (int ks = 0; ks < 4; ks++) {
                uint32_t off = (wrow + lrow) * 128 + ks * 32 + cb;
                uint32_t sw = off ^ (((wrow + lrow) & 7) << 4);
                LDMX4(qh[ks], S + sw);
                LDMX4(ql[ks], S + 16384 + sw);
            }
        }

        uint32_t buf = S + 32768 + (kt & 1) * 32768;

        // --- S = Q K^T (3-term split, frag double-buffered) ---
        float sf[8][4];
#pragma unroll
        for (int nf = 0; nf < 8; nf++)
#pragma unroll
            for (int t = 0; t < 4; t++) sf[nf][t] = 0.f;

        uint32_t kh2[2][4], kl2[2][4];
        {
            uint32_t sw = (uint32_t)(lrow * 128 + cb) ^ lswz;
            LDMX4(kh2[0], buf + sw);
            LDMX4(kl2[0], buf + 8192 + sw);
        }
#pragma unroll
        for (int ks = 0; ks < 4; ks++) {
#pragma unroll
            for (int nf2 = 0; nf2 < 4; nf2++) {
                const int cur = (ks * 4 + nf2) & 1, nxt = cur ^ 1;
                if (nf2 < 3) {
                    int row = (nf2 + 1) * 16 + lrow;
                    uint32_t sw = (uint32_t)(row * 128 + ks * 32 + cb) ^ ((row & 7) << 4);
                    LDMX4(kh2[nxt], buf + sw);
                    LDMX4(kl2[nxt], buf + 8192 + sw);
                } else if (ks < 3) {
                    uint32_t sw = (uint32_t)(lrow * 128 + (ks + 1) * 32 + cb) ^ lswz;
                    LDMX4(kh2[nxt], buf + sw);
                    LDMX4(kl2[nxt], buf + 8192 + sw);
                }
                float* d0 = sf[2 * nf2];
                float* d1 = sf[2 * nf2 + 1];
                mma_bf16(d0, qh[ks][0], qh[ks][1], qh[ks][2], qh[ks][3], kh2[cur][0], kh2[cur][2]);
                mma_bf16(d0, qh[ks][0], qh[ks][1], qh[ks][2], qh[ks][3], kl2[cur][0], kl2[cur][2]);
                mma_bf16(d0, ql[ks][0], ql[ks][1], ql[ks][2], ql[ks][3], kh2[cur][0], kh2[cur][2]);
                mma_bf16(d1, qh[ks][0], qh[ks][1], qh[ks][2], qh[ks][3], kh2[cur][1], kh2[cur][3]);
                mma_bf16(d1, qh[ks][0], qh[ks][1], qh[ks][2], qh[ks][3], kl2[cur][1], kl2[cur][3]);
                mma_bf16(d1, ql[ks][0], ql[ks][1], ql[ks][2], ql[ks][3], kh2[cur][1], kh2[cur][3]);
            }
        }

        // --- scale + gated bias + online softmax (log2 domain) ---
        int colbase = kt * 64 + 2 * (lane & 3);
        float rm0 = -1e30f, rm1 = -1e30f;
#pragma unroll
        for (int nf = 0; nf < 8; nf++) {
            float2 bb0 = *(const float2*)(bias0 + colbase + nf * 8);
            float2 bb1 = *(const float2*)(bias1 + colbase + nf * 8);
            sf[nf][0] = fmaf(sf[nf][0], SC, g32 * bb0.x);
            sf[nf][1] = fmaf(sf[nf][1], SC, g32 * bb0.y);
            sf[nf][2] = fmaf(sf[nf][2], SC, g32 * bb1.x);
            sf[nf][3] = fmaf(sf[nf][3], SC, g32 * bb1.y);
            rm0 = fmaxf(rm0, fmaxf(sf[nf][0], sf[nf][1]));
            rm1 = fmaxf(rm1, fmaxf(sf[nf][2], sf[nf][3]));
        }
        rm0 = fmaxf(rm0, __shfl_xor_sync(0xffffffffu, rm0, 1));
        rm0 = fmaxf(rm0, __shfl_xor_sync(0xffffffffu, rm0, 2));
        rm1 = fmaxf(rm1, __shfl_xor_sync(0xffffffffu, rm1, 1));
        rm1 = fmaxf(rm1, __shfl_xor_sync(0xffffffffu, rm1, 2));

        float mn0 = fmaxf(m0r, rm0), mn1 = fmaxf(m1r, rm1);
        float al0 = ex2f(m0r - mn0), al1 = ex2f(m1r - mn1);
        m0r = mn0; m1r = mn1;
        float rs0 = 0.f, rs1 = 0.f;
#pragma unroll
        for (int nf = 0; nf < 8; nf++) {
            sf[nf][0] = ex2f(sf[nf][0] - mn0);
            sf[nf][1] = ex2f(sf[nf][1] - mn0);
            sf[nf][2] = ex2f(sf[nf][2] - mn1);
            sf[nf][3] = ex2f(sf[nf][3] - mn1);
            rs0 += sf[nf][0] + sf[nf][1];
            rs1 += sf[nf][2] + sf[nf][3];
        }
        rs0 += __shfl_xor_sync(0xffffffffu, rs0, 1);
        rs0 += __shfl_xor_sync(0xffffffffu, rs0, 2);
        rs1 += __shfl_xor_sync(0xffffffffu, rs1, 1);
        rs1 += __shfl_xor_sync(0xffffffffu, rs1, 2);
        l0r = l0r * al0 + rs0;
        l1r = l1r * al1 + rs1;
#pragma unroll
        for (int nf = 0; nf < 8; nf++) {
            o[nf][0] *= al0; o[nf][1] *= al0;
            o[nf][2] *= al1; o[nf][3] *= al1;
        }

        // --- O += P V (P in regs, V frags double-buffered) ---
        const uint32_t vHs = buf + 16384, vLs = buf + 24576;
        uint32_t vh2[2][4], vl2[2][4];
        {
            uint32_t sw = (uint32_t)(lrow * 128 + cb) ^ lswz;
            LDMX4(vh2[0], vHs + sw);
            LDMX4(vl2[0], vLs + sw);
        }
#pragma unroll
        for (int kk = 0; kk < 4; kk++) {
            const int na = 2 * kk, nb = 2 * kk + 1;
            uint32_t u0 = __float_as_uint(sf[na][0]), u1 = __float_as_uint(sf[na][1]);
            uint32_t u2 = __float_as_uint(sf[na][2]), u3 = __float_as_uint(sf[na][3]);
            uint32_t w0 = __float_as_uint(sf[nb][0]), w1 = __float_as_uint(sf[nb][1]);
            uint32_t w2 = __float_as_uint(sf[nb][2]), w3 = __float_as_uint(sf[nb][3]);
            uint32_t ph_[4], pl_[4];
            ph_[0] = pack2_hi(u0, u1);
            ph_[1] = pack2_hi(u2, u3);
            ph_[2] = pack2_hi(w0, w1);
            ph_[3] = pack2_hi(w2, w3);
            pl_[0] = pack2_bf16(sf[na][0] - __uint_as_float(u0 & 0xFFFF0000u),
                                sf[na][1] - __uint_as_float(u1 & 0xFFFF0000u));
            pl_[1] = pack2_bf16(sf[na][2] - __uint_as_float(u2 & 0xFFFF0000u),
                                sf[na][3] - __uint_as_float(u3 & 0xFFFF0000u));
            pl_[2] = pack2_bf16(sf[nb][0] - __uint_as_float(w0 & 0xFFFF0000u),
                                sf[nb][1] - __uint_as_float(w1 & 0xFFFF0000u));
            pl_[3] = pack2_bf16(sf[nb][2] - __uint_as_float(w2 & 0xFFFF0000u),
                                sf[nb][3] - __uint_as_float(w3 & 0xFFFF0000u));
#pragma unroll
            for (int nf2 = 0; nf2 < 4; nf2++) {
                const int cur = (kk * 4 + nf2) & 1, nxt = cur ^ 1;
                if (nf2 < 3) {
                    int row = (nf2 + 1) * 16 + lrow;
                    uint32_t sw = (uint32_t)(row * 128 + kk * 32 + cb) ^ ((row & 7) << 4);
                    LDMX4(vh2[nxt], vHs + sw);
                    LDMX4(vl2[nxt], vLs + sw);
                } else if (kk < 3) {
                    uint32_t sw = (uint32_t)(lrow * 128 + (kk + 1) * 32 + cb) ^ lswz;
                    LDMX4(vh2[nxt], vHs + sw);
                    LDMX4(vl2[nxt], vLs + sw);
                }
                float* d0 = o[2 * nf2];
                float* d1 = o[2 * nf2 + 1];
                mma_bf16(d0, ph_[0], ph_[1], ph_[2], ph_[3], vh2[cur][0], vh2[cur][2]);
                mma_bf16(d0, ph_[0], ph_[1], ph_[2], ph_[3], vl2[cur][0], vl2[cur][2]);
                mma_bf16(d0, pl_[0], pl_[1], pl_[2], pl_[3], vh2[cur][0], vh2[cur][2]);
                mma_bf16(d1, ph_[0], ph_[1], ph_[2], ph_[3], vh2[cur][1], vh2[cur][3]);
                mma_bf16(d1, ph_[0], ph_[1], ph_[2], ph_[3], vl2[cur][1], vl2[cur][3]);
                mma_bf16(d1, pl_[0], pl_[1], pl_[2], pl_[3], vh2[cur][1], vh2[cur][3]);
            }
        }
    }

    // epilogue: normalize + write bf16 hi/lo swizzled A-tile for the out-projection
    float i0 = 1.f / l0r, i1 = 1.f / l1r;
    size_t tb = (((size_t)(b * 16 + qt)) * 16 + h) * 16384;
    int lr0 = wrow + r0l, lr1 = lr0 + 8;
    uint32_t x0 = (lr0 & 7) << 4, x1 = (lr1 & 7) << 4;
#pragma unroll
    for (int nf = 0; nf < 8; nf++) {
        int dd = nf * 8 + 2 * (lane & 3);
        float v0 = o[nf][0] * i0, v1 = o[nf][1] * i0;
        float v2 = o[nf][2] * i1, v3 = o[nf][3] * i1;
        uint32_t u0 = __float_as_uint(v0), u1 = __float_as_uint(v1);
        uint32_t u2 = __float_as_uint(v2), u3 = __float_as_uint(v3);
        uint32_t o0 = (lr0 * 128 + dd * 2) ^ x0;
        uint32_t o1 = (lr1 * 128 + dd * 2) ^ x1;
        *(uint32_t*)((char*)gAh2 + tb + o0) = pack2_hi(u0, u1);
        *(uint32_t*)((char*)gAh2 + tb + o1) = pack2_hi(u2, u3);
        *(uint32_t*)((char*)gAl2 + tb + o0) =
            pack2_bf16(v0 - __uint_as_float(u0 & 0xFFFF0000u),
                       v1 - __uint_as_float(u1 & 0xFFFF0000u));
        *(uint32_t*)((char*)gAl2 + tb + o1) =
            pack2_bf16(v2 - __uint_as_float(u2 & 0xFFFF0000u),
                       v3 - __uint_as_float(u3 & 0xFFFF0000u));
    }
}

// ---------------- launch ----------------
extern "C" void kernel_launch(void* const* d_in, const int* in_sizes, int n_in,
                              void* d_out, int out_size)
{
    (void)in_sizes; (void)n_in; (void)out_size;
    const float* x    = (const float*)d_in[0];
    const float* cm   = (const float*)d_in[1];
    const float* im   = (const float*)d_in[2];
    const float* wqkv = (const float*)d_in[3];
    const float* wout = (const float*)d_in[4];
    const float* qnw  = (const float*)d_in[5];
    const float* knw  = (const float*)d_in[6];
    const float* gate = (const float*)d_in[7];
    float* out = (float*)d_out;

    void *xh, *xl, *wqh, *wql, *woh, *wol, *ah2, *al2;
    cudaGetSymbolAddress(&xh, gXh);   cudaGetSymbolAddress(&xl, gXl);
    cudaGetSymbolAddress(&wqh, gWqh); cudaGetSymbolAddress(&wql, gWql);
    cudaGetSymbolAddress(&woh, gWoh); cudaGetSymbolAddress(&wol, gWol);
    cudaGetSymbolAddress(&ah2, gAh2); cudaGetSymbolAddress(&al2, gAl2);

    cudaFuncSetAttribute(attn2_kernel, cudaFuncAttributeMaxDynamicSharedMemorySize, ATTN2_SMEM);
    cudaFuncSetAttribute(gemm_hmma<0>, cudaFuncAttributeMaxDynamicSharedMemorySize, GEMM_SMEM);
    cudaFuncSetAttribute(gemm_hmma<1>, cudaFuncAttributeMaxDynamicSharedMemorySize, GEMM_SMEM);

    const int M = BB * NSEQ;   // 4096

    // 1) split-convert inputs
    conv_split_kernel<<<(4096 * 1024 / 8) / 256, 256>>>(x,    (__nv_bfloat16*)xh,  (__nv_bfloat16*)xl,  1024);
    conv_split_kernel<<<(3072 * 1024 / 8) / 256, 256>>>(wqkv, (__nv_bfloat16*)wqh, (__nv_bfloat16*)wql, 1024);
    conv_split_kernel<<<(1024 * 1024 / 8) / 256, 256>>>(wout, (__nv_bfloat16*)woh, (__nv_bfloat16*)wol, 1024);

    // 2) QKV projection (HMMA) with fused RMSNorm + split epilogue
    gemm_hmma<1><<<dim3(3 * DMOD / 128, M / 128), 512, GEMM_SMEM>>>(
        (const char*)xh, (const char*)xl, (const char*)wqh, (const char*)wql,
        nullptr, 1024 / 64, 3 * DMOD, qnw, knw);

    // 3) V -> transposed bf16 hi/lo tiles
    vsplit_kernel<<<dim3(NSEQ / 64, BH), 256>>>();

    // 4) bias precompute
    bias_kernel<<<BB * NSEQ, 256>>>(cm, im);

    // 5) HMMA flash attention (writes split A-tiles for out-proj directly)
    attn2_kernel<<<dim3(NSEQ / 128, BH), 256, ATTN2_SMEM>>>(gate);

    // 6) out-projection straight into d_out
    gemm_hmma<0><<<dim3(DMOD / 128, M / 128), 512, GEMM_SMEM>>>(
        (const char*)ah2, (const char*)al2, (const char*)woh, (const char*)wol,
        out, 1024 / 64, DMOD, nullptr, nullptr);
}

// round 9
// speedup vs baseline: 1.6269x; 1.0846x over previous
#include <cuda_runtime.h>
#include <cuda_bf16.h>
#include <math.h>
#include <stdint.h>

#define BB   2
#define NSEQ 2048
#define DMOD 1024
#define NH   16
#define HDIM 64
#define NC   4
#define BH   (BB * NH)

// ---------------- scratch (device globals; no allocation allowed) ----------------
__device__ float g_v[(size_t)BB * NH * NSEQ * HDIM];
__device__ float g_bias[(size_t)BB * NSEQ * NSEQ];

// bf16 split operands, pre-swizzled 128x64 SW128 tiles (16KB each)
__device__ __nv_bfloat16 gXh[(size_t)4096 * 1024];
__device__ __nv_bfloat16 gXl[(size_t)4096 * 1024];
__device__ __nv_bfloat16 gWqh[(size_t)3072 * 1024];
__device__ __nv_bfloat16 gWql[(size_t)3072 * 1024];
__device__ __nv_bfloat16 gWoh[(size_t)1024 * 1024];
__device__ __nv_bfloat16 gWol[(size_t)1024 * 1024];
__device__ __nv_bfloat16 gAh2[(size_t)4096 * 1024];
__device__ __nv_bfloat16 gAl2[(size_t)4096 * 1024];

// attention operands
__device__ __nv_bfloat16 gQh[(size_t)BH * NSEQ * HDIM];
__device__ __nv_bfloat16 gQl[(size_t)BH * NSEQ * HDIM];
__device__ __nv_bfloat16 gKh[(size_t)BH * NSEQ * HDIM];
__device__ __nv_bfloat16 gKl[(size_t)BH * NSEQ * HDIM];
__device__ __nv_bfloat16 gVth[(size_t)BH * NSEQ * HDIM];
__device__ __nv_bfloat16 gVtl[(size_t)BH * NSEQ * HDIM];

// ---------------- PTX helpers (base sm_103-legal only) ----------------
__device__ __forceinline__ uint32_t smem_u32(const void* p) {
    uint32_t a;
    asm("{ .reg .u64 t; cvta.to.shared.u64 t, %1; cvt.u32.u64 %0, t; }" : "=r"(a) : "l"(p));
    return a;
}

#define CP_ASYNC16(dst, src) \
    asm volatile("cp.async.cg.shared.global [%0], [%1], 16;" :: "r"(dst), "l"(src) : "memory")
#define CP_COMMIT() asm volatile("cp.async.commit_group;" ::: "memory")
#define CP_WAIT0()  asm volatile("cp.async.wait_group 0;" ::: "memory")
#define CP_WAIT1()  asm volatile("cp.async.wait_group 1;" ::: "memory")

#define LDMX4(r, a) \
    asm volatile("ldmatrix.sync.aligned.m8n8.x4.shared.b16 {%0,%1,%2,%3}, [%4];" \
        : "=r"((r)[0]), "=r"((r)[1]), "=r"((r)[2]), "=r"((r)[3]) : "r"(a))

__device__ __forceinline__ void mma_bf16(float* d, uint32_t a0, uint32_t a1,
                                         uint32_t a2, uint32_t a3,
                                         uint32_t b0, uint32_t b1) {
    asm volatile(
        "mma.sync.aligned.m16n8k16.row.col.f32.bf16.bf16.f32 "
        "{%0,%1,%2,%3},{%4,%5,%6,%7},{%8,%9},{%0,%1,%2,%3};"
        : "+f"(d[0]), "+f"(d[1]), "+f"(d[2]), "+f"(d[3])
        : "r"(a0), "r"(a1), "r"(a2), "r"(a3), "r"(b0), "r"(b1));
}

__device__ __forceinline__ uint32_t pack2_bf16(float lo, float hi) {
    uint32_t r;
    asm("cvt.rn.bf16x2.f32 %0, %1, %2;" : "=r"(r) : "f"(hi), "f"(lo));
    return r;
}
__device__ __forceinline__ uint32_t pack2_hi(uint32_t u0, uint32_t u1) {
    uint32_t r;
    asm("prmt.b32 %0, %1, %2, 0x7632;" : "=r"(r) : "r"(u0), "r"(u1));
    return r;
}
__device__ __forceinline__ float ex2f(float x) {
    float r;
    asm("ex2.approx.f32 %0, %1;" : "=f"(r) : "f"(x));
    return r;
}

// ---------------- split-conversion: fp32 row-major -> blocked swizzled bf16 hi/lo ----------------
__global__ void __launch_bounds__(256)
conv_split_kernel(const float* __restrict__ src, __nv_bfloat16* __restrict__ dh,
                  __nv_bfloat16* __restrict__ dl, int K)
{
    size_t idx = ((size_t)blockIdx.x * 256 + threadIdx.x) * 8;
    int r  = (int)(idx / K);
    int c0 = (int)(idx % K);
    float4 v0 = *(const float4*)(src + idx);
    float4 v1 = *(const float4*)(src + idx + 4);
    float f[8] = {v0.x, v0.y, v0.z, v0.w, v1.x, v1.y, v1.z, v1.w};
    __nv_bfloat16 h[8], l[8];
#pragma unroll
    for (int i = 0; i < 8; i++) {
        h[i] = __float2bfloat16(f[i]);
        l[i] = __float2bfloat16(f[i] - __bfloat162float(h[i]));
    }
    int rt = r >> 7, lr = r & 127, ch = c0 >> 6, lc = c0 & 63;
    size_t tile = (size_t)rt * (K >> 6) + ch;
    uint32_t off = lr * 128 + lc * 2;
    uint32_t sw = off ^ ((off >> 3) & 0x70);
    size_t db = tile * 16384 + sw;
    *(uint4*)((char*)dh + db) = *(uint4*)h;
    *(uint4*)((char*)dl + db) = *(uint4*)l;
}

// ---------------- HMMA GEMM: 256 threads, 8 warps (8m x 1n), CTA tile 128x64 ----------------
// 48KB/buffer, double-buffered -> 96KB smem -> 2 CTAs/SM for cross-CTA pipe overlap.
// MODE 0: row-major store. MODE 1: QKV epilogue (fused RMSNorm + split writes; v -> g_v).
#define GEMM_SMEM (2 * 48 * 1024)

template <int MODE>
__global__ void __launch_bounds__(256, 2)
gemm_hmma(const char* __restrict__ Ah, const char* __restrict__ Al,
          const char* __restrict__ Bh, const char* __restrict__ Bl,
          float* __restrict__ Cout, int KC, int Nt,
          const float* __restrict__ qw, const float* __restrict__ kw)
{
    extern __shared__ char smraw[];
    const uint32_t smemS = smem_u32(smraw);
    const int tid  = threadIdx.x;
    const int lane = tid & 31;
    const int warp = tid >> 5;          // 0..7, owns rows warp*16..warp*16+15
    const int jcol = blockIdx.x;        // 64-col chunk index

    const size_t tA0 = (size_t)blockIdx.y * KC * 16384;
    const size_t tB0 = ((size_t)(jcol >> 1) * KC) * 16384 + (size_t)(jcol & 1) * 8192;

    float acc[8][4];
#pragma unroll
    for (int j = 0; j < 8; j++)
#pragma unroll
        for (int t = 0; t < 4; t++) acc[j][t] = 0.f;

    const int lrow = lane & 15;
    const int cb   = (lane >> 4) << 4;

    // buffer layout (48KB): Ah 0..16K | Al 16K..32K | Bh 32K..40K | Bl 40K..48K
    // prologue: chunk 0 into buffer 0
    {
        const char* sA0 = Ah + tA0 + tid * 16;
        const char* sA1 = Al + tA0 + tid * 16;
        const char* sB0 = Bh + tB0 + tid * 16;
        const char* sB1 = Bl + tB0 + tid * 16;
        uint32_t d0 = smemS + tid * 16;
#pragma unroll
        for (int i = 0; i < 4; i++) {
            CP_ASYNC16(d0 + i * 4096,         sA0 + i * 4096);
            CP_ASYNC16(d0 + 16384 + i * 4096, sA1 + i * 4096);
        }
#pragma unroll
        for (int i = 0; i < 2; i++) {
            CP_ASYNC16(d0 + 32768 + i * 4096, sB0 + i * 4096);
            CP_ASYNC16(d0 + 40960 + i * 4096, sB1 + i * 4096);
        }
        CP_COMMIT();
    }

    const int arow = warp * 16 + lrow;
    const uint32_t aswz = (uint32_t)((arow & 7) << 4);
    const uint32_t abase = arow * 128 + cb;

    for (int kc = 0; kc < KC; kc++) {
        __syncthreads();
        if (kc + 1 < KC) {
            size_t goA = tA0 + (size_t)(kc + 1) * 16384;
            size_t goB = tB0 + (size_t)(kc + 1) * 16384;
            const char* sA0 = Ah + goA + tid * 16;
            const char* sA1 = Al + goA + tid * 16;
            const char* sB0 = Bh + goB + tid * 16;
            const char* sB1 = Bl + goB + tid * 16;
            uint32_t d0 = smemS + ((kc + 1) & 1) * 49152 + tid * 16;
#pragma unroll
            for (int i = 0; i < 4; i++) {
                CP_ASYNC16(d0 + i * 4096,         sA0 + i * 4096);
                CP_ASYNC16(d0 + 16384 + i * 4096, sA1 + i * 4096);
            }
#pragma unroll
            for (int i = 0; i < 2; i++) {
                CP_ASYNC16(d0 + 32768 + i * 4096, sB0 + i * 4096);
                CP_ASYNC16(d0 + 40960 + i * 4096, sB1 + i * 4096);
            }
            CP_COMMIT();
            CP_WAIT1();
        } else {
            CP_WAIT0();
        }
        __syncthreads();

        uint32_t buf = smemS + (kc & 1) * 49152;
        const uint32_t aHs = buf, aLs = buf + 16384, bHs = buf + 32768, bLs = buf + 40960;

#pragma unroll
        for (int ks = 0; ks < 4; ks++) {
            uint32_t ah[4], al[4];
            {
                uint32_t sw = (abase + ks * 32) ^ aswz;
                LDMX4(ah, aHs + sw);
                LDMX4(al, aLs + sw);
            }
#pragma unroll
            for (int nf2 = 0; nf2 < 4; nf2++) {
                int row = nf2 * 16 + lrow;
                uint32_t sw = (uint32_t)(row * 128 + ks * 32 + cb) ^ ((row & 7) << 4);
                uint32_t bh[4], bl[4];
                LDMX4(bh, bHs + sw);
                LDMX4(bl, bLs + sw);
                float* d0 = acc[2 * nf2];
                float* d1 = acc[2 * nf2 + 1];
                mma_bf16(d0, ah[0], ah[1], ah[2], ah[3], bh[0], bh[2]);
                mma_bf16(d0, ah[0], ah[1], ah[2], ah[3], bl[0], bl[2]);
                mma_bf16(d0, al[0], al[1], al[2], al[3], bh[0], bh[2]);
                mma_bf16(d1, ah[0], ah[1], ah[2], ah[3], bh[1], bh[3]);
                mma_bf16(d1, ah[0], ah[1], ah[2], ah[3], bl[1], bl[3]);
                mma_bf16(d1, al[0], al[1], al[2], al[3], bh[1], bh[3]);
            }
        }
    }

    const int r0l = lane >> 2;
    const int c2  = (lane & 3) * 2;

    if (MODE == 0) {
        const int m0 = blockIdx.y * 128 + warp * 16 + r0l;
        const int n0 = jcol * 64;
#pragma unroll
        for (int nf = 0; nf < 8; nf++) {
            int n = n0 + nf * 8 + c2;
            *(float2*)(Cout + (size_t)m0 * Nt + n)       = make_float2(acc[nf][0], acc[nf][1]);
            *(float2*)(Cout + (size_t)(m0 + 8) * Nt + n) = make_float2(acc[nf][2], acc[nf][3]);
        }
    } else {
        const int which = jcol >> 4;     // 0:q 1:k 2:v
        const int h = jcol & 15;
        const int m0 = blockIdx.y * 128 + warp * 16 + r0l;
        const int m1 = m0 + 8;
        const int b0i = m0 >> 11, n0i = m0 & 2047;
        const int b1i = m1 >> 11, n1i = m1 & 2047;

        if (which == 2) {
            float* vb = g_v;
#pragma unroll
            for (int nf = 0; nf < 8; nf++) {
                int dd = nf * 8 + c2;
                *(float2*)&vb[(((size_t)(b0i * NH + h)) * NSEQ + n0i) * HDIM + dd] =
                    make_float2(acc[nf][0], acc[nf][1]);
                *(float2*)&vb[(((size_t)(b1i * NH + h)) * NSEQ + n1i) * HDIM + dd] =
                    make_float2(acc[nf][2], acc[nf][3]);
            }
        } else {
            const float* w = (which == 0) ? qw : kw;
            char* dh = (which == 0) ? (char*)gQh : (char*)gKh;
            char* dl = (which == 0) ? (char*)gQl : (char*)gKl;
            float ss0 = 0.f, ss1 = 0.f;
#pragma unroll
            for (int nf = 0; nf < 8; nf++) {
                ss0 += acc[nf][0] * acc[nf][0] + acc[nf][1] * acc[nf][1];
                ss1 += acc[nf][2] * acc[nf][2] + acc[nf][3] * acc[nf][3];
            }
            ss0 += __shfl_xor_sync(0xffffffffu, ss0, 1);
            ss0 += __shfl_xor_sync(0xffffffffu, ss0, 2);
            ss1 += __shfl_xor_sync(0xffffffffu, ss1, 1);
            ss1 += __shfl_xor_sync(0xffffffffu, ss1, 2);
            float r0 = rsqrtf(ss0 * (1.0f / HDIM) + 1e-6f);
            float r1 = rsqrtf(ss1 * (1.0f / HDIM) + 1e-6f);

            size_t tb0 = (((size_t)(b0i * NH + h)) * 16 + (n0i >> 7)) * 16384;
            size_t tb1 = (((size_t)(b1i * NH + h)) * 16 + (n1i >> 7)) * 16384;
            int lr0 = n0i & 127, lr1 = n1i & 127;
            uint32_t x0 = (lr0 & 7) << 4, x1 = (lr1 & 7) << 4;
#pragma unroll
            for (int nf = 0; nf < 8; nf++) {
                int dd = nf * 8 + c2;
                float2 wv = *(const float2*)(w + dd);
                float v0 = acc[nf][0] * r0 * wv.x;
                float v1 = acc[nf][1] * r0 * wv.y;
                float v2 = acc[nf][2] * r1 * wv.x;
                float v3 = acc[nf][3] * r1 * wv.y;
                uint32_t u0 = __float_as_uint(v0), u1 = __float_as_uint(v1);
                uint32_t u2 = __float_as_uint(v2), u3 = __float_as_uint(v3);
                uint32_t o0 = (lr0 * 128 + dd * 2) ^ x0;
                uint32_t o1 = (lr1 * 128 + dd * 2) ^ x1;
                *(uint32_t*)(dh + tb0 + o0) = pack2_hi(u0, u1);
                *(uint32_t*)(dh + tb1 + o1) = pack2_hi(u2, u3);
                *(uint32_t*)(dl + tb0 + o0) =
                    pack2_bf16(v0 - __uint_as_float(u0 & 0xFFFF0000u),
                               v1 - __uint_as_float(u1 & 0xFFFF0000u));
                *(uint32_t*)(dl + tb1 + o1) =
                    pack2_bf16(v2 - __uint_as_float(u2 & 0xFFFF0000u),
                               v3 - __uint_as_float(u3 & 0xFFFF0000u));
            }
        }
    }
}

// ---------------- V transpose + split ----------------
__global__ void __launch_bounds__(256)
vsplit_kernel()
{
    __shared__ float stg[64][65];
    const int kt = blockIdx.x, bh = blockIdx.y;
    const int tid = threadIdx.x;
    {
        int s = tid >> 2, d0 = (tid & 3) * 16;
        const float* vp = g_v + ((size_t)bh * NSEQ + kt * 64 + s) * HDIM + d0;
#pragma unroll
        for (int i = 0; i < 4; i++) {
            float4 v = *(const float4*)(vp + i * 4);
            stg[s][d0 + i * 4 + 0] = v.x;
            stg[s][d0 + i * 4 + 1] = v.y;
            stg[s][d0 + i * 4 + 2] = v.z;
            stg[s][d0 + i * 4 + 3] = v.w;
        }
    }
    __syncthreads();
    {
        int dR = tid >> 2, c0 = (tid & 3) * 16;
        uint32_t hw[8], lw[8];
#pragma unroll
        for (int j = 0; j < 8; j++) {
            float f0 = stg[c0 + 2 * j][dR];
            float f1 = stg[c0 + 2 * j + 1][dR];
            uint32_t u0 = __float_as_uint(f0), u1 = __float_as_uint(f1);
            hw[j] = pack2_hi(u0, u1);
            float l0 = f0 - __uint_as_float(u0 & 0xFFFF0000u);
            float l1 = f1 - __uint_as_float(u1 & 0xFFFF0000u);
            lw[j] = pack2_bf16(l0, l1);
        }
        size_t tb = ((size_t)bh * 32 + kt) * 8192;
        uint32_t off0 = dR * 128 + c0 * 2;
        uint32_t x = (dR & 7) << 4;
        *(uint4*)((char*)gVth + tb + (off0 ^ x))        = make_uint4(hw[0], hw[1], hw[2], hw[3]);
        *(uint4*)((char*)gVth + tb + ((off0 + 16) ^ x)) = make_uint4(hw[4], hw[5], hw[6], hw[7]);
        *(uint4*)((char*)gVtl + tb + (off0 ^ x))        = make_uint4(lw[0], lw[1], lw[2], lw[3]);
        *(uint4*)((char*)gVtl + tb + ((off0 + 16) ^ x)) = make_uint4(lw[4], lw[5], lw[6], lw[7]);
    }
}

// ---------------- bias precompute ----------------
__global__ void __launch_bounds__(256)
bias_kernel(const float* __restrict__ cm, const float* __restrict__ im)
{
    int bq = blockIdx.x;
    int b = bq / NSEQ, q = bq % NSEQ;
    const float* cmb = cm + (size_t)b * NC * NSEQ;
    float c0 = cmb[q], c1 = cmb[NSEQ + q], c2 = cmb[2 * NSEQ + q], c3 = cmb[3 * NSEQ + q];

    float mx = 0.f;
    for (int k = threadIdx.x; k < NSEQ; k += 256) {
        float s = c0 * cmb[k] + c1 * cmb[NSEQ + k] + c2 * cmb[2 * NSEQ + k] + c3 * cmb[3 * NSEQ + k];
        mx = fmaxf(mx, s);
    }
    __shared__ float red[8];
#pragma unroll
    for (int o = 16; o > 0; o >>= 1) mx = fmaxf(mx, __shfl_xor_sync(0xffffffffu, mx, o));
    if ((threadIdx.x & 31) == 0) red[threadIdx.x >> 5] = mx;
    __syncthreads();
    if (threadIdx.x == 0) {
        float m = red[0];
#pragma unroll
        for (int wN = 1; wN < 8; wN++) m = fmaxf(m, red[wN]);
        red[0] = fmaxf(m, 1e-6f);
    }
    __syncthreads();
    float inv = 1.f / red[0];
    const float* imr = im + (size_t)bq * NSEQ;
    float* br = g_bias + (size_t)bq * NSEQ;
    for (int k = threadIdx.x; k < NSEQ; k += 256) {
        float s = c0 * cmb[k] + c1 * cmb[NSEQ + k] + c2 * cmb[2 * NSEQ + k] + c3 * cmb[3 * NSEQ + k];
        br[k] = 2.f * s * inv - 1.f + 0.3f * imr[k];
    }
}

// ---------------- HMMA flash attention: 80KB smem -> 2 CTAs/SM ----------------
// smem: Qlo 16KB | KVbuf0 32KB | KVbuf1 32KB.  Q-hi staged through KVbuf1 -> regs.
// KV buffer: Kh 8K | Kl 8K | Vth 8K | Vtl 8K.
#define ATTN2_SMEM (16384 + 2 * 32768)

__global__ void __launch_bounds__(256, 2)
attn2_kernel(const float* __restrict__ gate)
{
    extern __shared__ char smraw[];
    const uint32_t S = smem_u32(smraw);
    const uint32_t BUF0 = S + 16384;
    const int tid = threadIdx.x, lane = tid & 31, warp = tid >> 5;
    const int bh = blockIdx.y, b = bh >> 4, h = bh & 15;
    const int qt = blockIdx.x, q0 = qt * 128;
    const float LOG2E = 1.44269504f;
    const float g32 = 3.f * fminf(fmaxf(gate[h], 0.f), 1.f) * LOG2E;
    const float SC = 0.125f * LOG2E;
    const int lrow = lane & 15, cb = (lane >> 4) << 4;
    const int wrow = warp * 16;

    // prologue: one group — Qh -> BUF1 (staged), Ql -> Qlo slot, KV0 -> BUF0
    {
        size_t qoff = ((size_t)(bh * 16 + qt)) * 16384 + tid * 16;
        uint32_t dql = S + tid * 16;            // Qlo permanent
        uint32_t dqh = BUF0 + 32768 + tid * 16; // staged in BUF1
#pragma unroll
        for (int i = 0; i < 4; i++) {
            CP_ASYNC16(dqh + i * 4096, (const char*)gQh + qoff + i * 4096);
            CP_ASYNC16(dql + i * 4096, (const char*)gQl + qoff + i * 4096);
        }
        size_t koff = ((size_t)(bh * 16)) * 16384 + tid * 16;
        size_t voff = ((size_t)(bh * 32)) * 8192 + tid * 16;
        uint32_t dk = BUF0 + tid * 16;
#pragma unroll
        for (int i = 0; i < 2; i++) {
            CP_ASYNC16(dk + 0     + i * 4096, (const char*)gKh  + koff + i * 4096);
            CP_ASYNC16(dk + 8192  + i * 4096, (const char*)gKl  + koff + i * 4096);
            CP_ASYNC16(dk + 16384 + i * 4096, (const char*)gVth + voff + i * 4096);
            CP_ASYNC16(dk + 24576 + i * 4096, (const char*)gVtl + voff + i * 4096);
        }
        CP_COMMIT();
    }

    CP_WAIT0();
    __syncthreads();

    // extract Q-hi fragments from the staging area (BUF1) before it is overwritten
    uint32_t qh[4][4];
    {
        const int qrow = wrow + lrow;
        const uint32_t qswz = (uint32_t)((qrow & 7) << 4);
#pragma unroll
        for (int ks = 0; ks < 4; ks++) {
            uint32_t sw = (uint32_t)(qrow * 128 + ks * 32 + cb) ^ qswz;
            LDMX4(qh[ks], BUF0 + 32768 + sw);
        }
    }

    float o[8][4];
#pragma unroll
    for (int nf = 0; nf < 8; nf++)
#pragma unroll
        for (int t = 0; t < 4; t++) o[nf][t] = 0.f;
    float m0r = -1e30f, m1r = -1e30f, l0r = 0.f, l1r = 0.f;

    const int r0l = lane >> 2;
    const float* bias0 = g_bias + ((size_t)(b * NSEQ + q0 + wrow + r0l)) * NSEQ;
    const float* bias1 = bias0 + 8 * NSEQ;
    const uint32_t lswz = (uint32_t)((lrow & 7) << 4);
    const int qrow = wrow + lrow;
    const uint32_t qlbase = (uint32_t)(qrow * 128 + cb);
    const uint32_t qlswz = (uint32_t)((qrow & 7) << 4);

    for (int kt = 0; kt < 32; kt++) {
        __syncthreads();   // everyone done with the buffer about to be refilled (and Qh staging at kt=0)
        if (kt + 1 < 32) {
            int k2 = kt + 1;
            size_t koff = ((size_t)(bh * 16 + (k2 >> 1))) * 16384 + (size_t)(k2 & 1) * 8192 + tid * 16;
            size_t voff = ((size_t)(bh * 32 + k2)) * 8192 + tid * 16;
            uint32_t d = BUF0 + (k2 & 1) * 32768 + tid * 16;
#pragma unroll
            for (int i = 0; i < 2; i++) {
                CP_ASYNC16(d + 0     + i * 4096, (const char*)gKh  + koff + i * 4096);
                CP_ASYNC16(d + 8192  + i * 4096, (const char*)gKl  + koff + i * 4096);
                CP_ASYNC16(d + 16384 + i * 4096, (const char*)gVth + voff + i * 4096);
                CP_ASYNC16(d + 24576 + i * 4096, (const char*)gVtl + voff + i * 4096);
            }
            CP_COMMIT();
            CP_WAIT1();
        } else {
            CP_WAIT0();
        }
        __syncthreads();

        uint32_t buf = BUF0 + (kt & 1) * 32768;

        // --- S = Q K^T (3-term split; Q-lo LDSM'd per-ks from its permanent slot) ---
        float sf[8][4];
#pragma unroll
        for (int nf = 0; nf < 8; nf++)
#pragma unroll
            for (int t = 0; t < 4; t++) sf[nf][t] = 0.f;

#pragma unroll
        for (int ks = 0; ks < 4; ks++) {
            uint32_t qlf[4];
            {
                uint32_t sw = (qlbase + ks * 32) ^ qlswz;
                LDMX4(qlf, S + sw);
            }
#pragma unroll
            for (int nf2 = 0; nf2 < 4; nf2++) {
                int row = nf2 * 16 + lrow;
                uint32_t sw = (uint32_t)(row * 128 + ks * 32 + cb) ^ ((row & 7) << 4);
                uint32_t kh_[4], kl_[4];
                LDMX4(kh_, buf + sw);
                LDMX4(kl_, buf + 8192 + sw);
                float* d0 = sf[2 * nf2];
                float* d1 = sf[2 * nf2 + 1];
                mma_bf16(d0, qh[ks][0], qh[ks][1], qh[ks][2], qh[ks][3], kh_[0], kh_[2]);
                mma_bf16(d0, qh[ks][0], qh[ks][1], qh[ks][2], qh[ks][3], kl_[0], kl_[2]);
                mma_bf16(d0, qlf[0], qlf[1], qlf[2], qlf[3], kh_[0], kh_[2]);
                mma_bf16(d1, qh[ks][0], qh[ks][1], qh[ks][2], qh[ks][3], kh_[1], kh_[3]);
                mma_bf16(d1, qh[ks][0], qh[ks][1], qh[ks][2], qh[ks][3], kl_[1], kl_[3]);
                mma_bf16(d1, qlf[0], qlf[1], qlf[2], qlf[3], kh_[1], kh_[3]);
            }
        }

        // --- scale + gated bias + online softmax (log2 domain) ---
        int colbase = kt * 64 + 2 * (lane & 3);
        float rm0 = -1e30f, rm1 = -1e30f;
#pragma unroll
        for (int nf = 0; nf < 8; nf++) {
            float2 bb0 = *(const float2*)(bias0 + colbase + nf * 8);
            float2 bb1 = *(const float2*)(bias1 + colbase + nf * 8);
            sf[nf][0] = fmaf(sf[nf][0], SC, g32 * bb0.x);
            sf[nf][1] = fmaf(sf[nf][1], SC, g32 * bb0.y);
            sf[nf][2] = fmaf(sf[nf][2], SC, g32 * bb1.x);
            sf[nf][3] = fmaf(sf[nf][3], SC, g32 * bb1.y);
            rm0 = fmaxf(rm0, fmaxf(sf[nf][0], sf[nf][1]));
            rm1 = fmaxf(rm1, fmaxf(sf[nf][2], sf[nf][3]));
        }
        rm0 = fmaxf(rm0, __shfl_xor_sync(0xffffffffu, rm0, 1));
        rm0 = fmaxf(rm0, __shfl_xor_sync(0xffffffffu, rm0, 2));
        rm1 = fmaxf(rm1, __shfl_xor_sync(0xffffffffu, rm1, 1));
        rm1 = fmaxf(rm1, __shfl_xor_sync(0xffffffffu, rm1, 2));

        float mn0 = fmaxf(m0r, rm0), mn1 = fmaxf(m1r, rm1);
        float al0 = ex2f(m0r - mn0), al1 = ex2f(m1r - mn1);
        m0r = mn0; m1r = mn1;
        float rs0 = 0.f, rs1 = 0.f;
#pragma unroll
        for (int nf = 0; nf < 8; nf++) {
            sf[nf][0] = ex2f(sf[nf][0] - mn0);
            sf[nf][1] = ex2f(sf[nf][1] - mn0);
            sf[nf][2] = ex2f(sf[nf][2] - mn1);
            sf[nf][3] = ex2f(sf[nf][3] - mn1);
            rs0 += sf[nf][0] + sf[nf][1];
            rs1 += sf[nf][2] + sf[nf][3];
        }
        rs0 += __shfl_xor_sync(0xffffffffu, rs0, 1);
        rs0 += __shfl_xor_sync(0xffffffffu, rs0, 2);
        rs1 += __shfl_xor_sync(0xffffffffu, rs1, 1);
        rs1 += __shfl_xor_sync(0xffffffffu, rs1, 2);
        l0r = l0r * al0 + rs0;
        l1r = l1r * al1 + rs1;
#pragma unroll
        for (int nf = 0; nf < 8; nf++) {
            o[nf][0] *= al0; o[nf][1] *= al0;
            o[nf][2] *= al1; o[nf][3] *= al1;
        }

        // --- O += P V (P fragments from registers, hi/lo split) ---
        const uint32_t vHs = buf + 16384, vLs = buf + 24576;
#pragma unroll
        for (int kk = 0; kk < 4; kk++) {
            const int na = 2 * kk, nb = 2 * kk + 1;
            uint32_t u0 = __float_as_uint(sf[na][0]), u1 = __float_as_uint(sf[na][1]);
            uint32_t u2 = __float_as_uint(sf[na][2]), u3 = __float_as_uint(sf[na][3]);
            uint32_t w0 = __float_as_uint(sf[nb][0]), w1 = __float_as_uint(sf[nb][1]);
            uint32_t w2 = __float_as_uint(sf[nb][2]), w3 = __float_as_uint(sf[nb][3]);
            uint32_t ph_[4], pl_[4];
            ph_[0] = pack2_hi(u0, u1);
            ph_[1] = pack2_hi(u2, u3);
            ph_[2] = pack2_hi(w0, w1);
            ph_[3] = pack2_hi(w2, w3);
            pl_[0] = pack2_bf16(sf[na][0] - __uint_as_float(u0 & 0xFFFF0000u),
                                sf[na][1] - __uint_as_float(u1 & 0xFFFF0000u));
            pl_[1] = pack2_bf16(sf[na][2] - __uint_as_float(u2 & 0xFFFF0000u),
                                sf[na][3] - __uint_as_float(u3 & 0xFFFF0000u));
            pl_[2] = pack2_bf16(sf[nb][0] - __uint_as_float(w0 & 0xFFFF0000u),
                                sf[nb][1] - __uint_as_float(w1 & 0xFFFF0000u));
            pl_[3] = pack2_bf16(sf[nb][2] - __uint_as_float(w2 & 0xFFFF0000u),
                                sf[nb][3] - __uint_as_float(w3 & 0xFFFF0000u));
#pragma unroll
            for (int nf2 = 0; nf2 < 4; nf2++) {
                int row = nf2 * 16 + lrow;
                uint32_t sw = (uint32_t)(row * 128 + kk * 32 + cb) ^ ((row & 7) << 4);
                uint32_t vh_[4], vl_[4];
                LDMX4(vh_, vHs + sw);
                LDMX4(vl_, vLs + sw);
                float* d0 = o[2 * nf2];
                float* d1 = o[2 * nf2 + 1];
                mma_bf16(d0, ph_[0], ph_[1], ph_[2], ph_[3], vh_[0], vh_[2]);
                mma_bf16(d0, ph_[0], ph_[1], ph_[2], ph_[3], vl_[0], vl_[2]);
                mma_bf16(d0, pl_[0], pl_[1], pl_[2], pl_[3], vh_[0], vh_[2]);
                mma_bf16(d1, ph_[0], ph_[1], ph_[2], ph_[3], vh_[1], vh_[3]);
                mma_bf16(d1, ph_[0], ph_[1], ph_[2], ph_[3], vl_[1], vl_[3]);
                mma_bf16(d1, pl_[0], pl_[1], pl_[2], pl_[3], vh_[1], vh_[3]);
            }
        }
    }

    // epilogue: normalize + write bf16 hi/lo swizzled A-tile for the out-projection
    float i0 = 1.f / l0r, i1 = 1.f / l1r;
    size_t tb = (((size_t)(b * 16 + qt)) * 16 + h) * 16384;
    int lr0 = wrow + r0l, lr1 = lr0 + 8;
    uint32_t x0 = (lr0 & 7) << 4, x1 = (lr1 & 7) << 4;
#pragma unroll
    for (int nf = 0; nf < 8; nf++) {
        int dd = nf * 8 + 2 * (lane & 3);
        float v0 = o[nf][0] * i0, v1 = o[nf][1] * i0;
        float v2 = o[nf][2] * i1, v3 = o[nf][3] * i1;
        uint32_t u0 = __float_as_uint(v0), u1 = __float_as_uint(v1);
        uint32_t u2 = __float_as_uint(v2), u3 = __float_as_uint(v3);
        uint32_t o0 = (lr0 * 128 + dd * 2) ^ x0;
        uint32_t o1 = (lr1 * 128 + dd * 2) ^ x1;
        *(uint32_t*)((char*)gAh2 + tb + o0) = pack2_hi(u0, u1);
        *(uint32_t*)((char*)gAh2 + tb + o1) = pack2_hi(u2, u3);
        *(uint32_t*)((char*)gAl2 + tb + o0) =
            pack2_bf16(v0 - __uint_as_float(u0 & 0xFFFF0000u),
                       v1 - __uint_as_float(u1 & 0xFFFF0000u));
        *(uint32_t*)((char*)gAl2 + tb + o1) =
            pack2_bf16(v2 - __uint_as_float(u2 & 0xFFFF0000u),
                       v3 - __uint_as_float(u3 & 0xFFFF0000u));
    }
}

// ---------------- launch ----------------
extern "C" void kernel_launch(void* const* d_in, const int* in_sizes, int n_in,
                              void* d_out, int out_size)
{
    (void)in_sizes; (void)n_in; (void)out_size;
    const float* x    = (const float*)d_in[0];
    const float* cm   = (const float*)d_in[1];
    const float* im   = (const float*)d_in[2];
    const float* wqkv = (const float*)d_in[3];
    const float* wout = (const float*)d_in[4];
    const float* qnw  = (const float*)d_in[5];
    const float* knw  = (const float*)d_in[6];
    const float* gate = (const float*)d_in[7];
    float* out = (float*)d_out;

    void *xh, *xl, *wqh, *wql, *woh, *wol, *ah2, *al2;
    cudaGetSymbolAddress(&xh, gXh);   cudaGetSymbolAddress(&xl, gXl);
    cudaGetSymbolAddress(&wqh, gWqh); cudaGetSymbolAddress(&wql, gWql);
    cudaGetSymbolAddress(&woh, gWoh); cudaGetSymbolAddress(&wol, gWol);
    cudaGetSymbolAddress(&ah2, gAh2); cudaGetSymbolAddress(&al2, gAl2);

    cudaFuncSetAttribute(attn2_kernel, cudaFuncAttributeMaxDynamicSharedMemorySize, ATTN2_SMEM);
    cudaFuncSetAttribute(gemm_hmma<0>, cudaFuncAttributeMaxDynamicSharedMemorySize, GEMM_SMEM);
    cudaFuncSetAttribute(gemm_hmma<1>, cudaFuncAttributeMaxDynamicSharedMemorySize, GEMM_SMEM);

    const int M = BB * NSEQ;   // 4096

    // 1) split-convert inputs
    conv_split_kernel<<<(4096 * 1024 / 8) / 256, 256>>>(x,    (__nv_bfloat16*)xh,  (__nv_bfloat16*)xl,  1024);
    conv_split_kernel<<<(3072 * 1024 / 8) / 256, 256>>>(wqkv, (__nv_bfloat16*)wqh, (__nv_bfloat16*)wql, 1024);
    conv_split_kernel<<<(1024 * 1024 / 8) / 256, 256>>>(wout, (__nv_bfloat16*)woh, (__nv_bfloat16*)wol, 1024);

    // 2) QKV projection (HMMA, 2 CTAs/SM) with fused RMSNorm + split epilogue
    gemm_hmma<1><<<dim3(3 * DMOD / 64, M / 128), 256, GEMM_SMEM>>>(
        (const char*)xh, (const char*)xl, (const char*)wqh, (const char*)wql,
        nullptr, 1024 / 64, 3 * DMOD, qnw, knw);

    // 3) V -> transposed bf16 hi/lo tiles
    vsplit_kernel<<<dim3(NSEQ / 64, BH), 256>>>();

    // 4) bias precompute
    bias_kernel<<<BB * NSEQ, 256>>>(cm, im);

    // 5) HMMA flash attention (2 CTAs/SM; writes split A-tiles for out-proj)
    attn2_kernel<<<dim3(NSEQ / 128, BH), 256, ATTN2_SMEM>>>(gate);

    // 6) out-projection straight into d_out
    gemm_hmma<0><<<dim3(DMOD / 64, M / 128), 256, GEMM_SMEM>>>(
        (const char*)ah2, (const char*)al2, (const char*)woh, (const char*)wol,
        out, 1024 / 64, DMOD, nullptr, nullptr);
}

// round 10
// speedup vs baseline: 1.6793x; 1.0322x over previous
#include <cuda_runtime.h>
#include <cuda_bf16.h>
#include <math.h>
#include <stdint.h>

#define BB   2
#define NSEQ 2048
#define DMOD 1024
#define NH   16
#define HDIM 64
#define NC   4
#define BH   (BB * NH)

// ---------------- scratch (device globals; no allocation allowed) ----------------
__device__ float g_v[(size_t)BB * NH * NSEQ * HDIM];
__device__ float g_bias[(size_t)BB * NSEQ * NSEQ];

// bf16 split operands, pre-swizzled 128x64 SW128 tiles (16KB each)
__device__ __nv_bfloat16 gXh[(size_t)4096 * 1024];
__device__ __nv_bfloat16 gXl[(size_t)4096 * 1024];
__device__ __nv_bfloat16 gWqh[(size_t)3072 * 1024];
__device__ __nv_bfloat16 gWql[(size_t)3072 * 1024];
__device__ __nv_bfloat16 gWoh[(size_t)1024 * 1024];
__device__ __nv_bfloat16 gWol[(size_t)1024 * 1024];
__device__ __nv_bfloat16 gAh2[(size_t)4096 * 1024];
__device__ __nv_bfloat16 gAl2[(size_t)4096 * 1024];

// attention operands
__device__ __nv_bfloat16 gQh[(size_t)BH * NSEQ * HDIM];
__device__ __nv_bfloat16 gQl[(size_t)BH * NSEQ * HDIM];
__device__ __nv_bfloat16 gKh[(size_t)BH * NSEQ * HDIM];
__device__ __nv_bfloat16 gKl[(size_t)BH * NSEQ * HDIM];
__device__ __nv_bfloat16 gVth[(size_t)BH * NSEQ * HDIM];
__device__ __nv_bfloat16 gVtl[(size_t)BH * NSEQ * HDIM];

// ---------------- PTX helpers (base sm_103-legal only) ----------------
__device__ __forceinline__ uint32_t smem_u32(const void* p) {
    uint32_t a;
    asm("{ .reg .u64 t; cvta.to.shared.u64 t, %1; cvt.u32.u64 %0, t; }" : "=r"(a) : "l"(p));
    return a;
}

#define CP_ASYNC16(dst, src) \
    asm volatile("cp.async.cg.shared.global [%0], [%1], 16;" :: "r"(dst), "l"(src) : "memory")
#define CP_COMMIT() asm volatile("cp.async.commit_group;" ::: "memory")
#define CP_WAIT0()  asm volatile("cp.async.wait_group 0;" ::: "memory")
#define CP_WAIT1()  asm volatile("cp.async.wait_group 1;" ::: "memory")

#define LDMX4(r, a) \
    asm volatile("ldmatrix.sync.aligned.m8n8.x4.shared.b16 {%0,%1,%2,%3}, [%4];" \
        : "=r"((r)[0]), "=r"((r)[1]), "=r"((r)[2]), "=r"((r)[3]) : "r"(a))

__device__ __forceinline__ void mma_bf16(float* d, uint32_t a0, uint32_t a1,
                                         uint32_t a2, uint32_t a3,
                                         uint32_t b0, uint32_t b1) {
    asm volatile(
        "mma.sync.aligned.m16n8k16.row.col.f32.bf16.bf16.f32 "
        "{%0,%1,%2,%3},{%4,%5,%6,%7},{%8,%9},{%0,%1,%2,%3};"
        : "+f"(d[0]), "+f"(d[1]), "+f"(d[2]), "+f"(d[3])
        : "r"(a0), "r"(a1), "r"(a2), "r"(a3), "r"(b0), "r"(b1));
}

__device__ __forceinline__ uint32_t pack2_bf16(float lo, float hi) {
    uint32_t r;
    asm("cvt.rn.bf16x2.f32 %0, %1, %2;" : "=r"(r) : "f"(hi), "f"(lo));
    return r;
}
__device__ __forceinline__ uint32_t pack2_hi(uint32_t u0, uint32_t u1) {
    uint32_t r;
    asm("prmt.b32 %0, %1, %2, 0x7632;" : "=r"(r) : "r"(u0), "r"(u1));
    return r;
}
__device__ __forceinline__ float ex2f(float x) {
    float r;
    asm("ex2.approx.f32 %0, %1;" : "=f"(r) : "f"(x));
    return r;
}

// ---------------- split-conversion: fp32 row-major -> blocked swizzled bf16 hi/lo ----------------
__global__ void __launch_bounds__(256)
conv_split_kernel(const float* __restrict__ src, __nv_bfloat16* __restrict__ dh,
                  __nv_bfloat16* __restrict__ dl, int K)
{
    size_t idx = ((size_t)blockIdx.x * 256 + threadIdx.x) * 8;
    int r  = (int)(idx / K);
    int c0 = (int)(idx % K);
    float4 v0 = *(const float4*)(src + idx);
    float4 v1 = *(const float4*)(src + idx + 4);
    float f[8] = {v0.x, v0.y, v0.z, v0.w, v1.x, v1.y, v1.z, v1.w};
    __nv_bfloat16 h[8], l[8];
#pragma unroll
    for (int i = 0; i < 8; i++) {
        h[i] = __float2bfloat16(f[i]);
        l[i] = __float2bfloat16(f[i] - __bfloat162float(h[i]));
    }
    int rt = r >> 7, lr = r & 127, ch = c0 >> 6, lc = c0 & 63;
    size_t tile = (size_t)rt * (K >> 6) + ch;
    uint32_t off = lr * 128 + lc * 2;
    uint32_t sw = off ^ ((off >> 3) & 0x70);
    size_t db = tile * 16384 + sw;
    *(uint4*)((char*)dh + db) = *(uint4*)h;
    *(uint4*)((char*)dl + db) = *(uint4*)l;
}

// ---------------- HMMA GEMM: 128 threads, 4 warps, warp tile 32x64, CTA tile 128x64 ----------------
// 48KB/buffer double-buffered -> 96KB smem -> 2 CTAs/SM. B-frags reused across 2 m-frags.
#define GEMM_SMEM (2 * 48 * 1024)

template <int MODE>
__global__ void __launch_bounds__(128, 2)
gemm_hmma(const char* __restrict__ Ah, const char* __restrict__ Al,
          const char* __restrict__ Bh, const char* __restrict__ Bl,
          float* __restrict__ Cout, int KC, int Nt,
          const float* __restrict__ qw, const float* __restrict__ kw)
{
    extern __shared__ char smraw[];
    const uint32_t smemS = smem_u32(smraw);
    const int tid  = threadIdx.x;
    const int lane = tid & 31;
    const int warp = tid >> 5;          // 0..3, owns rows warp*32..warp*32+31
    const int jcol = blockIdx.x;        // 64-col chunk index

    const size_t tA0 = (size_t)blockIdx.y * KC * 16384;
    const size_t tB0 = ((size_t)(jcol >> 1) * KC) * 16384 + (size_t)(jcol & 1) * 8192;

    float acc[2][8][4];
#pragma unroll
    for (int m = 0; m < 2; m++)
#pragma unroll
        for (int j = 0; j < 8; j++)
#pragma unroll
            for (int t = 0; t < 4; t++) acc[m][j][t] = 0.f;

    const int lrow = lane & 15;
    const int cb   = (lane >> 4) << 4;

    // buffer layout (48KB): Ah 0..16K | Al 16K..32K | Bh 32K..40K | Bl 40K..48K
    // prologue: chunk 0 into buffer 0  (128 threads x 24 x 16B)
    {
        const char* sA0 = Ah + tA0 + tid * 16;
        const char* sA1 = Al + tA0 + tid * 16;
        const char* sB0 = Bh + tB0 + tid * 16;
        const char* sB1 = Bl + tB0 + tid * 16;
        uint32_t d0 = smemS + tid * 16;
#pragma unroll
        for (int i = 0; i < 8; i++) {
            CP_ASYNC16(d0 + i * 2048,         sA0 + i * 2048);
            CP_ASYNC16(d0 + 16384 + i * 2048, sA1 + i * 2048);
        }
#pragma unroll
        for (int i = 0; i < 4; i++) {
            CP_ASYNC16(d0 + 32768 + i * 2048, sB0 + i * 2048);
            CP_ASYNC16(d0 + 40960 + i * 2048, sB1 + i * 2048);
        }
        CP_COMMIT();
    }

    for (int kc = 0; kc < KC; kc++) {
        __syncthreads();
        if (kc + 1 < KC) {
            size_t goA = tA0 + (size_t)(kc + 1) * 16384;
            size_t goB = tB0 + (size_t)(kc + 1) * 16384;
            const char* sA0 = Ah + goA + tid * 16;
            const char* sA1 = Al + goA + tid * 16;
            const char* sB0 = Bh + goB + tid * 16;
            const char* sB1 = Bl + goB + tid * 16;
            uint32_t d0 = smemS + ((kc + 1) & 1) * 49152 + tid * 16;
#pragma unroll
            for (int i = 0; i < 8; i++) {
                CP_ASYNC16(d0 + i * 2048,         sA0 + i * 2048);
                CP_ASYNC16(d0 + 16384 + i * 2048, sA1 + i * 2048);
            }
#pragma unroll
            for (int i = 0; i < 4; i++) {
                CP_ASYNC16(d0 + 32768 + i * 2048, sB0 + i * 2048);
                CP_ASYNC16(d0 + 40960 + i * 2048, sB1 + i * 2048);
            }
            CP_COMMIT();
            CP_WAIT1();
        } else {
            CP_WAIT0();
        }
        __syncthreads();

        uint32_t buf = smemS + (kc & 1) * 49152;
        const uint32_t aHs = buf, aLs = buf + 16384, bHs = buf + 32768, bLs = buf + 40960;

#pragma unroll
        for (int ks = 0; ks < 4; ks++) {
            uint32_t ah[2][4], al[2][4];
#pragma unroll
            for (int mf = 0; mf < 2; mf++) {
                int row = warp * 32 + mf * 16 + lrow;
                uint32_t sw = (uint32_t)(row * 128 + ks * 32 + cb) ^ ((row & 7) << 4);
                LDMX4(ah[mf], aHs + sw);
                LDMX4(al[mf], aLs + sw);
            }
#pragma unroll
            for (int nf2 = 0; nf2 < 4; nf2++) {
                int row = nf2 * 16 + lrow;
                uint32_t sw = (uint32_t)(row * 128 + ks * 32 + cb) ^ ((row & 7) << 4);
                uint32_t bh[4], bl[4];
                LDMX4(bh, bHs + sw);
                LDMX4(bl, bLs + sw);
#pragma unroll
                for (int mf = 0; mf < 2; mf++) {
                    float* d0 = acc[mf][2 * nf2];
                    float* d1 = acc[mf][2 * nf2 + 1];
                    mma_bf16(d0, ah[mf][0], ah[mf][1], ah[mf][2], ah[mf][3], bh[0], bh[2]);
                    mma_bf16(d0, ah[mf][0], ah[mf][1], ah[mf][2], ah[mf][3], bl[0], bl[2]);
                    mma_bf16(d0, al[mf][0], al[mf][1], al[mf][2], al[mf][3], bh[0], bh[2]);
                    mma_bf16(d1, ah[mf][0], ah[mf][1], ah[mf][2], ah[mf][3], bh[1], bh[3]);
                    mma_bf16(d1, ah[mf][0], ah[mf][1], ah[mf][2], ah[mf][3], bl[1], bl[3]);
                    mma_bf16(d1, al[mf][0], al[mf][1], al[mf][2], al[mf][3], bh[1], bh[3]);
                }
            }
        }
    }

    const int r0l = lane >> 2;
    const int c2  = (lane & 3) * 2;

    if (MODE == 0) {
        const int n0 = jcol * 64;
#pragma unroll
        for (int mf = 0; mf < 2; mf++) {
            const int m0 = blockIdx.y * 128 + warp * 32 + mf * 16 + r0l;
#pragma unroll
            for (int nf = 0; nf < 8; nf++) {
                int n = n0 + nf * 8 + c2;
                *(float2*)(Cout + (size_t)m0 * Nt + n)       = make_float2(acc[mf][nf][0], acc[mf][nf][1]);
                *(float2*)(Cout + (size_t)(m0 + 8) * Nt + n) = make_float2(acc[mf][nf][2], acc[mf][nf][3]);
            }
        }
    } else {
        const int which = jcol >> 4;     // 0:q 1:k 2:v
        const int h = jcol & 15;
#pragma unroll
        for (int mf = 0; mf < 2; mf++) {
            const int m0 = blockIdx.y * 128 + warp * 32 + mf * 16 + r0l;
            const int m1 = m0 + 8;
            const int b0i = m0 >> 11, n0i = m0 & 2047;
            const int b1i = m1 >> 11, n1i = m1 & 2047;

            if (which == 2) {
                float* vb = g_v;
#pragma unroll
                for (int nf = 0; nf < 8; nf++) {
                    int dd = nf * 8 + c2;
                    *(float2*)&vb[(((size_t)(b0i * NH + h)) * NSEQ + n0i) * HDIM + dd] =
                        make_float2(acc[mf][nf][0], acc[mf][nf][1]);
                    *(float2*)&vb[(((size_t)(b1i * NH + h)) * NSEQ + n1i) * HDIM + dd] =
                        make_float2(acc[mf][nf][2], acc[mf][nf][3]);
                }
            } else {
                const float* w = (which == 0) ? qw : kw;
                char* dh = (which == 0) ? (char*)gQh : (char*)gKh;
                char* dl = (which == 0) ? (char*)gQl : (char*)gKl;
                float ss0 = 0.f, ss1 = 0.f;
#pragma unroll
                for (int nf = 0; nf < 8; nf++) {
                    ss0 += acc[mf][nf][0] * acc[mf][nf][0] + acc[mf][nf][1] * acc[mf][nf][1];
                    ss1 += acc[mf][nf][2] * acc[mf][nf][2] + acc[mf][nf][3] * acc[mf][nf][3];
                }
                ss0 += __shfl_xor_sync(0xffffffffu, ss0, 1);
                ss0 += __shfl_xor_sync(0xffffffffu, ss0, 2);
                ss1 += __shfl_xor_sync(0xffffffffu, ss1, 1);
                ss1 += __shfl_xor_sync(0xffffffffu, ss1, 2);
                float r0 = rsqrtf(ss0 * (1.0f / HDIM) + 1e-6f);
                float r1 = rsqrtf(ss1 * (1.0f / HDIM) + 1e-6f);

                size_t tb0 = (((size_t)(b0i * NH + h)) * 16 + (n0i >> 7)) * 16384;
                size_t tb1 = (((size_t)(b1i * NH + h)) * 16 + (n1i >> 7)) * 16384;
                int lr0 = n0i & 127, lr1 = n1i & 127;
                uint32_t x0 = (lr0 & 7) << 4, x1 = (lr1 & 7) << 4;
#pragma unroll
                for (int nf = 0; nf < 8; nf++) {
                    int dd = nf * 8 + c2;
                    float2 wv = *(const float2*)(w + dd);
                    float v0 = acc[mf][nf][0] * r0 * wv.x;
                    float v1 = acc[mf][nf][1] * r0 * wv.y;
                    float v2 = acc[mf][nf][2] * r1 * wv.x;
                    float v3 = acc[mf][nf][3] * r1 * wv.y;
                    uint32_t u0 = __float_as_uint(v0), u1 = __float_as_uint(v1);
                    uint32_t u2 = __float_as_uint(v2), u3 = __float_as_uint(v3);
                    uint32_t o0 = (lr0 * 128 + dd * 2) ^ x0;
                    uint32_t o1 = (lr1 * 128 + dd * 2) ^ x1;
                    *(uint32_t*)(dh + tb0 + o0) = pack2_hi(u0, u1);
                    *(uint32_t*)(dh + tb1 + o1) = pack2_hi(u2, u3);
                    *(uint32_t*)(dl + tb0 + o0) =
                        pack2_bf16(v0 - __uint_as_float(u0 & 0xFFFF0000u),
                                   v1 - __uint_as_float(u1 & 0xFFFF0000u));
                    *(uint32_t*)(dl + tb1 + o1) =
                        pack2_bf16(v2 - __uint_as_float(u2 & 0xFFFF0000u),
                                   v3 - __uint_as_float(u3 & 0xFFFF0000u));
                }
            }
        }
    }
}

// ---------------- V transpose + split ----------------
__global__ void __launch_bounds__(256)
vsplit_kernel()
{
    __shared__ float stg[64][65];
    const int kt = blockIdx.x, bh = blockIdx.y;
    const int tid = threadIdx.x;
    {
        int s = tid >> 2, d0 = (tid & 3) * 16;
        const float* vp = g_v + ((size_t)bh * NSEQ + kt * 64 + s) * HDIM + d0;
#pragma unroll
        for (int i = 0; i < 4; i++) {
            float4 v = *(const float4*)(vp + i * 4);
            stg[s][d0 + i * 4 + 0] = v.x;
            stg[s][d0 + i * 4 + 1] = v.y;
            stg[s][d0 + i * 4 + 2] = v.z;
            stg[s][d0 + i * 4 + 3] = v.w;
        }
    }
    __syncthreads();
    {
        int dR = tid >> 2, c0 = (tid & 3) * 16;
        uint32_t hw[8], lw[8];
#pragma unroll
        for (int j = 0; j < 8; j++) {
            float f0 = stg[c0 + 2 * j][dR];
            float f1 = stg[c0 + 2 * j + 1][dR];
            uint32_t u0 = __float_as_uint(f0), u1 = __float_as_uint(f1);
            hw[j] = pack2_hi(u0, u1);
            float l0 = f0 - __uint_as_float(u0 & 0xFFFF0000u);
            float l1 = f1 - __uint_as_float(u1 & 0xFFFF0000u);
            lw[j] = pack2_bf16(l0, l1);
        }
        size_t tb = ((size_t)bh * 32 + kt) * 8192;
        uint32_t off0 = dR * 128 + c0 * 2;
        uint32_t x = (dR & 7) << 4;
        *(uint4*)((char*)gVth + tb + (off0 ^ x))        = make_uint4(hw[0], hw[1], hw[2], hw[3]);
        *(uint4*)((char*)gVth + tb + ((off0 + 16) ^ x)) = make_uint4(hw[4], hw[5], hw[6], hw[7]);
        *(uint4*)((char*)gVtl + tb + (off0 ^ x))        = make_uint4(lw[0], lw[1], lw[2], lw[3]);
        *(uint4*)((char*)gVtl + tb + ((off0 + 16) ^ x)) = make_uint4(lw[4], lw[5], lw[6], lw[7]);
    }
}

// ---------------- bias precompute ----------------
__global__ void __launch_bounds__(256)
bias_kernel(const float* __restrict__ cm, const float* __restrict__ im)
{
    int bq = blockIdx.x;
    int b = bq / NSEQ, q = bq % NSEQ;
    const float* cmb = cm + (size_t)b * NC * NSEQ;
    float c0 = cmb[q], c1 = cmb[NSEQ + q], c2 = cmb[2 * NSEQ + q], c3 = cmb[3 * NSEQ + q];

    float mx = 0.f;
    for (int k = threadIdx.x; k < NSEQ; k += 256) {
        float s = c0 * cmb[k] + c1 * cmb[NSEQ + k] + c2 * cmb[2 * NSEQ + k] + c3 * cmb[3 * NSEQ + k];
        mx = fmaxf(mx, s);
    }
    __shared__ float red[8];
#pragma unroll
    for (int o = 16; o > 0; o >>= 1) mx = fmaxf(mx, __shfl_xor_sync(0xffffffffu, mx, o));
    if ((threadIdx.x & 31) == 0) red[threadIdx.x >> 5] = mx;
    __syncthreads();
    if (threadIdx.x == 0) {
        float m = red[0];
#pragma unroll
        for (int wN = 1; wN < 8; wN++) m = fmaxf(m, red[wN]);
        red[0] = fmaxf(m, 1e-6f);
    }
    __syncthreads();
    float inv = 1.f / red[0];
    const float* imr = im + (size_t)bq * NSEQ;
    float* br = g_bias + (size_t)bq * NSEQ;
    for (int k = threadIdx.x; k < NSEQ; k += 256) {
        float s = c0 * cmb[k] + c1 * cmb[NSEQ + k] + c2 * cmb[2 * NSEQ + k] + c3 * cmb[3 * NSEQ + k];
        br[k] = 2.f * s * inv - 1.f + 0.3f * imr[k];
    }
}

// ---------------- HMMA flash attention: 128 threads, 4 warps, warp tile 32q x 64k ----------------
// smem: Qlo 16KB | KVbuf0 32KB | KVbuf1 32KB = 80KB -> 2 CTAs/SM. K/V frags reused across 2 m-frags.
#define ATTN2_SMEM (16384 + 2 * 32768)

__global__ void __launch_bounds__(128, 2)
attn2_kernel(const float* __restrict__ gate)
{
    extern __shared__ char smraw[];
    const uint32_t S = smem_u32(smraw);
    const uint32_t BUF0 = S + 16384;
    const int tid = threadIdx.x, lane = tid & 31, warp = tid >> 5;   // 4 warps
    const int bh = blockIdx.y, b = bh >> 4, h = bh & 15;
    const int qt = blockIdx.x, q0 = qt * 128;
    const float LOG2E = 1.44269504f;
    const float g32 = 3.f * fminf(fmaxf(gate[h], 0.f), 1.f) * LOG2E;
    const float SC = 0.125f * LOG2E;
    const int lrow = lane & 15, cb = (lane >> 4) << 4;
    const int wrow = warp * 32;

    // prologue: Qh -> BUF1 staging, Ql -> permanent slot, KV0 -> BUF0 (128 thr)
    {
        size_t qoff = ((size_t)(bh * 16 + qt)) * 16384 + tid * 16;
        uint32_t dql = S + tid * 16;
        uint32_t dqh = BUF0 + 32768 + tid * 16;
#pragma unroll
        for (int i = 0; i < 8; i++) {
            CP_ASYNC16(dqh + i * 2048, (const char*)gQh + qoff + i * 2048);
            CP_ASYNC16(dql + i * 2048, (const char*)gQl + qoff + i * 2048);
        }
        size_t koff = ((size_t)(bh * 16)) * 16384 + tid * 16;
        size_t voff = ((size_t)(bh * 32)) * 8192 + tid * 16;
        uint32_t dk = BUF0 + tid * 16;
#pragma unroll
        for (int i = 0; i < 4; i++) {
            CP_ASYNC16(dk + 0     + i * 2048, (const char*)gKh  + koff + i * 2048);
            CP_ASYNC16(dk + 8192  + i * 2048, (const char*)gKl  + koff + i * 2048);
            CP_ASYNC16(dk + 16384 + i * 2048, (const char*)gVth + voff + i * 2048);
            CP_ASYNC16(dk + 24576 + i * 2048, (const char*)gVtl + voff + i * 2048);
        }
        CP_COMMIT();
    }

    CP_WAIT0();
    __syncthreads();

    // extract Q-hi fragments (both m-frags) from the BUF1 staging before it is overwritten
    uint32_t qh[2][4][4];
#pragma unroll
    for (int mf = 0; mf < 2; mf++) {
        int qrow = wrow + mf * 16 + lrow;
        uint32_t qswz = (uint32_t)((qrow & 7) << 4);
#pragma unroll
        for (int ks = 0; ks < 4; ks++) {
            uint32_t sw = (uint32_t)(qrow * 128 + ks * 32 + cb) ^ qswz;
            LDMX4(qh[mf][ks], BUF0 + 32768 + sw);
        }
    }

    float o[2][8][4];
#pragma unroll
    for (int mf = 0; mf < 2; mf++)
#pragma unroll
        for (int nf = 0; nf < 8; nf++)
#pragma unroll
            for (int t = 0; t < 4; t++) o[mf][nf][t] = 0.f;
    float mr[4] = {-1e30f, -1e30f, -1e30f, -1e30f};
    float lr[4] = {0.f, 0.f, 0.f, 0.f};

    const int r0l = lane >> 2;
    const float* biasP[4];
#pragma unroll
    for (int rr = 0; rr < 4; rr++)
        biasP[rr] = g_bias + ((size_t)(b * NSEQ + q0 + wrow + (rr >> 1) * 16 + (rr & 1) * 8 + r0l)) * NSEQ;

    for (int kt = 0; kt < 32; kt++) {
        __syncthreads();
        if (kt + 1 < 32) {
            int k2 = kt + 1;
            size_t koff = ((size_t)(bh * 16 + (k2 >> 1))) * 16384 + (size_t)(k2 & 1) * 8192 + tid * 16;
            size_t voff = ((size_t)(bh * 32 + k2)) * 8192 + tid * 16;
            uint32_t d = BUF0 + (k2 & 1) * 32768 + tid * 16;
#pragma unroll
            for (int i = 0; i < 4; i++) {
                CP_ASYNC16(d + 0     + i * 2048, (const char*)gKh  + koff + i * 2048);
                CP_ASYNC16(d + 8192  + i * 2048, (const char*)gKl  + koff + i * 2048);
                CP_ASYNC16(d + 16384 + i * 2048, (const char*)gVth + voff + i * 2048);
                CP_ASYNC16(d + 24576 + i * 2048, (const char*)gVtl + voff + i * 2048);
            }
            CP_COMMIT();
            CP_WAIT1();
        } else {
            CP_WAIT0();
        }
        __syncthreads();

        uint32_t buf = BUF0 + (kt & 1) * 32768;

        // --- S = Q K^T (3-term split; K frags shared across both m-frags) ---
        float sf[2][8][4];
#pragma unroll
        for (int mf = 0; mf < 2; mf++)
#pragma unroll
            for (int nf = 0; nf < 8; nf++)
#pragma unroll
                for (int t = 0; t < 4; t++) sf[mf][nf][t] = 0.f;

#pragma unroll
        for (int ks = 0; ks < 4; ks++) {
            uint32_t qlf[2][4];
#pragma unroll
            for (int mf = 0; mf < 2; mf++) {
                int qrow = wrow + mf * 16 + lrow;
                uint32_t sw = (uint32_t)(qrow * 128 + ks * 32 + cb) ^ ((qrow & 7) << 4);
                LDMX4(qlf[mf], S + sw);
            }
#pragma unroll
            for (int nf2 = 0; nf2 < 4; nf2++) {
                int row = nf2 * 16 + lrow;
                uint32_t sw = (uint32_t)(row * 128 + ks * 32 + cb) ^ ((row & 7) << 4);
                uint32_t kh_[4], kl_[4];
                LDMX4(kh_, buf + sw);
                LDMX4(kl_, buf + 8192 + sw);
#pragma unroll
                for (int mf = 0; mf < 2; mf++) {
                    float* d0 = sf[mf][2 * nf2];
                    float* d1 = sf[mf][2 * nf2 + 1];
                    mma_bf16(d0, qh[mf][ks][0], qh[mf][ks][1], qh[mf][ks][2], qh[mf][ks][3], kh_[0], kh_[2]);
                    mma_bf16(d0, qh[mf][ks][0], qh[mf][ks][1], qh[mf][ks][2], qh[mf][ks][3], kl_[0], kl_[2]);
                    mma_bf16(d0, qlf[mf][0], qlf[mf][1], qlf[mf][2], qlf[mf][3], kh_[0], kh_[2]);
                    mma_bf16(d1, qh[mf][ks][0], qh[mf][ks][1], qh[mf][ks][2], qh[mf][ks][3], kh_[1], kh_[3]);
                    mma_bf16(d1, qh[mf][ks][0], qh[mf][ks][1], qh[mf][ks][2], qh[mf][ks][3], kl_[1], kl_[3]);
                    mma_bf16(d1, qlf[mf][0], qlf[mf][1], qlf[mf][2], qlf[mf][3], kh_[1], kh_[3]);
                }
            }
        }

        // --- scale + gated bias + online softmax (log2 domain) per m-frag ---
        int colbase = kt * 64 + 2 * (lane & 3);
#pragma unroll
        for (int mf = 0; mf < 2; mf++) {
            float rm0 = -1e30f, rm1 = -1e30f;
#pragma unroll
            for (int nf = 0; nf < 8; nf++) {
                float2 bb0 = *(const float2*)(biasP[2 * mf]     + colbase + nf * 8);
                float2 bb1 = *(const float2*)(biasP[2 * mf + 1] + colbase + nf * 8);
                sf[mf][nf][0] = fmaf(sf[mf][nf][0], SC, g32 * bb0.x);
                sf[mf][nf][1] = fmaf(sf[mf][nf][1], SC, g32 * bb0.y);
                sf[mf][nf][2] = fmaf(sf[mf][nf][2], SC, g32 * bb1.x);
                sf[mf][nf][3] = fmaf(sf[mf][nf][3], SC, g32 * bb1.y);
                rm0 = fmaxf(rm0, fmaxf(sf[mf][nf][0], sf[mf][nf][1]));
                rm1 = fmaxf(rm1, fmaxf(sf[mf][nf][2], sf[mf][nf][3]));
            }
            rm0 = fmaxf(rm0, __shfl_xor_sync(0xffffffffu, rm0, 1));
            rm0 = fmaxf(rm0, __shfl_xor_sync(0xffffffffu, rm0, 2));
            rm1 = fmaxf(rm1, __shfl_xor_sync(0xffffffffu, rm1, 1));
            rm1 = fmaxf(rm1, __shfl_xor_sync(0xffffffffu, rm1, 2));

            float mn0 = fmaxf(mr[2 * mf], rm0), mn1 = fmaxf(mr[2 * mf + 1], rm1);
            float al0 = ex2f(mr[2 * mf] - mn0), al1 = ex2f(mr[2 * mf + 1] - mn1);
            mr[2 * mf] = mn0; mr[2 * mf + 1] = mn1;
            float rs0 = 0.f, rs1 = 0.f;
#pragma unroll
            for (int nf = 0; nf < 8; nf++) {
                sf[mf][nf][0] = ex2f(sf[mf][nf][0] - mn0);
                sf[mf][nf][1] = ex2f(sf[mf][nf][1] - mn0);
                sf[mf][nf][2] = ex2f(sf[mf][nf][2] - mn1);
                sf[mf][nf][3] = ex2f(sf[mf][nf][3] - mn1);
                rs0 += sf[mf][nf][0] + sf[mf][nf][1];
                rs1 += sf[mf][nf][2] + sf[mf][nf][3];
            }
            rs0 += __shfl_xor_sync(0xffffffffu, rs0, 1);
            rs0 += __shfl_xor_sync(0xffffffffu, rs0, 2);
            rs1 += __shfl_xor_sync(0xffffffffu, rs1, 1);
            rs1 += __shfl_xor_sync(0xffffffffu, rs1, 2);
            lr[2 * mf]     = lr[2 * mf] * al0 + rs0;
            lr[2 * mf + 1] = lr[2 * mf + 1] * al1 + rs1;
#pragma unroll
            for (int nf = 0; nf < 8; nf++) {
                o[mf][nf][0] *= al0; o[mf][nf][1] *= al0;
                o[mf][nf][2] *= al1; o[mf][nf][3] *= al1;
            }
        }

        // --- O += P V (P packed in regs; V frags shared across both m-frags) ---
        const uint32_t vHs = buf + 16384, vLs = buf + 24576;
#pragma unroll
        for (int kk = 0; kk < 4; kk++) {
            uint32_t ph_[2][4], pl_[2][4];
#pragma unroll
            for (int mf = 0; mf < 2; mf++) {
                const int na = 2 * kk, nb = 2 * kk + 1;
                uint32_t u0 = __float_as_uint(sf[mf][na][0]), u1 = __float_as_uint(sf[mf][na][1]);
                uint32_t u2 = __float_as_uint(sf[mf][na][2]), u3 = __float_as_uint(sf[mf][na][3]);
                uint32_t w0 = __float_as_uint(sf[mf][nb][0]), w1 = __float_as_uint(sf[mf][nb][1]);
                uint32_t w2 = __float_as_uint(sf[mf][nb][2]), w3 = __float_as_uint(sf[mf][nb][3]);
                ph_[mf][0] = pack2_hi(u0, u1);
                ph_[mf][1] = pack2_hi(u2, u3);
                ph_[mf][2] = pack2_hi(w0, w1);
                ph_[mf][3] = pack2_hi(w2, w3);
                pl_[mf][0] = pack2_bf16(sf[mf][na][0] - __uint_as_float(u0 & 0xFFFF0000u),
                                        sf[mf][na][1] - __uint_as_float(u1 & 0xFFFF0000u));
                pl_[mf][1] = pack2_bf16(sf[mf][na][2] - __uint_as_float(u2 & 0xFFFF0000u),
                                        sf[mf][na][3] - __uint_as_float(u3 & 0xFFFF0000u));
                pl_[mf][2] = pack2_bf16(sf[mf][nb][0] - __uint_as_float(w0 & 0xFFFF0000u),
                                        sf[mf][nb][1] - __uint_as_float(w1 & 0xFFFF0000u));
                pl_[mf][3] = pack2_bf16(sf[mf][nb][2] - __uint_as_float(w2 & 0xFFFF0000u),
                                        sf[mf][nb][3] - __uint_as_float(w3 & 0xFFFF0000u));
            }
#pragma unroll
            for (int nf2 = 0; nf2 < 4; nf2++) {
                int row = nf2 * 16 + lrow;
                uint32_t sw = (uint32_t)(row * 128 + kk * 32 + cb) ^ ((row & 7) << 4);
                uint32_t vh_[4], vl_[4];
                LDMX4(vh_, vHs + sw);
                LDMX4(vl_, vLs + sw);
#pragma unroll
                for (int mf = 0; mf < 2; mf++) {
                    float* d0 = o[mf][2 * nf2];
                    float* d1 = o[mf][2 * nf2 + 1];
                    mma_bf16(d0, ph_[mf][0], ph_[mf][1], ph_[mf][2], ph_[mf][3], vh_[0], vh_[2]);
                    mma_bf16(d0, ph_[mf][0], ph_[mf][1], ph_[mf][2], ph_[mf][3], vl_[0], vl_[2]);
                    mma_bf16(d0, pl_[mf][0], pl_[mf][1], pl_[mf][2], pl_[mf][3], vh_[0], vh_[2]);
                    mma_bf16(d1, ph_[mf][0], ph_[mf][1], ph_[mf][2], ph_[mf][3], vh_[1], vh_[3]);
                    mma_bf16(d1, ph_[mf][0], ph_[mf][1], ph_[mf][2], ph_[mf][3], vl_[1], vl_[3]);
                    mma_bf16(d1, pl_[mf][0], pl_[mf][1], pl_[mf][2], pl_[mf][3], vh_[1], vh_[3]);
                }
            }
        }
    }

    // epilogue: normalize + write bf16 hi/lo swizzled A-tile for the out-projection
    size_t tb = (((size_t)(b * 16 + qt)) * 16 + h) * 16384;
#pragma unroll
    for (int mf = 0; mf < 2; mf++) {
        float i0 = 1.f / lr[2 * mf], i1 = 1.f / lr[2 * mf + 1];
        int lr0 = wrow + mf * 16 + r0l, lr1 = lr0 + 8;
        uint32_t x0 = (lr0 & 7) << 4, x1 = (lr1 & 7) << 4;
#pragma unroll
        for (int nf = 0; nf < 8; nf++) {
            int dd = nf * 8 + 2 * (lane & 3);
            float v0 = o[mf][nf][0] * i0, v1 = o[mf][nf][1] * i0;
            float v2 = o[mf][nf][2] * i1, v3 = o[mf][nf][3] * i1;
            uint32_t u0 = __float_as_uint(v0), u1 = __float_as_uint(v1);
            uint32_t u2 = __float_as_uint(v2), u3 = __float_as_uint(v3);
            uint32_t o0 = (lr0 * 128 + dd * 2) ^ x0;
            uint32_t o1 = (lr1 * 128 + dd * 2) ^ x1;
            *(uint32_t*)((char*)gAh2 + tb + o0) = pack2_hi(u0, u1);
            *(uint32_t*)((char*)gAh2 + tb + o1) = pack2_hi(u2, u3);
            *(uint32_t*)((char*)gAl2 + tb + o0) =
                pack2_bf16(v0 - __uint_as_float(u0 & 0xFFFF0000u),
                           v1 - __uint_as_float(u1 & 0xFFFF0000u));
            *(uint32_t*)((char*)gAl2 + tb + o1) =
                pack2_bf16(v2 - __uint_as_float(u2 & 0xFFFF0000u),
                           v3 - __uint_as_float(u3 & 0xFFFF0000u));
        }
    }
}

// ---------------- launch ----------------
extern "C" void kernel_launch(void* const* d_in, const int* in_sizes, int n_in,
                              void* d_out, int out_size)
{
    (void)in_sizes; (void)n_in; (void)out_size;
    const float* x    = (const float*)d_in[0];
    const float* cm   = (const float*)d_in[1];
    const float* im   = (const float*)d_in[2];
    const float* wqkv = (const float*)d_in[3];
    const float* wout = (const float*)d_in[4];
    const float* qnw  = (const float*)d_in[5];
    const float* knw  = (const float*)d_in[6];
    const float* gate = (const float*)d_in[7];
    float* out = (float*)d_out;

    void *xh, *xl, *wqh, *wql, *woh, *wol, *ah2, *al2;
    cudaGetSymbolAddress(&xh, gXh);   cudaGetSymbolAddress(&xl, gXl);
    cudaGetSymbolAddress(&wqh, gWqh); cudaGetSymbolAddress(&wql, gWql);
    cudaGetSymbolAddress(&woh, gWoh); cudaGetSymbolAddress(&wol, gWol);
    cudaGetSymbolAddress(&ah2, gAh2); cudaGetSymbolAddress(&al2, gAl2);

    cudaFuncSetAttribute(attn2_kernel, cudaFuncAttributeMaxDynamicSharedMemorySize, ATTN2_SMEM);
    cudaFuncSetAttribute(gemm_hmma<0>, cudaFuncAttributeMaxDynamicSharedMemorySize, GEMM_SMEM);
    cudaFuncSetAttribute(gemm_hmma<1>, cudaFuncAttributeMaxDynamicSharedMemorySize, GEMM_SMEM);

    const int M = BB * NSEQ;   // 4096

    // 1) split-convert inputs
    conv_split_kernel<<<(4096 * 1024 / 8) / 256, 256>>>(x,    (__nv_bfloat16*)xh,  (__nv_bfloat16*)xl,  1024);
    conv_split_kernel<<<(3072 * 1024 / 8) / 256, 256>>>(wqkv, (__nv_bfloat16*)wqh, (__nv_bfloat16*)wql, 1024);
    conv_split_kernel<<<(1024 * 1024 / 8) / 256, 256>>>(wout, (__nv_bfloat16*)woh, (__nv_bfloat16*)wol, 1024);

    // 2) QKV projection (HMMA, 4-warp CTAs, 2 CTAs/SM) with fused RMSNorm + split epilogue
    gemm_hmma<1><<<dim3(3 * DMOD / 64, M / 128), 128, GEMM_SMEM>>>(
        (const char*)xh, (const char*)xl, (const char*)wqh, (const char*)wql,
        nullptr, 1024 / 64, 3 * DMOD, qnw, knw);

    // 3) V -> transposed bf16 hi/lo tiles
    vsplit_kernel<<<dim3(NSEQ / 64, BH), 256>>>();

    // 4) bias precompute
    bias_kernel<<<BB * NSEQ, 256>>>(cm, im);

    // 5) HMMA flash attention (4-warp CTAs, 2 CTAs/SM; writes split A-tiles)
    attn2_kernel<<<dim3(NSEQ / 128, BH), 128, ATTN2_SMEM>>>(gate);

    // 6) out-projection straight into d_out
    gemm_hmma<0><<<dim3(DMOD / 64, M / 128), 128, GEMM_SMEM>>>(
        (const char*)ah2, (const char*)al2, (const char*)woh, (const char*)wol,
        out, 1024 / 64, DMOD, nullptr, nullptr);
}

// round 11
// speedup vs baseline: 2.2912x; 1.3643x over previous
#include <cuda_runtime.h>
#include <cuda_bf16.h>
#include <cuda_fp16.h>
#include <math.h>
#include <stdint.h>

#define BB   2
#define NSEQ 2048
#define DMOD 1024
#define NH   16
#define HDIM 64
#define NC   4
#define BH   (BB * NH)

// ---------------- scratch (device globals; no allocation allowed) ----------------
__device__ float g_v[(size_t)BB * NH * NSEQ * HDIM];
__device__ float g_bias[(size_t)BB * NSEQ * NSEQ];

// bf16 split operands for the GEMMs, pre-swizzled 128x64 SW128 tiles (16KB each)
__device__ __nv_bfloat16 gXh[(size_t)4096 * 1024];
__device__ __nv_bfloat16 gXl[(size_t)4096 * 1024];
__device__ __nv_bfloat16 gWqh[(size_t)3072 * 1024];
__device__ __nv_bfloat16 gWql[(size_t)3072 * 1024];
__device__ __nv_bfloat16 gWoh[(size_t)1024 * 1024];
__device__ __nv_bfloat16 gWol[(size_t)1024 * 1024];
__device__ __nv_bfloat16 gAh2[(size_t)4096 * 1024];
__device__ __nv_bfloat16 gAl2[(size_t)4096 * 1024];

// attention operands: single fp16, pre-swizzled tiles
__device__ __half gQf[(size_t)BH * NSEQ * HDIM];
__device__ __half gKf[(size_t)BH * NSEQ * HDIM];
__device__ __half gVtf[(size_t)BH * NSEQ * HDIM];

// ---------------- PTX helpers (base sm_103-legal only) ----------------
__device__ __forceinline__ uint32_t smem_u32(const void* p) {
    uint32_t a;
    asm("{ .reg .u64 t; cvta.to.shared.u64 t, %1; cvt.u32.u64 %0, t; }" : "=r"(a) : "l"(p));
    return a;
}

#define CP_ASYNC16(dst, src) \
    asm volatile("cp.async.cg.shared.global [%0], [%1], 16;" :: "r"(dst), "l"(src) : "memory")
#define CP_COMMIT() asm volatile("cp.async.commit_group;" ::: "memory")
#define CP_WAIT0()  asm volatile("cp.async.wait_group 0;" ::: "memory")
#define CP_WAIT1()  asm volatile("cp.async.wait_group 1;" ::: "memory")

#define LDMX4(r, a) \
    asm volatile("ldmatrix.sync.aligned.m8n8.x4.shared.b16 {%0,%1,%2,%3}, [%4];" \
        : "=r"((r)[0]), "=r"((r)[1]), "=r"((r)[2]), "=r"((r)[3]) : "r"(a))

__device__ __forceinline__ void mma_bf16(float* d, uint32_t a0, uint32_t a1,
                                         uint32_t a2, uint32_t a3,
                                         uint32_t b0, uint32_t b1) {
    asm volatile(
        "mma.sync.aligned.m16n8k16.row.col.f32.bf16.bf16.f32 "
        "{%0,%1,%2,%3},{%4,%5,%6,%7},{%8,%9},{%0,%1,%2,%3};"
        : "+f"(d[0]), "+f"(d[1]), "+f"(d[2]), "+f"(d[3])
        : "r"(a0), "r"(a1), "r"(a2), "r"(a3), "r"(b0), "r"(b1));
}

__device__ __forceinline__ void mma_f16(float* d, uint32_t a0, uint32_t a1,
                                        uint32_t a2, uint32_t a3,
                                        uint32_t b0, uint32_t b1) {
    asm volatile(
        "mma.sync.aligned.m16n8k16.row.col.f32.f16.f16.f32 "
        "{%0,%1,%2,%3},{%4,%5,%6,%7},{%8,%9},{%0,%1,%2,%3};"
        : "+f"(d[0]), "+f"(d[1]), "+f"(d[2]), "+f"(d[3])
        : "r"(a0), "r"(a1), "r"(a2), "r"(a3), "r"(b0), "r"(b1));
}

__device__ __forceinline__ uint32_t pack2_bf16(float lo, float hi) {
    uint32_t r;
    asm("cvt.rn.bf16x2.f32 %0, %1, %2;" : "=r"(r) : "f"(hi), "f"(lo));
    return r;
}
// fp16x2 pack: first arg -> lower half
__device__ __forceinline__ uint32_t pack2_f16(float lo, float hi) {
    uint32_t r;
    asm("cvt.rn.f16x2.f32 %0, %1, %2;" : "=r"(r) : "f"(hi), "f"(lo));
    return r;
}
__device__ __forceinline__ uint32_t pack2_hi(uint32_t u0, uint32_t u1) {
    uint32_t r;
    asm("prmt.b32 %0, %1, %2, 0x7632;" : "=r"(r) : "r"(u0), "r"(u1));
    return r;
}
__device__ __forceinline__ float ex2f(float x) {
    float r;
    asm("ex2.approx.f32 %0, %1;" : "=f"(r) : "f"(x));
    return r;
}

// ---------------- split-conversion: fp32 row-major -> blocked swizzled bf16 hi/lo ----------------
__global__ void __launch_bounds__(256)
conv_split_kernel(const float* __restrict__ src, __nv_bfloat16* __restrict__ dh,
                  __nv_bfloat16* __restrict__ dl, int K)
{
    size_t idx = ((size_t)blockIdx.x * 256 + threadIdx.x) * 8;
    int r  = (int)(idx / K);
    int c0 = (int)(idx % K);
    float4 v0 = *(const float4*)(src + idx);
    float4 v1 = *(const float4*)(src + idx + 4);
    float f[8] = {v0.x, v0.y, v0.z, v0.w, v1.x, v1.y, v1.z, v1.w};
    __nv_bfloat16 h[8], l[8];
#pragma unroll
    for (int i = 0; i < 8; i++) {
        h[i] = __float2bfloat16(f[i]);
        l[i] = __float2bfloat16(f[i] - __bfloat162float(h[i]));
    }
    int rt = r >> 7, lr = r & 127, ch = c0 >> 6, lc = c0 & 63;
    size_t tile = (size_t)rt * (K >> 6) + ch;
    uint32_t off = lr * 128 + lc * 2;
    uint32_t sw = off ^ ((off >> 3) & 0x70);
    size_t db = tile * 16384 + sw;
    *(uint4*)((char*)dh + db) = *(uint4*)h;
    *(uint4*)((char*)dl + db) = *(uint4*)l;
}

// ---------------- HMMA GEMM: 128 threads, 4 warps, warp tile 32x64, CTA tile 128x64 ----------------
#define GEMM_SMEM (2 * 48 * 1024)

template <int MODE>
__global__ void __launch_bounds__(128, 2)
gemm_hmma(const char* __restrict__ Ah, const char* __restrict__ Al,
          const char* __restrict__ Bh, const char* __restrict__ Bl,
          float* __restrict__ Cout, int KC, int Nt,
          const float* __restrict__ qw, const float* __restrict__ kw)
{
    extern __shared__ char smraw[];
    const uint32_t smemS = smem_u32(smraw);
    const int tid  = threadIdx.x;
    const int lane = tid & 31;
    const int warp = tid >> 5;
    const int jcol = blockIdx.x;

    const size_t tA0 = (size_t)blockIdx.y * KC * 16384;
    const size_t tB0 = ((size_t)(jcol >> 1) * KC) * 16384 + (size_t)(jcol & 1) * 8192;

    float acc[2][8][4];
#pragma unroll
    for (int m = 0; m < 2; m++)
#pragma unroll
        for (int j = 0; j < 8; j++)
#pragma unroll
            for (int t = 0; t < 4; t++) acc[m][j][t] = 0.f;

    const int lrow = lane & 15;
    const int cb   = (lane >> 4) << 4;

    {
        const char* sA0 = Ah + tA0 + tid * 16;
        const char* sA1 = Al + tA0 + tid * 16;
        const char* sB0 = Bh + tB0 + tid * 16;
        const char* sB1 = Bl + tB0 + tid * 16;
        uint32_t d0 = smemS + tid * 16;
#pragma unroll
        for (int i = 0; i < 8; i++) {
            CP_ASYNC16(d0 + i * 2048,         sA0 + i * 2048);
            CP_ASYNC16(d0 + 16384 + i * 2048, sA1 + i * 2048);
        }
#pragma unroll
        for (int i = 0; i < 4; i++) {
            CP_ASYNC16(d0 + 32768 + i * 2048, sB0 + i * 2048);
            CP_ASYNC16(d0 + 40960 + i * 2048, sB1 + i * 2048);
        }
        CP_COMMIT();
    }

    for (int kc = 0; kc < KC; kc++) {
        __syncthreads();
        if (kc + 1 < KC) {
            size_t goA = tA0 + (size_t)(kc + 1) * 16384;
            size_t goB = tB0 + (size_t)(kc + 1) * 16384;
            const char* sA0 = Ah + goA + tid * 16;
            const char* sA1 = Al + goA + tid * 16;
            const char* sB0 = Bh + goB + tid * 16;
            const char* sB1 = Bl + goB + tid * 16;
            uint32_t d0 = smemS + ((kc + 1) & 1) * 49152 + tid * 16;
#pragma unroll
            for (int i = 0; i < 8; i++) {
                CP_ASYNC16(d0 + i * 2048,         sA0 + i * 2048);
                CP_ASYNC16(d0 + 16384 + i * 2048, sA1 + i * 2048);
            }
#pragma unroll
            for (int i = 0; i < 4; i++) {
                CP_ASYNC16(d0 + 32768 + i * 2048, sB0 + i * 2048);
                CP_ASYNC16(d0 + 40960 + i * 2048, sB1 + i * 2048);
            }
            CP_COMMIT();
            CP_WAIT1();
        } else {
            CP_WAIT0();
        }
        __syncthreads();

        uint32_t buf = smemS + (kc & 1) * 49152;
        const uint32_t aHs = buf, aLs = buf + 16384, bHs = buf + 32768, bLs = buf + 40960;

#pragma unroll
        for (int ks = 0; ks < 4; ks++) {
            uint32_t ah[2][4], al[2][4];
#pragma unroll
            for (int mf = 0; mf < 2; mf++) {
                int row = warp * 32 + mf * 16 + lrow;
                uint32_t sw = (uint32_t)(row * 128 + ks * 32 + cb) ^ ((row & 7) << 4);
                LDMX4(ah[mf], aHs + sw);
                LDMX4(al[mf], aLs + sw);
            }
#pragma unroll
            for (int nf2 = 0; nf2 < 4; nf2++) {
                int row = nf2 * 16 + lrow;
                uint32_t sw = (uint32_t)(row * 128 + ks * 32 + cb) ^ ((row & 7) << 4);
                uint32_t bh[4], bl[4];
                LDMX4(bh, bHs + sw);
                LDMX4(bl, bLs + sw);
#pragma unroll
                for (int mf = 0; mf < 2; mf++) {
                    float* d0 = acc[mf][2 * nf2];
                    float* d1 = acc[mf][2 * nf2 + 1];
                    mma_bf16(d0, ah[mf][0], ah[mf][1], ah[mf][2], ah[mf][3], bh[0], bh[2]);
                    mma_bf16(d0, ah[mf][0], ah[mf][1], ah[mf][2], ah[mf][3], bl[0], bl[2]);
                    mma_bf16(d0, al[mf][0], al[mf][1], al[mf][2], al[mf][3], bh[0], bh[2]);
                    mma_bf16(d1, ah[mf][0], ah[mf][1], ah[mf][2], ah[mf][3], bh[1], bh[3]);
                    mma_bf16(d1, ah[mf][0], ah[mf][1], ah[mf][2], ah[mf][3], bl[1], bl[3]);
                    mma_bf16(d1, al[mf][0], al[mf][1], al[mf][2], al[mf][3], bh[1], bh[3]);
                }
            }
        }
    }

    const int r0l = lane >> 2;
    const int c2  = (lane & 3) * 2;

    if (MODE == 0) {
        const int n0 = jcol * 64;
#pragma unroll
        for (int mf = 0; mf < 2; mf++) {
            const int m0 = blockIdx.y * 128 + warp * 32 + mf * 16 + r0l;
#pragma unroll
            for (int nf = 0; nf < 8; nf++) {
                int n = n0 + nf * 8 + c2;
                *(float2*)(Cout + (size_t)m0 * Nt + n)       = make_float2(acc[mf][nf][0], acc[mf][nf][1]);
                *(float2*)(Cout + (size_t)(m0 + 8) * Nt + n) = make_float2(acc[mf][nf][2], acc[mf][nf][3]);
            }
        }
    } else {
        const int which = jcol >> 4;     // 0:q 1:k 2:v
        const int h = jcol & 15;
#pragma unroll
        for (int mf = 0; mf < 2; mf++) {
            const int m0 = blockIdx.y * 128 + warp * 32 + mf * 16 + r0l;
            const int m1 = m0 + 8;
            const int b0i = m0 >> 11, n0i = m0 & 2047;
            const int b1i = m1 >> 11, n1i = m1 & 2047;

            if (which == 2) {
                float* vb = g_v;
#pragma unroll
                for (int nf = 0; nf < 8; nf++) {
                    int dd = nf * 8 + c2;
                    *(float2*)&vb[(((size_t)(b0i * NH + h)) * NSEQ + n0i) * HDIM + dd] =
                        make_float2(acc[mf][nf][0], acc[mf][nf][1]);
                    *(float2*)&vb[(((size_t)(b1i * NH + h)) * NSEQ + n1i) * HDIM + dd] =
                        make_float2(acc[mf][nf][2], acc[mf][nf][3]);
                }
            } else {
                const float* w = (which == 0) ? qw : kw;
                char* df = (which == 0) ? (char*)gQf : (char*)gKf;
                float ss0 = 0.f, ss1 = 0.f;
#pragma unroll
                for (int nf = 0; nf < 8; nf++) {
                    ss0 += acc[mf][nf][0] * acc[mf][nf][0] + acc[mf][nf][1] * acc[mf][nf][1];
                    ss1 += acc[mf][nf][2] * acc[mf][nf][2] + acc[mf][nf][3] * acc[mf][nf][3];
                }
                ss0 += __shfl_xor_sync(0xffffffffu, ss0, 1);
                ss0 += __shfl_xor_sync(0xffffffffu, ss0, 2);
                ss1 += __shfl_xor_sync(0xffffffffu, ss1, 1);
                ss1 += __shfl_xor_sync(0xffffffffu, ss1, 2);
                float r0 = rsqrtf(ss0 * (1.0f / HDIM) + 1e-6f);
                float r1 = rsqrtf(ss1 * (1.0f / HDIM) + 1e-6f);

                size_t tb0 = (((size_t)(b0i * NH + h)) * 16 + (n0i >> 7)) * 16384;
                size_t tb1 = (((size_t)(b1i * NH + h)) * 16 + (n1i >> 7)) * 16384;
                int lr0 = n0i & 127, lr1 = n1i & 127;
                uint32_t x0 = (lr0 & 7) << 4, x1 = (lr1 & 7) << 4;
#pragma unroll
                for (int nf = 0; nf < 8; nf++) {
                    int dd = nf * 8 + c2;
                    float2 wv = *(const float2*)(w + dd);
                    float v0 = acc[mf][nf][0] * r0 * wv.x;
                    float v1 = acc[mf][nf][1] * r0 * wv.y;
                    float v2 = acc[mf][nf][2] * r1 * wv.x;
                    float v3 = acc[mf][nf][3] * r1 * wv.y;
                    uint32_t o0 = (lr0 * 128 + dd * 2) ^ x0;
                    uint32_t o1 = (lr1 * 128 + dd * 2) ^ x1;
                    *(uint32_t*)(df + tb0 + o0) = pack2_f16(v0, v1);
                    *(uint32_t*)(df + tb1 + o1) = pack2_f16(v2, v3);
                }
            }
        }
    }
}

// ---------------- V transpose + fp16 convert: g_v[bh][seq][64] -> V^T 64x64 swizzled tiles ----------------
__global__ void __launch_bounds__(256)
vsplit_kernel()
{
    __shared__ float stg[64][65];
    const int kt = blockIdx.x, bh = blockIdx.y;
    const int tid = threadIdx.x;
    {
        int s = tid >> 2, d0 = (tid & 3) * 16;
        const float* vp = g_v + ((size_t)bh * NSEQ + kt * 64 + s) * HDIM + d0;
#pragma unroll
        for (int i = 0; i < 4; i++) {
            float4 v = *(const float4*)(vp + i * 4);
            stg[s][d0 + i * 4 + 0] = v.x;
            stg[s][d0 + i * 4 + 1] = v.y;
            stg[s][d0 + i * 4 + 2] = v.z;
            stg[s][d0 + i * 4 + 3] = v.w;
        }
    }
    __syncthreads();
    {
        int dR = tid >> 2, c0 = (tid & 3) * 16;
        uint32_t hw[8];
#pragma unroll
        for (int j = 0; j < 8; j++) {
            float f0 = stg[c0 + 2 * j][dR];
            float f1 = stg[c0 + 2 * j + 1][dR];
            hw[j] = pack2_f16(f0, f1);
        }
        size_t tb = ((size_t)bh * 32 + kt) * 8192;
        uint32_t off0 = dR * 128 + c0 * 2;
        uint32_t x = (dR & 7) << 4;
        *(uint4*)((char*)gVtf + tb + (off0 ^ x))        = make_uint4(hw[0], hw[1], hw[2], hw[3]);
        *(uint4*)((char*)gVtf + tb + ((off0 + 16) ^ x)) = make_uint4(hw[4], hw[5], hw[6], hw[7]);
    }
}

// ---------------- bias precompute ----------------
__global__ void __launch_bounds__(256)
bias_kernel(const float* __restrict__ cm, const float* __restrict__ im)
{
    int bq = blockIdx.x;
    int b = bq / NSEQ, q = bq % NSEQ;
    const float* cmb = cm + (size_t)b * NC * NSEQ;
    float c0 = cmb[q], c1 = cmb[NSEQ + q], c2 = cmb[2 * NSEQ + q], c3 = cmb[3 * NSEQ + q];

    float mx = 0.f;
    for (int k = threadIdx.x; k < NSEQ; k += 256) {
        float s = c0 * cmb[k] + c1 * cmb[NSEQ + k] + c2 * cmb[2 * NSEQ + k] + c3 * cmb[3 * NSEQ + k];
        mx = fmaxf(mx, s);
    }
    __shared__ float red[8];
#pragma unroll
    for (int o = 16; o > 0; o >>= 1) mx = fmaxf(mx, __shfl_xor_sync(0xffffffffu, mx, o));
    if ((threadIdx.x & 31) == 0) red[threadIdx.x >> 5] = mx;
    __syncthreads();
    if (threadIdx.x == 0) {
        float m = red[0];
#pragma unroll
        for (int wN = 1; wN < 8; wN++) m = fmaxf(m, red[wN]);
        red[0] = fmaxf(m, 1e-6f);
    }
    __syncthreads();
    float inv = 1.f / red[0];
    const float* imr = im + (size_t)bq * NSEQ;
    float* br = g_bias + (size_t)bq * NSEQ;
    for (int k = threadIdx.x; k < NSEQ; k += 256) {
        float s = c0 * cmb[k] + c1 * cmb[NSEQ + k] + c2 * cmb[2 * NSEQ + k] + c3 * cmb[3 * NSEQ + k];
        br[k] = 2.f * s * inv - 1.f + 0.3f * imr[k];
    }
}

// ---------------- HMMA flash attention (fp16 single-term) ----------------
// 128 threads, 4 warps, warp tile 32q x 64k.
// smem: Qf 16KB | KVbuf0 16KB | KVbuf1 16KB = 48KB.  KV buffer: Kf 8K | Vtf 8K.
#define ATTN2_SMEM (16384 + 2 * 16384)

__global__ void __launch_bounds__(128, 2)
attn2_kernel(const float* __restrict__ gate)
{
    extern __shared__ char smraw[];
    const uint32_t S = smem_u32(smraw);
    const uint32_t BUF0 = S + 16384;
    const int tid = threadIdx.x, lane = tid & 31, warp = tid >> 5;
    const int bh = blockIdx.y, b = bh >> 4, h = bh & 15;
    const int qt = blockIdx.x, q0 = qt * 128;
    const float LOG2E = 1.44269504f;
    const float g32 = 3.f * fminf(fmaxf(gate[h], 0.f), 1.f) * LOG2E;
    const float SC = 0.125f * LOG2E;
    const int lrow = lane & 15, cb = (lane >> 4) << 4;
    const int wrow = warp * 32;

    // prologue: Qf -> S, KV0 -> BUF0
    {
        size_t qoff = ((size_t)(bh * 16 + qt)) * 16384 + tid * 16;
        uint32_t dq = S + tid * 16;
#pragma unroll
        for (int i = 0; i < 8; i++)
            CP_ASYNC16(dq + i * 2048, (const char*)gQf + qoff + i * 2048);
        size_t koff = ((size_t)(bh * 16)) * 16384 + tid * 16;
        size_t voff = ((size_t)(bh * 32)) * 8192 + tid * 16;
        uint32_t dk = BUF0 + tid * 16;
#pragma unroll
        for (int i = 0; i < 4; i++) {
            CP_ASYNC16(dk + i * 2048,        (const char*)gKf  + koff + i * 2048);
            CP_ASYNC16(dk + 8192 + i * 2048, (const char*)gVtf + voff + i * 2048);
        }
        CP_COMMIT();
    }

    CP_WAIT0();
    __syncthreads();

    // Q fragments to registers (both m-frags, all 4 k-steps)
    uint32_t qf[2][4][4];
#pragma unroll
    for (int mf = 0; mf < 2; mf++) {
        int qrow = wrow + mf * 16 + lrow;
        uint32_t qswz = (uint32_t)((qrow & 7) << 4);
#pragma unroll
        for (int ks = 0; ks < 4; ks++) {
            uint32_t sw = (uint32_t)(qrow * 128 + ks * 32 + cb) ^ qswz;
            LDMX4(qf[mf][ks], S + sw);
        }
    }

    float o[2][8][4];
#pragma unroll
    for (int mf = 0; mf < 2; mf++)
#pragma unroll
        for (int nf = 0; nf < 8; nf++)
#pragma unroll
            for (int t = 0; t < 4; t++) o[mf][nf][t] = 0.f;
    float mr[4] = {-1e30f, -1e30f, -1e30f, -1e30f};
    float lr[4] = {0.f, 0.f, 0.f, 0.f};

    const int r0l = lane >> 2;
    const float* biasP[4];
#pragma unroll
    for (int rr = 0; rr < 4; rr++)
        biasP[rr] = g_bias + ((size_t)(b * NSEQ + q0 + wrow + (rr >> 1) * 16 + (rr & 1) * 8 + r0l)) * NSEQ;

    for (int kt = 0; kt < 32; kt++) {
        __syncthreads();
        if (kt + 1 < 32) {
            int k2 = kt + 1;
            size_t koff = ((size_t)(bh * 16 + (k2 >> 1))) * 16384 + (size_t)(k2 & 1) * 8192 + tid * 16;
            size_t voff = ((size_t)(bh * 32 + k2)) * 8192 + tid * 16;
            uint32_t d = BUF0 + (k2 & 1) * 16384 + tid * 16;
#pragma unroll
            for (int i = 0; i < 4; i++) {
                CP_ASYNC16(d + i * 2048,        (const char*)gKf  + koff + i * 2048);
                CP_ASYNC16(d + 8192 + i * 2048, (const char*)gVtf + voff + i * 2048);
            }
            CP_COMMIT();
            CP_WAIT1();
        } else {
            CP_WAIT0();
        }
        __syncthreads();

        uint32_t buf = BUF0 + (kt & 1) * 16384;

        // --- S = Q K^T (single fp16 MMA; K frags shared across both m-frags) ---
        float sf[2][8][4];
#pragma unroll
        for (int mf = 0; mf < 2; mf++)
#pragma unroll
            for (int nf = 0; nf < 8; nf++)
#pragma unroll
                for (int t = 0; t < 4; t++) sf[mf][nf][t] = 0.f;

#pragma unroll
        for (int ks = 0; ks < 4; ks++) {
#pragma unroll
            for (int nf2 = 0; nf2 < 4; nf2++) {
                int row = nf2 * 16 + lrow;
                uint32_t sw = (uint32_t)(row * 128 + ks * 32 + cb) ^ ((row & 7) << 4);
                uint32_t kf[4];
                LDMX4(kf, buf + sw);
#pragma unroll
                for (int mf = 0; mf < 2; mf++) {
                    mma_f16(sf[mf][2 * nf2],     qf[mf][ks][0], qf[mf][ks][1], qf[mf][ks][2], qf[mf][ks][3], kf[0], kf[2]);
                    mma_f16(sf[mf][2 * nf2 + 1], qf[mf][ks][0], qf[mf][ks][1], qf[mf][ks][2], qf[mf][ks][3], kf[1], kf[3]);
                }
            }
        }

        // --- scale + gated bias + online softmax (log2 domain) per m-frag ---
        int colbase = kt * 64 + 2 * (lane & 3);
#pragma unroll
        for (int mf = 0; mf < 2; mf++) {
            float rm0 = -1e30f, rm1 = -1e30f;
#pragma unroll
            for (int nf = 0; nf < 8; nf++) {
                float2 bb0 = *(const float2*)(biasP[2 * mf]     + colbase + nf * 8);
                float2 bb1 = *(const float2*)(biasP[2 * mf + 1] + colbase + nf * 8);
                sf[mf][nf][0] = fmaf(sf[mf][nf][0], SC, g32 * bb0.x);
                sf[mf][nf][1] = fmaf(sf[mf][nf][1], SC, g32 * bb0.y);
                sf[mf][nf][2] = fmaf(sf[mf][nf][2], SC, g32 * bb1.x);
                sf[mf][nf][3] = fmaf(sf[mf][nf][3], SC, g32 * bb1.y);
                rm0 = fmaxf(rm0, fmaxf(sf[mf][nf][0], sf[mf][nf][1]));
                rm1 = fmaxf(rm1, fmaxf(sf[mf][nf][2], sf[mf][nf][3]));
            }
            rm0 = fmaxf(rm0, __shfl_xor_sync(0xffffffffu, rm0, 1));
            rm0 = fmaxf(rm0, __shfl_xor_sync(0xffffffffu, rm0, 2));
            rm1 = fmaxf(rm1, __shfl_xor_sync(0xffffffffu, rm1, 1));
            rm1 = fmaxf(rm1, __shfl_xor_sync(0xffffffffu, rm1, 2));

            float mn0 = fmaxf(mr[2 * mf], rm0), mn1 = fmaxf(mr[2 * mf + 1], rm1);
            float al0 = ex2f(mr[2 * mf] - mn0), al1 = ex2f(mr[2 * mf + 1] - mn1);
            mr[2 * mf] = mn0; mr[2 * mf + 1] = mn1;
            float rs0 = 0.f, rs1 = 0.f;
#pragma unroll
            for (int nf = 0; nf < 8; nf++) {
                sf[mf][nf][0] = ex2f(sf[mf][nf][0] - mn0);
                sf[mf][nf][1] = ex2f(sf[mf][nf][1] - mn0);
                sf[mf][nf][2] = ex2f(sf[mf][nf][2] - mn1);
                sf[mf][nf][3] = ex2f(sf[mf][nf][3] - mn1);
                rs0 += sf[mf][nf][0] + sf[mf][nf][1];
                rs1 += sf[mf][nf][2] + sf[mf][nf][3];
            }
            rs0 += __shfl_xor_sync(0xffffffffu, rs0, 1);
            rs0 += __shfl_xor_sync(0xffffffffu, rs0, 2);
            rs1 += __shfl_xor_sync(0xffffffffu, rs1, 1);
            rs1 += __shfl_xor_sync(0xffffffffu, rs1, 2);
            lr[2 * mf]     = lr[2 * mf] * al0 + rs0;
            lr[2 * mf + 1] = lr[2 * mf + 1] * al1 + rs1;
#pragma unroll
            for (int nf = 0; nf < 8; nf++) {
                o[mf][nf][0] *= al0; o[mf][nf][1] *= al0;
                o[mf][nf][2] *= al1; o[mf][nf][3] *= al1;
            }
        }

        // --- O += P V (P packed fp16 in regs; V frags shared across m-frags) ---
        const uint32_t vFs = buf + 8192;
#pragma unroll
        for (int kk = 0; kk < 4; kk++) {
            uint32_t pf[2][4];
#pragma unroll
            for (int mf = 0; mf < 2; mf++) {
                const int na = 2 * kk, nb = 2 * kk + 1;
                pf[mf][0] = pack2_f16(sf[mf][na][0], sf[mf][na][1]);
                pf[mf][1] = pack2_f16(sf[mf][na][2], sf[mf][na][3]);
                pf[mf][2] = pack2_f16(sf[mf][nb][0], sf[mf][nb][1]);
                pf[mf][3] = pack2_f16(sf[mf][nb][2], sf[mf][nb][3]);
            }
#pragma unroll
            for (int nf2 = 0; nf2 < 4; nf2++) {
                int row = nf2 * 16 + lrow;
                uint32_t sw = (uint32_t)(row * 128 + kk * 32 + cb) ^ ((row & 7) << 4);
                uint32_t vf[4];
                LDMX4(vf, vFs + sw);
#pragma unroll
                for (int mf = 0; mf < 2; mf++) {
                    mma_f16(o[mf][2 * nf2],     pf[mf][0], pf[mf][1], pf[mf][2], pf[mf][3], vf[0], vf[2]);
                    mma_f16(o[mf][2 * nf2 + 1], pf[mf][0], pf[mf][1], pf[mf][2], pf[mf][3], vf[1], vf[3]);
                }
            }
        }
    }

    // epilogue: normalize + write bf16 hi/lo swizzled A-tile for the out-projection
    size_t tb = (((size_t)(b * 16 + qt)) * 16 + h) * 16384;
#pragma unroll
    for (int mf = 0; mf < 2; mf++) {
        float i0 = 1.f / lr[2 * mf], i1 = 1.f / lr[2 * mf + 1];
        int lr0 = wrow + mf * 16 + r0l, lr1 = lr0 + 8;
        uint32_t x0 = (lr0 & 7) << 4, x1 = (lr1 & 7) << 4;
#pragma unroll
        for (int nf = 0; nf < 8; nf++) {
            int dd = nf * 8 + 2 * (lane & 3);
            float v0 = o[mf][nf][0] * i0, v1 = o[mf][nf][1] * i0;
            float v2 = o[mf][nf][2] * i1, v3 = o[mf][nf][3] * i1;
            uint32_t u0 = __float_as_uint(v0), u1 = __float_as_uint(v1);
            uint32_t u2 = __float_as_uint(v2), u3 = __float_as_uint(v3);
            uint32_t o0 = (lr0 * 128 + dd * 2) ^ x0;
            uint32_t o1 = (lr1 * 128 + dd * 2) ^ x1;
            *(uint32_t*)((char*)gAh2 + tb + o0) = pack2_hi(u0, u1);
            *(uint32_t*)((char*)gAh2 + tb + o1) = pack2_hi(u2, u3);
            *(uint32_t*)((char*)gAl2 + tb + o0) =
                pack2_bf16(v0 - __uint_as_float(u0 & 0xFFFF0000u),
                           v1 - __uint_as_float(u1 & 0xFFFF0000u));
            *(uint32_t*)((char*)gAl2 + tb + o1) =
                pack2_bf16(v2 - __uint_as_float(u2 & 0xFFFF0000u),
                           v3 - __uint_as_float(u3 & 0xFFFF0000u));
        }
    }
}

// ---------------- launch ----------------
extern "C" void kernel_launch(void* const* d_in, const int* in_sizes, int n_in,
                              void* d_out, int out_size)
{
    (void)in_sizes; (void)n_in; (void)out_size;
    const float* x    = (const float*)d_in[0];
    const float* cm   = (const float*)d_in[1];
    const float* im   = (const float*)d_in[2];
    const float* wqkv = (const float*)d_in[3];
    const float* wout = (const float*)d_in[4];
    const float* qnw  = (const float*)d_in[5];
    const float* knw  = (const float*)d_in[6];
    const float* gate = (const float*)d_in[7];
    float* out = (float*)d_out;

    void *xh, *xl, *wqh, *wql, *woh, *wol, *ah2, *al2;
    cudaGetSymbolAddress(&xh, gXh);   cudaGetSymbolAddress(&xl, gXl);
    cudaGetSymbolAddress(&wqh, gWqh); cudaGetSymbolAddress(&wql, gWql);
    cudaGetSymbolAddress(&woh, gWoh); cudaGetSymbolAddress(&wol, gWol);
    cudaGetSymbolAddress(&ah2, gAh2); cudaGetSymbolAddress(&al2, gAl2);

    cudaFuncSetAttribute(attn2_kernel, cudaFuncAttributeMaxDynamicSharedMemorySize, ATTN2_SMEM);
    cudaFuncSetAttribute(gemm_hmma<0>, cudaFuncAttributeMaxDynamicSharedMemorySize, GEMM_SMEM);
    cudaFuncSetAttribute(gemm_hmma<1>, cudaFuncAttributeMaxDynamicSharedMemorySize, GEMM_SMEM);

    const int M = BB * NSEQ;   // 4096

    // 1) split-convert inputs
    conv_split_kernel<<<(4096 * 1024 / 8) / 256, 256>>>(x,    (__nv_bfloat16*)xh,  (__nv_bfloat16*)xl,  1024);
    conv_split_kernel<<<(3072 * 1024 / 8) / 256, 256>>>(wqkv, (__nv_bfloat16*)wqh, (__nv_bfloat16*)wql, 1024);
    conv_split_kernel<<<(1024 * 1024 / 8) / 256, 256>>>(wout, (__nv_bfloat16*)woh, (__nv_bfloat16*)wol, 1024);

    // 2) QKV projection (HMMA bf16 3-term) with fused RMSNorm + fp16 q/k epilogue
    gemm_hmma<1><<<dim3(3 * DMOD / 64, M / 128), 128, GEMM_SMEM>>>(
        (const char*)xh, (const char*)xl, (const char*)wqh, (const char*)wql,
        nullptr, 1024 / 64, 3 * DMOD, qnw, knw);

    // 3) V -> transposed fp16 tiles
    vsplit_kernel<<<dim3(NSEQ / 64, BH), 256>>>();

    // 4) bias precompute
    bias_kernel<<<BB * NSEQ, 256>>>(cm, im);

    // 5) fp16 HMMA flash attention (writes bf16 split A-tiles for out-proj)
    attn2_kernel<<<dim3(NSEQ / 128, BH), 128, ATTN2_SMEM>>>(gate);

    // 6) out-projection (bf16 3-term) straight into d_out
    gemm_hmma<0><<<dim3(DMOD / 64, M / 128), 128, GEMM_SMEM>>>(
        (const char*)ah2, (const char*)al2, (const char*)woh, (const char*)wol,
        out, 1024 / 64, DMOD, nullptr, nullptr);
}

// round 12
// speedup vs baseline: 3.5293x; 1.5404x over previous
#include <cuda_runtime.h>
#include <cuda_fp16.h>
#include <math.h>
#include <stdint.h>

#define BB   2
#define NSEQ 2048
#define DMOD 1024
#define NH   16
#define HDIM 64
#define NC   4
#define BH   (BB * NH)

// ---------------- scratch (device globals; no allocation allowed) ----------------
__device__ float g_v[(size_t)BB * NH * NSEQ * HDIM];
__device__ float g_bias[(size_t)BB * NSEQ * NSEQ];

// fp16 operands, pre-swizzled 128x64 SW128 tiles (16KB each)
__device__ __half gXf[(size_t)4096 * 1024];
__device__ __half gWqf[(size_t)3072 * 1024];
__device__ __half gWof[(size_t)1024 * 1024];
__device__ __half gAf[(size_t)4096 * 1024];

// attention operands: single fp16, pre-swizzled tiles
__device__ __half gQf[(size_t)BH * NSEQ * HDIM];
__device__ __half gKf[(size_t)BH * NSEQ * HDIM];
__device__ __half gVtf[(size_t)BH * NSEQ * HDIM];

// ---------------- PTX helpers (base sm_103-legal only) ----------------
__device__ __forceinline__ uint32_t smem_u32(const void* p) {
    uint32_t a;
    asm("{ .reg .u64 t; cvta.to.shared.u64 t, %1; cvt.u32.u64 %0, t; }" : "=r"(a) : "l"(p));
    return a;
}

#define CP_ASYNC16(dst, src) \
    asm volatile("cp.async.cg.shared.global [%0], [%1], 16;" :: "r"(dst), "l"(src) : "memory")
#define CP_COMMIT() asm volatile("cp.async.commit_group;" ::: "memory")
#define CP_WAIT0()  asm volatile("cp.async.wait_group 0;" ::: "memory")
#define CP_WAIT1()  asm volatile("cp.async.wait_group 1;" ::: "memory")

#define LDMX4(r, a) \
    asm volatile("ldmatrix.sync.aligned.m8n8.x4.shared.b16 {%0,%1,%2,%3}, [%4];" \
        : "=r"((r)[0]), "=r"((r)[1]), "=r"((r)[2]), "=r"((r)[3]) : "r"(a))

__device__ __forceinline__ void mma_f16(float* d, uint32_t a0, uint32_t a1,
                                        uint32_t a2, uint32_t a3,
                                        uint32_t b0, uint32_t b1) {
    asm volatile(
        "mma.sync.aligned.m16n8k16.row.col.f32.f16.f16.f32 "
        "{%0,%1,%2,%3},{%4,%5,%6,%7},{%8,%9},{%0,%1,%2,%3};"
        : "+f"(d[0]), "+f"(d[1]), "+f"(d[2]), "+f"(d[3])
        : "r"(a0), "r"(a1), "r"(a2), "r"(a3), "r"(b0), "r"(b1));
}

// fp16x2 pack: first arg -> lower half
__device__ __forceinline__ uint32_t pack2_f16(float lo, float hi) {
    uint32_t r;
    asm("cvt.rn.f16x2.f32 %0, %1, %2;" : "=r"(r) : "f"(hi), "f"(lo));
    return r;
}
__device__ __forceinline__ float ex2f(float x) {
    float r;
    asm("ex2.approx.f32 %0, %1;" : "=f"(r) : "f"(x));
    return r;
}

// ---------------- conversion: fp32 row-major -> blocked swizzled fp16 tiles ----------------
__global__ void __launch_bounds__(256)
conv_f16_kernel(const float* __restrict__ src, __half* __restrict__ dst, int K)
{
    size_t idx = ((size_t)blockIdx.x * 256 + threadIdx.x) * 8;
    int r  = (int)(idx / K);
    int c0 = (int)(idx % K);
    float4 v0 = *(const float4*)(src + idx);
    float4 v1 = *(const float4*)(src + idx + 4);
    uint4 w;
    w.x = pack2_f16(v0.x, v0.y);
    w.y = pack2_f16(v0.z, v0.w);
    w.z = pack2_f16(v1.x, v1.y);
    w.w = pack2_f16(v1.z, v1.w);
    int rt = r >> 7, lr = r & 127, ch = c0 >> 6, lc = c0 & 63;
    size_t tile = (size_t)rt * (K >> 6) + ch;
    uint32_t off = lr * 128 + lc * 2;
    uint32_t sw = off ^ ((off >> 3) & 0x70);
    *(uint4*)((char*)dst + tile * 16384 + sw) = w;
}

// ---------------- fp16 HMMA GEMM: 128 threads, 4 warps, warp tile 32x64, CTA tile 128x64 ----------------
// buffer 24KB (A 16K | B 8K), double-buffered 48KB -> 4 CTAs/SM.
// MODE 0: row-major f32 store. MODE 1: QKV epilogue (fused RMSNorm -> fp16 q/k tiles; v -> g_v f32).
#define GEMM_SMEM (2 * 24 * 1024)

template <int MODE>
__global__ void __launch_bounds__(128, 4)
gemm_f16(const char* __restrict__ Af, const char* __restrict__ Bf,
         float* __restrict__ Cout, int KC, int Nt,
         const float* __restrict__ qw, const float* __restrict__ kw)
{
    extern __shared__ char smraw[];
    const uint32_t smemS = smem_u32(smraw);
    const int tid  = threadIdx.x;
    const int lane = tid & 31;
    const int warp = tid >> 5;
    const int jcol = blockIdx.x;

    const size_t tA0 = (size_t)blockIdx.y * KC * 16384;
    const size_t tB0 = ((size_t)(jcol >> 1) * KC) * 16384 + (size_t)(jcol & 1) * 8192;

    float acc[2][8][4];
#pragma unroll
    for (int m = 0; m < 2; m++)
#pragma unroll
        for (int j = 0; j < 8; j++)
#pragma unroll
            for (int t = 0; t < 4; t++) acc[m][j][t] = 0.f;

    const int lrow = lane & 15;
    const int cb   = (lane >> 4) << 4;

    // prologue: chunk 0 into buffer 0 (A: 8 x 16B/thread, B: 4 x 16B/thread)
    {
        const char* sA = Af + tA0 + tid * 16;
        const char* sB = Bf + tB0 + tid * 16;
        uint32_t d0 = smemS + tid * 16;
#pragma unroll
        for (int i = 0; i < 8; i++) CP_ASYNC16(d0 + i * 2048, sA + i * 2048);
#pragma unroll
        for (int i = 0; i < 4; i++) CP_ASYNC16(d0 + 16384 + i * 2048, sB + i * 2048);
        CP_COMMIT();
    }

    for (int kc = 0; kc < KC; kc++) {
        __syncthreads();
        if (kc + 1 < KC) {
            const char* sA = Af + tA0 + (size_t)(kc + 1) * 16384 + tid * 16;
            const char* sB = Bf + tB0 + (size_t)(kc + 1) * 16384 + tid * 16;
            uint32_t d0 = smemS + ((kc + 1) & 1) * 24576 + tid * 16;
#pragma unroll
            for (int i = 0; i < 8; i++) CP_ASYNC16(d0 + i * 2048, sA + i * 2048);
#pragma unroll
            for (int i = 0; i < 4; i++) CP_ASYNC16(d0 + 16384 + i * 2048, sB + i * 2048);
            CP_COMMIT();
            CP_WAIT1();
        } else {
            CP_WAIT0();
        }
        __syncthreads();

        uint32_t buf = smemS + (kc & 1) * 24576;
        const uint32_t aS = buf, bS = buf + 16384;

#pragma unroll
        for (int ks = 0; ks < 4; ks++) {
            uint32_t af[2][4];
#pragma unroll
            for (int mf = 0; mf < 2; mf++) {
                int row = warp * 32 + mf * 16 + lrow;
                uint32_t sw = (uint32_t)(row * 128 + ks * 32 + cb) ^ ((row & 7) << 4);
                LDMX4(af[mf], aS + sw);
            }
#pragma unroll
            for (int nf2 = 0; nf2 < 4; nf2++) {
                int row = nf2 * 16 + lrow;
                uint32_t sw = (uint32_t)(row * 128 + ks * 32 + cb) ^ ((row & 7) << 4);
                uint32_t bfr[4];
                LDMX4(bfr, bS + sw);
#pragma unroll
                for (int mf = 0; mf < 2; mf++) {
                    mma_f16(acc[mf][2 * nf2],     af[mf][0], af[mf][1], af[mf][2], af[mf][3], bfr[0], bfr[2]);
                    mma_f16(acc[mf][2 * nf2 + 1], af[mf][0], af[mf][1], af[mf][2], af[mf][3], bfr[1], bfr[3]);
                }
            }
        }
    }

    const int r0l = lane >> 2;
    const int c2  = (lane & 3) * 2;

    if (MODE == 0) {
        const int n0 = jcol * 64;
#pragma unroll
        for (int mf = 0; mf < 2; mf++) {
            const int m0 = blockIdx.y * 128 + warp * 32 + mf * 16 + r0l;
#pragma unroll
            for (int nf = 0; nf < 8; nf++) {
                int n = n0 + nf * 8 + c2;
                *(float2*)(Cout + (size_t)m0 * Nt + n)       = make_float2(acc[mf][nf][0], acc[mf][nf][1]);
                *(float2*)(Cout + (size_t)(m0 + 8) * Nt + n) = make_float2(acc[mf][nf][2], acc[mf][nf][3]);
            }
        }
    } else {
        const int which = jcol >> 4;     // 0:q 1:k 2:v
        const int h = jcol & 15;
#pragma unroll
        for (int mf = 0; mf < 2; mf++) {
            const int m0 = blockIdx.y * 128 + warp * 32 + mf * 16 + r0l;
            const int m1 = m0 + 8;
            const int b0i = m0 >> 11, n0i = m0 & 2047;
            const int b1i = m1 >> 11, n1i = m1 & 2047;

            if (which == 2) {
                float* vb = g_v;
#pragma unroll
                for (int nf = 0; nf < 8; nf++) {
                    int dd = nf * 8 + c2;
                    *(float2*)&vb[(((size_t)(b0i * NH + h)) * NSEQ + n0i) * HDIM + dd] =
                        make_float2(acc[mf][nf][0], acc[mf][nf][1]);
                    *(float2*)&vb[(((size_t)(b1i * NH + h)) * NSEQ + n1i) * HDIM + dd] =
                        make_float2(acc[mf][nf][2], acc[mf][nf][3]);
                }
            } else {
                const float* w = (which == 0) ? qw : kw;
                char* df = (which == 0) ? (char*)gQf : (char*)gKf;
                float ss0 = 0.f, ss1 = 0.f;
#pragma unroll
                for (int nf = 0; nf < 8; nf++) {
                    ss0 += acc[mf][nf][0] * acc[mf][nf][0] + acc[mf][nf][1] * acc[mf][nf][1];
                    ss1 += acc[mf][nf][2] * acc[mf][nf][2] + acc[mf][nf][3] * acc[mf][nf][3];
                }
                ss0 += __shfl_xor_sync(0xffffffffu, ss0, 1);
                ss0 += __shfl_xor_sync(0xffffffffu, ss0, 2);
                ss1 += __shfl_xor_sync(0xffffffffu, ss1, 1);
                ss1 += __shfl_xor_sync(0xffffffffu, ss1, 2);
                float r0 = rsqrtf(ss0 * (1.0f / HDIM) + 1e-6f);
                float r1 = rsqrtf(ss1 * (1.0f / HDIM) + 1e-6f);

                size_t tb0 = (((size_t)(b0i * NH + h)) * 16 + (n0i >> 7)) * 16384;
                size_t tb1 = (((size_t)(b1i * NH + h)) * 16 + (n1i >> 7)) * 16384;
                int lr0 = n0i & 127, lr1 = n1i & 127;
                uint32_t x0 = (lr0 & 7) << 4, x1 = (lr1 & 7) << 4;
#pragma unroll
                for (int nf = 0; nf < 8; nf++) {
                    int dd = nf * 8 + c2;
                    float2 wv = *(const float2*)(w + dd);
                    float v0 = acc[mf][nf][0] * r0 * wv.x;
                    float v1 = acc[mf][nf][1] * r0 * wv.y;
                    float v2 = acc[mf][nf][2] * r1 * wv.x;
                    float v3 = acc[mf][nf][3] * r1 * wv.y;
                    uint32_t o0 = (lr0 * 128 + dd * 2) ^ x0;
                    uint32_t o1 = (lr1 * 128 + dd * 2) ^ x1;
                    *(uint32_t*)(df + tb0 + o0) = pack2_f16(v0, v1);
                    *(uint32_t*)(df + tb1 + o1) = pack2_f16(v2, v3);
                }
            }
        }
    }
}

// ---------------- V transpose + fp16 convert ----------------
__global__ void __launch_bounds__(256)
vsplit_kernel()
{
    __shared__ float stg[64][65];
    const int kt = blockIdx.x, bh = blockIdx.y;
    const int tid = threadIdx.x;
    {
        int s = tid >> 2, d0 = (tid & 3) * 16;
        const float* vp = g_v + ((size_t)bh * NSEQ + kt * 64 + s) * HDIM + d0;
#pragma unroll
        for (int i = 0; i < 4; i++) {
            float4 v = *(const float4*)(vp + i * 4);
            stg[s][d0 + i * 4 + 0] = v.x;
            stg[s][d0 + i * 4 + 1] = v.y;
            stg[s][d0 + i * 4 + 2] = v.z;
            stg[s][d0 + i * 4 + 3] = v.w;
        }
    }
    __syncthreads();
    {
        int dR = tid >> 2, c0 = (tid & 3) * 16;
        uint32_t hw[8];
#pragma unroll
        for (int j = 0; j < 8; j++)
            hw[j] = pack2_f16(stg[c0 + 2 * j][dR], stg[c0 + 2 * j + 1][dR]);
        size_t tb = ((size_t)bh * 32 + kt) * 8192;
        uint32_t off0 = dR * 128 + c0 * 2;
        uint32_t x = (dR & 7) << 4;
        *(uint4*)((char*)gVtf + tb + (off0 ^ x))        = make_uint4(hw[0], hw[1], hw[2], hw[3]);
        *(uint4*)((char*)gVtf + tb + ((off0 + 16) ^ x)) = make_uint4(hw[4], hw[5], hw[6], hw[7]);
    }
}

// ---------------- bias precompute ----------------
__global__ void __launch_bounds__(256)
bias_kernel(const float* __restrict__ cm, const float* __restrict__ im)
{
    int bq = blockIdx.x;
    int b = bq / NSEQ, q = bq % NSEQ;
    const float* cmb = cm + (size_t)b * NC * NSEQ;
    float c0 = cmb[q], c1 = cmb[NSEQ + q], c2 = cmb[2 * NSEQ + q], c3 = cmb[3 * NSEQ + q];

    float mx = 0.f;
    for (int k = threadIdx.x; k < NSEQ; k += 256) {
        float s = c0 * cmb[k] + c1 * cmb[NSEQ + k] + c2 * cmb[2 * NSEQ + k] + c3 * cmb[3 * NSEQ + k];
        mx = fmaxf(mx, s);
    }
    __shared__ float red[8];
#pragma unroll
    for (int o = 16; o > 0; o >>= 1) mx = fmaxf(mx, __shfl_xor_sync(0xffffffffu, mx, o));
    if ((threadIdx.x & 31) == 0) red[threadIdx.x >> 5] = mx;
    __syncthreads();
    if (threadIdx.x == 0) {
        float m = red[0];
#pragma unroll
        for (int wN = 1; wN < 8; wN++) m = fmaxf(m, red[wN]);
        red[0] = fmaxf(m, 1e-6f);
    }
    __syncthreads();
    float inv = 1.f / red[0];
    const float* imr = im + (size_t)bq * NSEQ;
    float* br = g_bias + (size_t)bq * NSEQ;
    for (int k = threadIdx.x; k < NSEQ; k += 256) {
        float s = c0 * cmb[k] + c1 * cmb[NSEQ + k] + c2 * cmb[2 * NSEQ + k] + c3 * cmb[3 * NSEQ + k];
        br[k] = 2.f * s * inv - 1.f + 0.3f * imr[k];
    }
}

// ---------------- fp16 HMMA flash attention ----------------
// 128 threads, 4 warps, warp tile 32q x 64k.
// smem: Qf 16KB | KVbuf0 16KB | KVbuf1 16KB = 48KB.  KV buffer: Kf 8K | Vtf 8K.
#define ATTN2_SMEM (16384 + 2 * 16384)

__global__ void __launch_bounds__(128, 2)
attn2_kernel(const float* __restrict__ gate)
{
    extern __shared__ char smraw[];
    const uint32_t S = smem_u32(smraw);
    const uint32_t BUF0 = S + 16384;
    const int tid = threadIdx.x, lane = tid & 31, warp = tid >> 5;
    const int bh = blockIdx.y, b = bh >> 4, h = bh & 15;
    const int qt = blockIdx.x, q0 = qt * 128;
    const float LOG2E = 1.44269504f;
    const float g32 = 3.f * fminf(fmaxf(gate[h], 0.f), 1.f) * LOG2E;
    const float SC = 0.125f * LOG2E;
    const int lrow = lane & 15, cb = (lane >> 4) << 4;
    const int wrow = warp * 32;

    // prologue: Qf -> S, KV0 -> BUF0
    {
        size_t qoff = ((size_t)(bh * 16 + qt)) * 16384 + tid * 16;
        uint32_t dq = S + tid * 16;
#pragma unroll
        for (int i = 0; i < 8; i++)
            CP_ASYNC16(dq + i * 2048, (const char*)gQf + qoff + i * 2048);
        size_t koff = ((size_t)(bh * 16)) * 16384 + tid * 16;
        size_t voff = ((size_t)(bh * 32)) * 8192 + tid * 16;
        uint32_t dk = BUF0 + tid * 16;
#pragma unroll
        for (int i = 0; i < 4; i++) {
            CP_ASYNC16(dk + i * 2048,        (const char*)gKf  + koff + i * 2048);
            CP_ASYNC16(dk + 8192 + i * 2048, (const char*)gVtf + voff + i * 2048);
        }
        CP_COMMIT();
    }

    CP_WAIT0();
    __syncthreads();

    uint32_t qf[2][4][4];
#pragma unroll
    for (int mf = 0; mf < 2; mf++) {
        int qrow = wrow + mf * 16 + lrow;
        uint32_t qswz = (uint32_t)((qrow & 7) << 4);
#pragma unroll
        for (int ks = 0; ks < 4; ks++) {
            uint32_t sw = (uint32_t)(qrow * 128 + ks * 32 + cb) ^ qswz;
            LDMX4(qf[mf][ks], S + sw);
        }
    }

    float o[2][8][4];
#pragma unroll
    for (int mf = 0; mf < 2; mf++)
#pragma unroll
        for (int nf = 0; nf < 8; nf++)
#pragma unroll
            for (int t = 0; t < 4; t++) o[mf][nf][t] = 0.f;
    float mr[4] = {-1e30f, -1e30f, -1e30f, -1e30f};
    float lr[4] = {0.f, 0.f, 0.f, 0.f};

    const int r0l = lane >> 2;
    const float* biasP[4];
#pragma unroll
    for (int rr = 0; rr < 4; rr++)
        biasP[rr] = g_bias + ((size_t)(b * NSEQ + q0 + wrow + (rr >> 1) * 16 + (rr & 1) * 8 + r0l)) * NSEQ;

    for (int kt = 0; kt < 32; kt++) {
        __syncthreads();
        if (kt + 1 < 32) {
            int k2 = kt + 1;
            size_t koff = ((size_t)(bh * 16 + (k2 >> 1))) * 16384 + (size_t)(k2 & 1) * 8192 + tid * 16;
            size_t voff = ((size_t)(bh * 32 + k2)) * 8192 + tid * 16;
            uint32_t d = BUF0 + (k2 & 1) * 16384 + tid * 16;
#pragma unroll
            for (int i = 0; i < 4; i++) {
                CP_ASYNC16(d + i * 2048,        (const char*)gKf  + koff + i * 2048);
                CP_ASYNC16(d + 8192 + i * 2048, (const char*)gVtf + voff + i * 2048);
            }
            CP_COMMIT();
            CP_WAIT1();
        } else {
            CP_WAIT0();
        }
        __syncthreads();

        uint32_t buf = BUF0 + (kt & 1) * 16384;

        // --- S = Q K^T ---
        float sf[2][8][4];
#pragma unroll
        for (int mf = 0; mf < 2; mf++)
#pragma unroll
            for (int nf = 0; nf < 8; nf++)
#pragma unroll
                for (int t = 0; t < 4; t++) sf[mf][nf][t] = 0.f;

#pragma unroll
        for (int ks = 0; ks < 4; ks++) {
#pragma unroll
            for (int nf2 = 0; nf2 < 4; nf2++) {
                int row = nf2 * 16 + lrow;
                uint32_t sw = (uint32_t)(row * 128 + ks * 32 + cb) ^ ((row & 7) << 4);
                uint32_t kf[4];
                LDMX4(kf, buf + sw);
#pragma unroll
                for (int mf = 0; mf < 2; mf++) {
                    mma_f16(sf[mf][2 * nf2],     qf[mf][ks][0], qf[mf][ks][1], qf[mf][ks][2], qf[mf][ks][3], kf[0], kf[2]);
                    mma_f16(sf[mf][2 * nf2 + 1], qf[mf][ks][0], qf[mf][ks][1], qf[mf][ks][2], qf[mf][ks][3], kf[1], kf[3]);
                }
            }
        }

        // --- scale + gated bias + online softmax (log2 domain) ---
        int colbase = kt * 64 + 2 * (lane & 3);
#pragma unroll
        for (int mf = 0; mf < 2; mf++) {
            float rm0 = -1e30f, rm1 = -1e30f;
#pragma unroll
            for (int nf = 0; nf < 8; nf++) {
                float2 bb0 = *(const float2*)(biasP[2 * mf]     + colbase + nf * 8);
                float2 bb1 = *(const float2*)(biasP[2 * mf + 1] + colbase + nf * 8);
                sf[mf][nf][0] = fmaf(sf[mf][nf][0], SC, g32 * bb0.x);
                sf[mf][nf][1] = fmaf(sf[mf][nf][1], SC, g32 * bb0.y);
                sf[mf][nf][2] = fmaf(sf[mf][nf][2], SC, g32 * bb1.x);
                sf[mf][nf][3] = fmaf(sf[mf][nf][3], SC, g32 * bb1.y);
                rm0 = fmaxf(rm0, fmaxf(sf[mf][nf][0], sf[mf][nf][1]));
                rm1 = fmaxf(rm1, fmaxf(sf[mf][nf][2], sf[mf][nf][3]));
            }
            rm0 = fmaxf(rm0, __shfl_xor_sync(0xffffffffu, rm0, 1));
            rm0 = fmaxf(rm0, __shfl_xor_sync(0xffffffffu, rm0, 2));
            rm1 = fmaxf(rm1, __shfl_xor_sync(0xffffffffu, rm1, 1));
            rm1 = fmaxf(rm1, __shfl_xor_sync(0xffffffffu, rm1, 2));

            float mn0 = fmaxf(mr[2 * mf], rm0), mn1 = fmaxf(mr[2 * mf + 1], rm1);
            float al0 = ex2f(mr[2 * mf] - mn0), al1 = ex2f(mr[2 * mf + 1] - mn1);
            mr[2 * mf] = mn0; mr[2 * mf + 1] = mn1;
            float rs0 = 0.f, rs1 = 0.f;
#pragma unroll
            for (int nf = 0; nf < 8; nf++) {
                sf[mf][nf][0] = ex2f(sf[mf][nf][0] - mn0);
                sf[mf][nf][1] = ex2f(sf[mf][nf][1] - mn0);
                sf[mf][nf][2] = ex2f(sf[mf][nf][2] - mn1);
                sf[mf][nf][3] = ex2f(sf[mf][nf][3] - mn1);
                rs0 += sf[mf][nf][0] + sf[mf][nf][1];
                rs1 += sf[mf][nf][2] + sf[mf][nf][3];
            }
            rs0 += __shfl_xor_sync(0xffffffffu, rs0, 1);
            rs0 += __shfl_xor_sync(0xffffffffu, rs0, 2);
            rs1 += __shfl_xor_sync(0xffffffffu, rs1, 1);
            rs1 += __shfl_xor_sync(0xffffffffu, rs1, 2);
            lr[2 * mf]     = lr[2 * mf] * al0 + rs0;
            lr[2 * mf + 1] = lr[2 * mf + 1] * al1 + rs1;
#pragma unroll
            for (int nf = 0; nf < 8; nf++) {
                o[mf][nf][0] *= al0; o[mf][nf][1] *= al0;
                o[mf][nf][2] *= al1; o[mf][nf][3] *= al1;
            }
        }

        // --- O += P V ---
        const uint32_t vFs = buf + 8192;
#pragma unroll
        for (int kk = 0; kk < 4; kk++) {
            uint32_t pf[2][4];
#pragma unroll
            for (int mf = 0; mf < 2; mf++) {
                const int na = 2 * kk, nb = 2 * kk + 1;
                pf[mf][0] = pack2_f16(sf[mf][na][0], sf[mf][na][1]);
                pf[mf][1] = pack2_f16(sf[mf][na][2], sf[mf][na][3]);
                pf[mf][2] = pack2_f16(sf[mf][nb][0], sf[mf][nb][1]);
                pf[mf][3] = pack2_f16(sf[mf][nb][2], sf[mf][nb][3]);
            }
#pragma unroll
            for (int nf2 = 0; nf2 < 4; nf2++) {
                int row = nf2 * 16 + lrow;
                uint32_t sw = (uint32_t)(row * 128 + kk * 32 + cb) ^ ((row & 7) << 4);
                uint32_t vf[4];
                LDMX4(vf, vFs + sw);
#pragma unroll
                for (int mf = 0; mf < 2; mf++) {
                    mma_f16(o[mf][2 * nf2],     pf[mf][0], pf[mf][1], pf[mf][2], pf[mf][3], vf[0], vf[2]);
                    mma_f16(o[mf][2 * nf2 + 1], pf[mf][0], pf[mf][1], pf[mf][2], pf[mf][3], vf[1], vf[3]);
                }
            }
        }
    }

    // epilogue: normalize + write fp16 swizzled A-tile for the out-projection
    size_t tb = (((size_t)(b * 16 + qt)) * 16 + h) * 16384;
#pragma unroll
    for (int mf = 0; mf < 2; mf++) {
        float i0 = 1.f / lr[2 * mf], i1 = 1.f / lr[2 * mf + 1];
        int lr0 = wrow + mf * 16 + r0l, lr1 = lr0 + 8;
        uint32_t x0 = (lr0 & 7) << 4, x1 = (lr1 & 7) << 4;
#pragma unroll
        for (int nf = 0; nf < 8; nf++) {
            int dd = nf * 8 + 2 * (lane & 3);
            uint32_t o0 = (lr0 * 128 + dd * 2) ^ x0;
            uint32_t o1 = (lr1 * 128 + dd * 2) ^ x1;
            *(uint32_t*)((char*)gAf + tb + o0) = pack2_f16(o[mf][nf][0] * i0, o[mf][nf][1] * i0);
            *(uint32_t*)((char*)gAf + tb + o1) = pack2_f16(o[mf][nf][2] * i1, o[mf][nf][3] * i1);
        }
    }
}

// ---------------- launch ----------------
extern "C" void kernel_launch(void* const* d_in, const int* in_sizes, int n_in,
                              void* d_out, int out_size)
{
    (void)in_sizes; (void)n_in; (void)out_size;
    const float* x    = (const float*)d_in[0];
    const float* cm   = (const float*)d_in[1];
    const float* im   = (const float*)d_in[2];
    const float* wqkv = (const float*)d_in[3];
    const float* wout = (const float*)d_in[4];
    const float* qnw  = (const float*)d_in[5];
    const float* knw  = (const float*)d_in[6];
    const float* gate = (const float*)d_in[7];
    float* out = (float*)d_out;

    void *xf, *wqf, *wof, *af;
    cudaGetSymbolAddress(&xf, gXf);
    cudaGetSymbolAddress(&wqf, gWqf);
    cudaGetSymbolAddress(&wof, gWof);
    cudaGetSymbolAddress(&af, gAf);

    cudaFuncSetAttribute(attn2_kernel, cudaFuncAttributeMaxDynamicSharedMemorySize, ATTN2_SMEM);
    cudaFuncSetAttribute(gemm_f16<0>, cudaFuncAttributeMaxDynamicSharedMemorySize, GEMM_SMEM);
    cudaFuncSetAttribute(gemm_f16<1>, cudaFuncAttributeMaxDynamicSharedMemorySize, GEMM_SMEM);

    const int M = BB * NSEQ;   // 4096

    // 1) convert inputs to fp16 swizzled tiles
    conv_f16_kernel<<<(4096 * 1024 / 8) / 256, 256>>>(x,    (__half*)xf,  1024);
    conv_f16_kernel<<<(3072 * 1024 / 8) / 256, 256>>>(wqkv, (__half*)wqf, 1024);
    conv_f16_kernel<<<(1024 * 1024 / 8) / 256, 256>>>(wout, (__half*)wof, 1024);

    // 2) QKV projection (fp16 HMMA, 4 CTAs/SM) with fused RMSNorm + fp16 q/k epilogue
    gemm_f16<1><<<dim3(3 * DMOD / 64, M / 128), 128, GEMM_SMEM>>>(
        (const char*)xf, (const char*)wqf, nullptr, 1024 / 64, 3 * DMOD, qnw, knw);

    // 3) V -> transposed fp16 tiles
    vsplit_kernel<<<dim3(NSEQ / 64, BH), 256>>>();

    // 4) bias precompute
    bias_kernel<<<BB * NSEQ, 256>>>(cm, im);

    // 5) fp16 HMMA flash attention (writes fp16 A-tiles for out-proj)
    attn2_kernel<<<dim3(NSEQ / 128, BH), 128, ATTN2_SMEM>>>(gate);

    // 6) out-projection (fp16 HMMA) straight into d_out
    gemm_f16<0><<<dim3(DMOD / 64, M / 128), 128, GEMM_SMEM>>>(
        (const char*)af, (const char*)wof, out, 1024 / 64, DMOD, nullptr, nullptr);
}

// round 13
// speedup vs baseline: 3.5557x; 1.0075x over previous
#include <cuda_runtime.h>
#include <cuda_fp16.h>
#include <math.h>
#include <stdint.h>

#define BB   2
#define NSEQ 2048
#define DMOD 1024
#define NH   16
#define HDIM 64
#define NC   4
#define BH   (BB * NH)

// ---------------- scratch (device globals; no allocation allowed) ----------------
__device__ float g_v[(size_t)BB * NH * NSEQ * HDIM];
__device__ float g_bias[(size_t)BB * NSEQ * NSEQ];

// fp16 operands, pre-swizzled 128x64 SW128 tiles (16KB each)
__device__ __half gXf[(size_t)4096 * 1024];
__device__ __half gWqf[(size_t)3072 * 1024];
__device__ __half gWof[(size_t)1024 * 1024];
__device__ __half gAf[(size_t)4096 * 1024];

// attention operands: single fp16, pre-swizzled tiles
__device__ __half gQf[(size_t)BH * NSEQ * HDIM];
__device__ __half gKf[(size_t)BH * NSEQ * HDIM];
__device__ __half gVtf[(size_t)BH * NSEQ * HDIM];

// ---------------- PTX helpers (base sm_103-legal only) ----------------
__device__ __forceinline__ uint32_t smem_u32(const void* p) {
    uint32_t a;
    asm("{ .reg .u64 t; cvta.to.shared.u64 t, %1; cvt.u32.u64 %0, t; }" : "=r"(a) : "l"(p));
    return a;
}

#define CP_ASYNC16(dst, src) \
    asm volatile("cp.async.cg.shared.global [%0], [%1], 16;" :: "r"(dst), "l"(src) : "memory")
#define CP_COMMIT() asm volatile("cp.async.commit_group;" ::: "memory")
#define CP_WAIT0()  asm volatile("cp.async.wait_group 0;" ::: "memory")
#define CP_WAIT1()  asm volatile("cp.async.wait_group 1;" ::: "memory")

#define LDMX4(r, a) \
    asm volatile("ldmatrix.sync.aligned.m8n8.x4.shared.b16 {%0,%1,%2,%3}, [%4];" \
        : "=r"((r)[0]), "=r"((r)[1]), "=r"((r)[2]), "=r"((r)[3]) : "r"(a))

__device__ __forceinline__ void mma_f16(float* d, uint32_t a0, uint32_t a1,
                                        uint32_t a2, uint32_t a3,
                                        uint32_t b0, uint32_t b1) {
    asm volatile(
        "mma.sync.aligned.m16n8k16.row.col.f32.f16.f16.f32 "
        "{%0,%1,%2,%3},{%4,%5,%6,%7},{%8,%9},{%0,%1,%2,%3};"
        : "+f"(d[0]), "+f"(d[1]), "+f"(d[2]), "+f"(d[3])
        : "r"(a0), "r"(a1), "r"(a2), "r"(a3), "r"(b0), "r"(b1));
}

// fp16x2 pack: first arg -> lower half
__device__ __forceinline__ uint32_t pack2_f16(float lo, float hi) {
    uint32_t r;
    asm("cvt.rn.f16x2.f32 %0, %1, %2;" : "=r"(r) : "f"(hi), "f"(lo));
    return r;
}
__device__ __forceinline__ float ex2f(float x) {
    float r;
    asm("ex2.approx.f32 %0, %1;" : "=f"(r) : "f"(x));
    return r;
}
__device__ __forceinline__ uint32_t ex2_f16x2(uint32_t x) {
    uint32_t r;
    asm("ex2.approx.f16x2 %0, %1;" : "=r"(r) : "r"(x));
    return r;
}

#define ONES2 0x3C003C00u   // fp16x2 {1.0, 1.0}

// ---------------- conversion: fp32 row-major -> blocked swizzled fp16 tiles ----------------
__global__ void __launch_bounds__(256)
conv_f16_kernel(const float* __restrict__ src, __half* __restrict__ dst, int K)
{
    size_t idx = ((size_t)blockIdx.x * 256 + threadIdx.x) * 8;
    int r  = (int)(idx / K);
    int c0 = (int)(idx % K);
    float4 v0 = *(const float4*)(src + idx);
    float4 v1 = *(const float4*)(src + idx + 4);
    uint4 w;
    w.x = pack2_f16(v0.x, v0.y);
    w.y = pack2_f16(v0.z, v0.w);
    w.z = pack2_f16(v1.x, v1.y);
    w.w = pack2_f16(v1.z, v1.w);
    int rt = r >> 7, lr = r & 127, ch = c0 >> 6, lc = c0 & 63;
    size_t tile = (size_t)rt * (K >> 6) + ch;
    uint32_t off = lr * 128 + lc * 2;
    uint32_t sw = off ^ ((off >> 3) & 0x70);
    *(uint4*)((char*)dst + tile * 16384 + sw) = w;
}

// ---------------- fp16 HMMA GEMM: 128 threads, 4 warps, warp tile 64x64, CTA tile 256x64 ----------------
// buffer 40KB (A0 16K | A1 16K | B 8K), double-buffered 80KB -> 2 CTAs/SM.
// A-frags reused over 8 n-frags, B-frags over 4 m-frags -> 128 B LDSM per MMA.
#define GEMM_SMEM (2 * 40 * 1024)

template <int MODE>
__global__ void __launch_bounds__(128, 2)
gemm_f16(const char* __restrict__ Af, const char* __restrict__ Bf,
         float* __restrict__ Cout, int KC, int Nt,
         const float* __restrict__ qw, const float* __restrict__ kw)
{
    extern __shared__ char smraw[];
    const uint32_t smemS = smem_u32(smraw);
    const int tid  = threadIdx.x;
    const int lane = tid & 31;
    const int warp = tid >> 5;
    const int jcol = blockIdx.x;

    const size_t tA0 = (size_t)(2 * blockIdx.y)     * KC * 16384;
    const size_t tA1 = (size_t)(2 * blockIdx.y + 1) * KC * 16384;
    const size_t tB0 = ((size_t)(jcol >> 1) * KC) * 16384 + (size_t)(jcol & 1) * 8192;

    float acc[4][8][4];
#pragma unroll
    for (int m = 0; m < 4; m++)
#pragma unroll
        for (int j = 0; j < 8; j++)
#pragma unroll
            for (int t = 0; t < 4; t++) acc[m][j][t] = 0.f;

    const int lrow = lane & 15;
    const int cb   = (lane >> 4) << 4;

    // prologue: chunk 0 into buffer 0 (A0 8 + A1 8 + B 4 x 16B per thread)
    {
        const char* sA0 = Af + tA0 + tid * 16;
        const char* sA1 = Af + tA1 + tid * 16;
        const char* sB  = Bf + tB0 + tid * 16;
        uint32_t d0 = smemS + tid * 16;
#pragma unroll
        for (int i = 0; i < 8; i++) {
            CP_ASYNC16(d0 + i * 2048,         sA0 + i * 2048);
            CP_ASYNC16(d0 + 16384 + i * 2048, sA1 + i * 2048);
        }
#pragma unroll
        for (int i = 0; i < 4; i++) CP_ASYNC16(d0 + 32768 + i * 2048, sB + i * 2048);
        CP_COMMIT();
    }

    for (int kc = 0; kc < KC; kc++) {
        __syncthreads();
        if (kc + 1 < KC) {
            size_t go = (size_t)(kc + 1) * 16384;
            const char* sA0 = Af + tA0 + go + tid * 16;
            const char* sA1 = Af + tA1 + go + tid * 16;
            const char* sB  = Bf + tB0 + go + tid * 16;
            uint32_t d0 = smemS + ((kc + 1) & 1) * 40960 + tid * 16;
#pragma unroll
            for (int i = 0; i < 8; i++) {
                CP_ASYNC16(d0 + i * 2048,         sA0 + i * 2048);
                CP_ASYNC16(d0 + 16384 + i * 2048, sA1 + i * 2048);
            }
#pragma unroll
            for (int i = 0; i < 4; i++) CP_ASYNC16(d0 + 32768 + i * 2048, sB + i * 2048);
            CP_COMMIT();
            CP_WAIT1();
        } else {
            CP_WAIT0();
        }
        __syncthreads();

        uint32_t buf = smemS + (kc & 1) * 40960;
        // warps 0,1 read A0 (rows 0..127); warps 2,3 read A1 (rows 128..255)
        const uint32_t aS = buf + (warp >> 1) * 16384;
        const uint32_t bS = buf + 32768;
        const int wrowA = (warp & 1) * 64;

#pragma unroll
        for (int ks = 0; ks < 4; ks++) {
            uint32_t af[4][4];
#pragma unroll
            for (int mf = 0; mf < 4; mf++) {
                int row = wrowA + mf * 16 + lrow;
                uint32_t sw = (uint32_t)(row * 128 + ks * 32 + cb) ^ ((row & 7) << 4);
                LDMX4(af[mf], aS + sw);
            }
#pragma unroll
            for (int nf2 = 0; nf2 < 4; nf2++) {
                int row = nf2 * 16 + lrow;
                uint32_t sw = (uint32_t)(row * 128 + ks * 32 + cb) ^ ((row & 7) << 4);
                uint32_t bfr[4];
                LDMX4(bfr, bS + sw);
#pragma unroll
                for (int mf = 0; mf < 4; mf++) {
                    mma_f16(acc[mf][2 * nf2],     af[mf][0], af[mf][1], af[mf][2], af[mf][3], bfr[0], bfr[2]);
                    mma_f16(acc[mf][2 * nf2 + 1], af[mf][0], af[mf][1], af[mf][2], af[mf][3], bfr[1], bfr[3]);
                }
            }
        }
    }

    const int r0l = lane >> 2;
    const int c2  = (lane & 3) * 2;

    if (MODE == 0) {
        const int n0 = jcol * 64;
#pragma unroll
        for (int mf = 0; mf < 4; mf++) {
            const int m0 = blockIdx.y * 256 + warp * 64 + mf * 16 + r0l;
#pragma unroll
            for (int nf = 0; nf < 8; nf++) {
                int n = n0 + nf * 8 + c2;
                *(float2*)(Cout + (size_t)m0 * Nt + n)       = make_float2(acc[mf][nf][0], acc[mf][nf][1]);
                *(float2*)(Cout + (size_t)(m0 + 8) * Nt + n) = make_float2(acc[mf][nf][2], acc[mf][nf][3]);
            }
        }
    } else {
        const int which = jcol >> 4;     // 0:q 1:k 2:v
        const int h = jcol & 15;
#pragma unroll
        for (int mf = 0; mf < 4; mf++) {
            const int m0 = blockIdx.y * 256 + warp * 64 + mf * 16 + r0l;
            const int m1 = m0 + 8;
            const int b0i = m0 >> 11, n0i = m0 & 2047;
            const int b1i = m1 >> 11, n1i = m1 & 2047;

            if (which == 2) {
                float* vb = g_v;
#pragma unroll
                for (int nf = 0; nf < 8; nf++) {
                    int dd = nf * 8 + c2;
                    *(float2*)&vb[(((size_t)(b0i * NH + h)) * NSEQ + n0i) * HDIM + dd] =
                        make_float2(acc[mf][nf][0], acc[mf][nf][1]);
                    *(float2*)&vb[(((size_t)(b1i * NH + h)) * NSEQ + n1i) * HDIM + dd] =
                        make_float2(acc[mf][nf][2], acc[mf][nf][3]);
                }
            } else {
                const float* w = (which == 0) ? qw : kw;
                char* df = (which == 0) ? (char*)gQf : (char*)gKf;
                float ss0 = 0.f, ss1 = 0.f;
#pragma unroll
                for (int nf = 0; nf < 8; nf++) {
                    ss0 += acc[mf][nf][0] * acc[mf][nf][0] + acc[mf][nf][1] * acc[mf][nf][1];
                    ss1 += acc[mf][nf][2] * acc[mf][nf][2] + acc[mf][nf][3] * acc[mf][nf][3];
                }
                ss0 += __shfl_xor_sync(0xffffffffu, ss0, 1);
                ss0 += __shfl_xor_sync(0xffffffffu, ss0, 2);
                ss1 += __shfl_xor_sync(0xffffffffu, ss1, 1);
                ss1 += __shfl_xor_sync(0xffffffffu, ss1, 2);
                float r0 = rsqrtf(ss0 * (1.0f / HDIM) + 1e-6f);
                float r1 = rsqrtf(ss1 * (1.0f / HDIM) + 1e-6f);

                size_t tb0 = (((size_t)(b0i * NH + h)) * 16 + (n0i >> 7)) * 16384;
                size_t tb1 = (((size_t)(b1i * NH + h)) * 16 + (n1i >> 7)) * 16384;
                int lr0 = n0i & 127, lr1 = n1i & 127;
                uint32_t x0 = (lr0 & 7) << 4, x1 = (lr1 & 7) << 4;
#pragma unroll
                for (int nf = 0; nf < 8; nf++) {
                    int dd = nf * 8 + c2;
                    float2 wv = *(const float2*)(w + dd);
                    float v0 = acc[mf][nf][0] * r0 * wv.x;
                    float v1 = acc[mf][nf][1] * r0 * wv.y;
                    float v2 = acc[mf][nf][2] * r1 * wv.x;
                    float v3 = acc[mf][nf][3] * r1 * wv.y;
                    uint32_t o0 = (lr0 * 128 + dd * 2) ^ x0;
                    uint32_t o1 = (lr1 * 128 + dd * 2) ^ x1;
                    *(uint32_t*)(df + tb0 + o0) = pack2_f16(v0, v1);
                    *(uint32_t*)(df + tb1 + o1) = pack2_f16(v2, v3);
                }
            }
        }
    }
}

// ---------------- V transpose + fp16 convert ----------------
__global__ void __launch_bounds__(256)
vsplit_kernel()
{
    __shared__ float stg[64][65];
    const int kt = blockIdx.x, bh = blockIdx.y;
    const int tid = threadIdx.x;
    {
        int s = tid >> 2, d0 = (tid & 3) * 16;
        const float* vp = g_v + ((size_t)bh * NSEQ + kt * 64 + s) * HDIM + d0;
#pragma unroll
        for (int i = 0; i < 4; i++) {
            float4 v = *(const float4*)(vp + i * 4);
            stg[s][d0 + i * 4 + 0] = v.x;
            stg[s][d0 + i * 4 + 1] = v.y;
            stg[s][d0 + i * 4 + 2] = v.z;
            stg[s][d0 + i * 4 + 3] = v.w;
        }
    }
    __syncthreads();
    {
        int dR = tid >> 2, c0 = (tid & 3) * 16;
        uint32_t hw[8];
#pragma unroll
        for (int j = 0; j < 8; j++)
            hw[j] = pack2_f16(stg[c0 + 2 * j][dR], stg[c0 + 2 * j + 1][dR]);
        size_t tb = ((size_t)bh * 32 + kt) * 8192;
        uint32_t off0 = dR * 128 + c0 * 2;
        uint32_t x = (dR & 7) << 4;
        *(uint4*)((char*)gVtf + tb + (off0 ^ x))        = make_uint4(hw[0], hw[1], hw[2], hw[3]);
        *(uint4*)((char*)gVtf + tb + ((off0 + 16) ^ x)) = make_uint4(hw[4], hw[5], hw[6], hw[7]);
    }
}

// ---------------- bias precompute ----------------
__global__ void __launch_bounds__(256)
bias_kernel(const float* __restrict__ cm, const float* __restrict__ im)
{
    int bq = blockIdx.x;
    int b = bq / NSEQ, q = bq % NSEQ;
    const float* cmb = cm + (size_t)b * NC * NSEQ;
    float c0 = cmb[q], c1 = cmb[NSEQ + q], c2 = cmb[2 * NSEQ + q], c3 = cmb[3 * NSEQ + q];

    float mx = 0.f;
    for (int k = threadIdx.x; k < NSEQ; k += 256) {
        float s = c0 * cmb[k] + c1 * cmb[NSEQ + k] + c2 * cmb[2 * NSEQ + k] + c3 * cmb[3 * NSEQ + k];
        mx = fmaxf(mx, s);
    }
    __shared__ float red[8];
#pragma unroll
    for (int o = 16; o > 0; o >>= 1) mx = fmaxf(mx, __shfl_xor_sync(0xffffffffu, mx, o));
    if ((threadIdx.x & 31) == 0) red[threadIdx.x >> 5] = mx;
    __syncthreads();
    if (threadIdx.x == 0) {
        float m = red[0];
#pragma unroll
        for (int wN = 1; wN < 8; wN++) m = fmaxf(m, red[wN]);
        red[0] = fmaxf(m, 1e-6f);
    }
    __syncthreads();
    float inv = 1.f / red[0];
    const float* imr = im + (size_t)bq * NSEQ;
    float* br = g_bias + (size_t)bq * NSEQ;
    for (int k = threadIdx.x; k < NSEQ; k += 256) {
        float s = c0 * cmb[k] + c1 * cmb[NSEQ + k] + c2 * cmb[2 * NSEQ + k] + c3 * cmb[3 * NSEQ + k];
        br[k] = 2.f * s * inv - 1.f + 0.3f * imr[k];
    }
}

// ---------------- fp16 HMMA flash attention ----------------
// 128 threads, 4 warps, warp tile 32q x 64k.
// smem: Qf 16KB | KVbuf0 16KB | KVbuf1 16KB = 48KB.
// Softmax: ex2.approx.f16x2 on packed P pairs; row sums via ones-vector MMA.
#define ATTN2_SMEM (16384 + 2 * 16384)

__global__ void __launch_bounds__(128, 2)
attn2_kernel(const float* __restrict__ gate)
{
    extern __shared__ char smraw[];
    const uint32_t S = smem_u32(smraw);
    const uint32_t BUF0 = S + 16384;
    const int tid = threadIdx.x, lane = tid & 31, warp = tid >> 5;
    const int bh = blockIdx.y, b = bh >> 4, h = bh & 15;
    const int qt = blockIdx.x, q0 = qt * 128;
    const float LOG2E = 1.44269504f;
    const float g32 = 3.f * fminf(fmaxf(gate[h], 0.f), 1.f) * LOG2E;
    const float SC = 0.125f * LOG2E;
    const int lrow = lane & 15, cb = (lane >> 4) << 4;
    const int wrow = warp * 32;

    // prologue: Qf -> S, KV0 -> BUF0
    {
        size_t qoff = ((size_t)(bh * 16 + qt)) * 16384 + tid * 16;
        uint32_t dq = S + tid * 16;
#pragma unroll
        for (int i = 0; i < 8; i++)
            CP_ASYNC16(dq + i * 2048, (const char*)gQf + qoff + i * 2048);
        size_t koff = ((size_t)(bh * 16)) * 16384 + tid * 16;
        size_t voff = ((size_t)(bh * 32)) * 8192 + tid * 16;
        uint32_t dk = BUF0 + tid * 16;
#pragma unroll
        for (int i = 0; i < 4; i++) {
            CP_ASYNC16(dk + i * 2048,        (const char*)gKf  + koff + i * 2048);
            CP_ASYNC16(dk + 8192 + i * 2048, (const char*)gVtf + voff + i * 2048);
        }
        CP_COMMIT();
    }

    CP_WAIT0();
    __syncthreads();

    uint32_t qf[2][4][4];
#pragma unroll
    for (int mf = 0; mf < 2; mf++) {
        int qrow = wrow + mf * 16 + lrow;
        uint32_t qswz = (uint32_t)((qrow & 7) << 4);
#pragma unroll
        for (int ks = 0; ks < 4; ks++) {
            uint32_t sw = (uint32_t)(qrow * 128 + ks * 32 + cb) ^ qswz;
            LDMX4(qf[mf][ks], S + sw);
        }
    }

    float o[2][8][4];
#pragma unroll
    for (int mf = 0; mf < 2; mf++)
#pragma unroll
        for (int nf = 0; nf < 8; nf++)
#pragma unroll
            for (int t = 0; t < 4; t++) o[mf][nf][t] = 0.f;
    float mr[4] = {-1e30f, -1e30f, -1e30f, -1e30f};
    float lr[4] = {0.f, 0.f, 0.f, 0.f};

    const int r0l = lane >> 2;
    const float* biasP[4];
#pragma unroll
    for (int rr = 0; rr < 4; rr++)
        biasP[rr] = g_bias + ((size_t)(b * NSEQ + q0 + wrow + (rr >> 1) * 16 + (rr & 1) * 8 + r0l)) * NSEQ;

    for (int kt = 0; kt < 32; kt++) {
        __syncthreads();
        if (kt + 1 < 32) {
            int k2 = kt + 1;
            size_t koff = ((size_t)(bh * 16 + (k2 >> 1))) * 16384 + (size_t)(k2 & 1) * 8192 + tid * 16;
            size_t voff = ((size_t)(bh * 32 + k2)) * 8192 + tid * 16;
            uint32_t d = BUF0 + (k2 & 1) * 16384 + tid * 16;
#pragma unroll
            for (int i = 0; i < 4; i++) {
                CP_ASYNC16(d + i * 2048,        (const char*)gKf  + koff + i * 2048);
                CP_ASYNC16(d + 8192 + i * 2048, (const char*)gVtf + voff + i * 2048);
            }
            CP_COMMIT();
            CP_WAIT1();
        } else {
            CP_WAIT0();
        }
        __syncthreads();

        uint32_t buf = BUF0 + (kt & 1) * 16384;

        // --- S = Q K^T ---
        float sf[2][8][4];
#pragma unroll
        for (int mf = 0; mf < 2; mf++)
#pragma unroll
            for (int nf = 0; nf < 8; nf++)
#pragma unroll
                for (int t = 0; t < 4; t++) sf[mf][nf][t] = 0.f;

#pragma unroll
        for (int ks = 0; ks < 4; ks++) {
#pragma unroll
            for (int nf2 = 0; nf2 < 4; nf2++) {
                int row = nf2 * 16 + lrow;
                uint32_t sw = (uint32_t)(row * 128 + ks * 32 + cb) ^ ((row & 7) << 4);
                uint32_t kf[4];
                LDMX4(kf, buf + sw);
#pragma unroll
                for (int mf = 0; mf < 2; mf++) {
                    mma_f16(sf[mf][2 * nf2],     qf[mf][ks][0], qf[mf][ks][1], qf[mf][ks][2], qf[mf][ks][3], kf[0], kf[2]);
                    mma_f16(sf[mf][2 * nf2 + 1], qf[mf][ks][0], qf[mf][ks][1], qf[mf][ks][2], qf[mf][ks][3], kf[1], kf[3]);
                }
            }
        }

        // --- scale + gated bias + online softmax (log2 domain, fp16x2 exp, MMA row-sum) ---
        int colbase = kt * 64 + 2 * (lane & 3);
        uint32_t pf[2][4][4];
#pragma unroll
        for (int mf = 0; mf < 2; mf++) {
            float rm0 = -1e30f, rm1 = -1e30f;
#pragma unroll
            for (int nf = 0; nf < 8; nf++) {
                float2 bb0 = *(const float2*)(biasP[2 * mf]     + colbase + nf * 8);
                float2 bb1 = *(const float2*)(biasP[2 * mf + 1] + colbase + nf * 8);
                sf[mf][nf][0] = fmaf(sf[mf][nf][0], SC, g32 * bb0.x);
                sf[mf][nf][1] = fmaf(sf[mf][nf][1], SC, g32 * bb0.y);
                sf[mf][nf][2] = fmaf(sf[mf][nf][2], SC, g32 * bb1.x);
                sf[mf][nf][3] = fmaf(sf[mf][nf][3], SC, g32 * bb1.y);
                rm0 = fmaxf(rm0, fmaxf(sf[mf][nf][0], sf[mf][nf][1]));
                rm1 = fmaxf(rm1, fmaxf(sf[mf][nf][2], sf[mf][nf][3]));
            }
            rm0 = fmaxf(rm0, __shfl_xor_sync(0xffffffffu, rm0, 1));
            rm0 = fmaxf(rm0, __shfl_xor_sync(0xffffffffu, rm0, 2));
            rm1 = fmaxf(rm1, __shfl_xor_sync(0xffffffffu, rm1, 1));
            rm1 = fmaxf(rm1, __shfl_xor_sync(0xffffffffu, rm1, 2));

            float mn0 = fmaxf(mr[2 * mf], rm0), mn1 = fmaxf(mr[2 * mf + 1], rm1);
            float al0 = ex2f(mr[2 * mf] - mn0), al1 = ex2f(mr[2 * mf + 1] - mn1);
            mr[2 * mf] = mn0; mr[2 * mf + 1] = mn1;

            float rsd[4] = {0.f, 0.f, 0.f, 0.f};
#pragma unroll
            for (int kk = 0; kk < 4; kk++) {
                const int na = 2 * kk, nb = 2 * kk + 1;
                pf[mf][kk][0] = ex2_f16x2(pack2_f16(sf[mf][na][0] - mn0, sf[mf][na][1] - mn0));
                pf[mf][kk][1] = ex2_f16x2(pack2_f16(sf[mf][na][2] - mn1, sf[mf][na][3] - mn1));
                pf[mf][kk][2] = ex2_f16x2(pack2_f16(sf[mf][nb][0] - mn0, sf[mf][nb][1] - mn0));
                pf[mf][kk][3] = ex2_f16x2(pack2_f16(sf[mf][nb][2] - mn1, sf[mf][nb][3] - mn1));
                mma_f16(rsd, pf[mf][kk][0], pf[mf][kk][1], pf[mf][kk][2], pf[mf][kk][3], ONES2, ONES2);
            }
            lr[2 * mf]     = lr[2 * mf] * al0 + rsd[0];
            lr[2 * mf + 1] = lr[2 * mf + 1] * al1 + rsd[2];
#pragma unroll
            for (int nf = 0; nf < 8; nf++) {
                o[mf][nf][0] *= al0; o[mf][nf][1] *= al0;
                o[mf][nf][2] *= al1; o[mf][nf][3] *= al1;
            }
        }

        // --- O += P V ---
        const uint32_t vFs = buf + 8192;
#pragma unroll
        for (int kk = 0; kk < 4; kk++) {
#pragma unroll
            for (int nf2 = 0; nf2 < 4; nf2++) {
                int row = nf2 * 16 + lrow;
                uint32_t sw = (uint32_t)(row * 128 + kk * 32 + cb) ^ ((row & 7) << 4);
                uint32_t vf[4];
                LDMX4(vf, vFs + sw);
#pragma unroll
                for (int mf = 0; mf < 2; mf++) {
                    mma_f16(o[mf][2 * nf2],     pf[mf][kk][0], pf[mf][kk][1], pf[mf][kk][2], pf[mf][kk][3], vf[0], vf[2]);
                    mma_f16(o[mf][2 * nf2 + 1], pf[mf][kk][0], pf[mf][kk][1], pf[mf][kk][2], pf[mf][kk][3], vf[1], vf[3]);
                }
            }
        }
    }

    // epilogue: normalize + write fp16 swizzled A-tile for the out-projection
    size_t tb = (((size_t)(b * 16 + qt)) * 16 + h) * 16384;
#pragma unroll
    for (int mf = 0; mf < 2; mf++) {
        float i0 = 1.f / lr[2 * mf], i1 = 1.f / lr[2 * mf + 1];
        int lr0 = wrow + mf * 16 + r0l, lr1 = lr0 + 8;
        uint32_t x0 = (lr0 & 7) << 4, x1 = (lr1 & 7) << 4;
#pragma unroll
        for (int nf = 0; nf < 8; nf++) {
            int dd = nf * 8 + 2 * (lane & 3);
            uint32_t o0 = (lr0 * 128 + dd * 2) ^ x0;
            uint32_t o1 = (lr1 * 128 + dd * 2) ^ x1;
            *(uint32_t*)((char*)gAf + tb + o0) = pack2_f16(o[mf][nf][0] * i0, o[mf][nf][1] * i0);
            *(uint32_t*)((char*)gAf + tb + o1) = pack2_f16(o[mf][nf][2] * i1, o[mf][nf][3] * i1);
        }
    }
}

// ---------------- launch ----------------
extern "C" void kernel_launch(void* const* d_in, const int* in_sizes, int n_in,
                              void* d_out, int out_size)
{
    (void)in_sizes; (void)n_in; (void)out_size;
    const float* x    = (const float*)d_in[0];
    const float* cm   = (const float*)d_in[1];
    const float* im   = (const float*)d_in[2];
    const float* wqkv = (const float*)d_in[3];
    const float* wout = (const float*)d_in[4];
    const float* qnw  = (const float*)d_in[5];
    const float* knw  = (const float*)d_in[6];
    const float* gate = (const float*)d_in[7];
    float* out = (float*)d_out;

    void *xf, *wqf, *wof, *af;
    cudaGetSymbolAddress(&xf, gXf);
    cudaGetSymbolAddress(&wqf, gWqf);
    cudaGetSymbolAddress(&wof, gWof);
    cudaGetSymbolAddress(&af, gAf);

    cudaFuncSetAttribute(attn2_kernel, cudaFuncAttributeMaxDynamicSharedMemorySize, ATTN2_SMEM);
    cudaFuncSetAttribute(gemm_f16<0>, cudaFuncAttributeMaxDynamicSharedMemorySize, GEMM_SMEM);
    cudaFuncSetAttribute(gemm_f16<1>, cudaFuncAttributeMaxDynamicSharedMemorySize, GEMM_SMEM);

    const int M = BB * NSEQ;   // 4096

    // 1) convert inputs to fp16 swizzled tiles
    conv_f16_kernel<<<(4096 * 1024 / 8) / 256, 256>>>(x,    (__half*)xf,  1024);
    conv_f16_kernel<<<(3072 * 1024 / 8) / 256, 256>>>(wqkv, (__half*)wqf, 1024);
    conv_f16_kernel<<<(1024 * 1024 / 8) / 256, 256>>>(wout, (__half*)wof, 1024);

    // 2) QKV projection (fp16 HMMA, 256x64 CTA tile) with fused RMSNorm + fp16 q/k epilogue
    gemm_f16<1><<<dim3(3 * DMOD / 64, M / 256), 128, GEMM_SMEM>>>(
        (const char*)xf, (const char*)wqf, nullptr, 1024 / 64, 3 * DMOD, qnw, knw);

    // 3) V -> transposed fp16 tiles
    vsplit_kernel<<<dim3(NSEQ / 64, BH), 256>>>();

    // 4) bias precompute
    bias_kernel<<<BB * NSEQ, 256>>>(cm, im);

    // 5) fp16 HMMA flash attention (writes fp16 A-tiles for out-proj)
    attn2_kernel<<<dim3(NSEQ / 128, BH), 128, ATTN2_SMEM>>>(gate);

    // 6) out-projection (fp16 HMMA) straight into d_out
    gemm_f16<0><<<dim3(DMOD / 64, M / 256), 128, GEMM_SMEM>>>(
        (const char*)af, (const char*)wof, out, 1024 / 64, DMOD, nullptr, nullptr);
}

// round 15
// speedup vs baseline: 3.7629x; 1.0583x over previous
#include <cuda_runtime.h>
#include <cuda_fp16.h>
#include <math.h>
#include <stdint.h>

#define BB   2
#define NSEQ 2048
#define DMOD 1024
#define NH   16
#define HDIM 64
#define NC   4
#define BH   (BB * NH)

// ---------------- scratch (device globals; no allocation allowed) ----------------
__device__ float g_v[(size_t)BB * NH * NSEQ * HDIM];
__device__ float g_bias[(size_t)BB * NSEQ * NSEQ];

// fp16 operands, pre-swizzled 128x64 SW128 tiles (16KB each)
__device__ __half gXf[(size_t)4096 * 1024];
__device__ __half gWqf[(size_t)3072 * 1024];
__device__ __half gWof[(size_t)1024 * 1024];
__device__ __half gAf[(size_t)4096 * 1024];

// attention operands: single fp16, pre-swizzled tiles
__device__ __half gQf[(size_t)BH * NSEQ * HDIM];
__device__ __half gKf[(size_t)BH * NSEQ * HDIM];
__device__ __half gVtf[(size_t)BH * NSEQ * HDIM];

// ---------------- PTX helpers (base sm_103-legal only) ----------------
__device__ __forceinline__ uint32_t smem_u32(const void* p) {
    uint32_t a;
    asm("{ .reg .u64 t; cvta.to.shared.u64 t, %1; cvt.u32.u64 %0, t; }" : "=r"(a) : "l"(p));
    return a;
}

#define CP_ASYNC16(dst, src) \
    asm volatile("cp.async.cg.shared.global [%0], [%1], 16;" :: "r"(dst), "l"(src) : "memory")
#define CP_COMMIT() asm volatile("cp.async.commit_group;" ::: "memory")
#define CP_WAIT0()  asm volatile("cp.async.wait_group 0;" ::: "memory")
#define CP_WAIT1()  asm volatile("cp.async.wait_group 1;" ::: "memory")

#define LDMX4(r, a) \
    asm volatile("ldmatrix.sync.aligned.m8n8.x4.shared.b16 {%0,%1,%2,%3}, [%4];" \
        : "=r"((r)[0]), "=r"((r)[1]), "=r"((r)[2]), "=r"((r)[3]) : "r"(a))

__device__ __forceinline__ void mma_f16(float* d, uint32_t a0, uint32_t a1,
                                        uint32_t a2, uint32_t a3,
                                        uint32_t b0, uint32_t b1) {
    asm volatile(
        "mma.sync.aligned.m16n8k16.row.col.f32.f16.f16.f32 "
        "{%0,%1,%2,%3},{%4,%5,%6,%7},{%8,%9},{%0,%1,%2,%3};"
        : "+f"(d[0]), "+f"(d[1]), "+f"(d[2]), "+f"(d[3])
        : "r"(a0), "r"(a1), "r"(a2), "r"(a3), "r"(b0), "r"(b1));
}

// fp16x2 pack: first arg -> lower half
__device__ __forceinline__ uint32_t pack2_f16(float lo, float hi) {
    uint32_t r;
    asm("cvt.rn.f16x2.f32 %0, %1, %2;" : "=r"(r) : "f"(hi), "f"(lo));
    return r;
}
__device__ __forceinline__ float ex2f(float x) {
    float r;
    asm("ex2.approx.f32 %0, %1;" : "=f"(r) : "f"(x));
    return r;
}
__device__ __forceinline__ uint32_t ex2_f16x2(uint32_t x) {
    uint32_t r;
    asm("ex2.approx.f16x2 %0, %1;" : "=r"(r) : "r"(x));
    return r;
}

#define ONES2 0x3C003C00u   // fp16x2 {1.0, 1.0}

// ---------------- conversion: fp32 row-major -> blocked swizzled fp16 tiles ----------------
__global__ void __launch_bounds__(256)
conv_f16_kernel(const float* __restrict__ src, __half* __restrict__ dst, int K)
{
    size_t idx = ((size_t)blockIdx.x * 256 + threadIdx.x) * 8;
    int r  = (int)(idx / K);
    int c0 = (int)(idx % K);
    float4 v0 = *(const float4*)(src + idx);
    float4 v1 = *(const float4*)(src + idx + 4);
    uint4 w;
    w.x = pack2_f16(v0.x, v0.y);
    w.y = pack2_f16(v0.z, v0.w);
    w.z = pack2_f16(v1.x, v1.y);
    w.w = pack2_f16(v1.z, v1.w);
    int rt = r >> 7, lr = r & 127, ch = c0 >> 6, lc = c0 & 63;
    size_t tile = (size_t)rt * (K >> 6) + ch;
    uint32_t off = lr * 128 + lc * 2;
    uint32_t sw = off ^ ((off >> 3) & 0x70);
    *(uint4*)((char*)dst + tile * 16384 + sw) = w;
}

// ---------------- fp16 HMMA GEMM: 128 threads, 4 warps, warp tile 32x64, CTA tile 128x64 ----------------
// buffer 24KB (A 16K | B 8K), double-buffered 48KB -> 4 CTAs/SM.  (round-12 config, measured 74us)
#define GEMM_SMEM (2 * 24 * 1024)

template <int MODE>
__global__ void __launch_bounds__(128, 4)
gemm_f16(const char* __restrict__ Af, const char* __restrict__ Bf,
         float* __restrict__ Cout, int KC, int Nt,
         const float* __restrict__ qw, const float* __restrict__ kw)
{
    extern __shared__ char smraw[];
    const uint32_t smemS = smem_u32(smraw);
    const int tid  = threadIdx.x;
    const int lane = tid & 31;
    const int warp = tid >> 5;
    const int jcol = blockIdx.x;

    const size_t tA0 = (size_t)blockIdx.y * KC * 16384;
    const size_t tB0 = ((size_t)(jcol >> 1) * KC) * 16384 + (size_t)(jcol & 1) * 8192;

    float acc[2][8][4];
#pragma unroll
    for (int m = 0; m < 2; m++)
#pragma unroll
        for (int j = 0; j < 8; j++)
#pragma unroll
            for (int t = 0; t < 4; t++) acc[m][j][t] = 0.f;

    const int lrow = lane & 15;
    const int cb   = (lane >> 4) << 4;

    // prologue: chunk 0 into buffer 0 (A: 8 x 16B/thread, B: 4 x 16B/thread)
    {
        const char* sA = Af + tA0 + tid * 16;
        const char* sB = Bf + tB0 + tid * 16;
        uint32_t d0 = smemS + tid * 16;
#pragma unroll
        for (int i = 0; i < 8; i++) CP_ASYNC16(d0 + i * 2048, sA + i * 2048);
#pragma unroll
        for (int i = 0; i < 4; i++) CP_ASYNC16(d0 + 16384 + i * 2048, sB + i * 2048);
        CP_COMMIT();
    }

    for (int kc = 0; kc < KC; kc++) {
        __syncthreads();
        if (kc + 1 < KC) {
            const char* sA = Af + tA0 + (size_t)(kc + 1) * 16384 + tid * 16;
            const char* sB = Bf + tB0 + (size_t)(kc + 1) * 16384 + tid * 16;
            uint32_t d0 = smemS + ((kc + 1) & 1) * 24576 + tid * 16;
#pragma unroll
            for (int i = 0; i < 8; i++) CP_ASYNC16(d0 + i * 2048, sA + i * 2048);
#pragma unroll
            for (int i = 0; i < 4; i++) CP_ASYNC16(d0 + 16384 + i * 2048, sB + i * 2048);
            CP_COMMIT();
            CP_WAIT1();
        } else {
            CP_WAIT0();
        }
        __syncthreads();

        uint32_t buf = smemS + (kc & 1) * 24576;
        const uint32_t aS = buf, bS = buf + 16384;

#pragma unroll
        for (int ks = 0; ks < 4; ks++) {
            uint32_t af[2][4];
#pragma unroll
            for (int mf = 0; mf < 2; mf++) {
                int row = warp * 32 + mf * 16 + lrow;
                uint32_t sw = (uint32_t)(row * 128 + ks * 32 + cb) ^ ((row & 7) << 4);
                LDMX4(af[mf], aS + sw);
            }
#pragma unroll
            for (int nf2 = 0; nf2 < 4; nf2++) {
                int row = nf2 * 16 + lrow;
                uint32_t sw = (uint32_t)(row * 128 + ks * 32 + cb) ^ ((row & 7) << 4);
                uint32_t bfr[4];
                LDMX4(bfr, bS + sw);
#pragma unroll
                for (int mf = 0; mf < 2; mf++) {
                    mma_f16(acc[mf][2 * nf2],     af[mf][0], af[mf][1], af[mf][2], af[mf][3], bfr[0], bfr[2]);
                    mma_f16(acc[mf][2 * nf2 + 1], af[mf][0], af[mf][1], af[mf][2], af[mf][3], bfr[1], bfr[3]);
                }
            }
        }
    }

    const int r0l = lane >> 2;
    const int c2  = (lane & 3) * 2;

    if (MODE == 0) {
        const int n0 = jcol * 64;
#pragma unroll
        for (int mf = 0; mf < 2; mf++) {
            const int m0 = blockIdx.y * 128 + warp * 32 + mf * 16 + r0l;
#pragma unroll
            for (int nf = 0; nf < 8; nf++) {
                int n = n0 + nf * 8 + c2;
                *(float2*)(Cout + (size_t)m0 * Nt + n)       = make_float2(acc[mf][nf][0], acc[mf][nf][1]);
                *(float2*)(Cout + (size_t)(m0 + 8) * Nt + n) = make_float2(acc[mf][nf][2], acc[mf][nf][3]);
            }
        }
    } else {
        const int which = jcol >> 4;     // 0:q 1:k 2:v
        const int h = jcol & 15;
#pragma unroll
        for (int mf = 0; mf < 2; mf++) {
            const int m0 = blockIdx.y * 128 + warp * 32 + mf * 16 + r0l;
            const int m1 = m0 + 8;
            const int b0i = m0 >> 11, n0i = m0 & 2047;
            const int b1i = m1 >> 11, n1i = m1 & 2047;

            if (which == 2) {
                float* vb = g_v;
#pragma unroll
                for (int nf = 0; nf < 8; nf++) {
                    int dd = nf * 8 + c2;
                    *(float2*)&vb[(((size_t)(b0i * NH + h)) * NSEQ + n0i) * HDIM + dd] =
                        make_float2(acc[mf][nf][0], acc[mf][nf][1]);
                    *(float2*)&vb[(((size_t)(b1i * NH + h)) * NSEQ + n1i) * HDIM + dd] =
                        make_float2(acc[mf][nf][2], acc[mf][nf][3]);
                }
            } else {
                const float* w = (which == 0) ? qw : kw;
                char* df = (which == 0) ? (char*)gQf : (char*)gKf;
                float ss0 = 0.f, ss1 = 0.f;
#pragma unroll
                for (int nf = 0; nf < 8; nf++) {
                    ss0 += acc[mf][nf][0] * acc[mf][nf][0] + acc[mf][nf][1] * acc[mf][nf][1];
                    ss1 += acc[mf][nf][2] * acc[mf][nf][2] + acc[mf][nf][3] * acc[mf][nf][3];
                }
                ss0 += __shfl_xor_sync(0xffffffffu, ss0, 1);
                ss0 += __shfl_xor_sync(0xffffffffu, ss0, 2);
                ss1 += __shfl_xor_sync(0xffffffffu, ss1, 1);
                ss1 += __shfl_xor_sync(0xffffffffu, ss1, 2);
                float r0 = rsqrtf(ss0 * (1.0f / HDIM) + 1e-6f);
                float r1 = rsqrtf(ss1 * (1.0f / HDIM) + 1e-6f);

                size_t tb0 = (((size_t)(b0i * NH + h)) * 16 + (n0i >> 7)) * 16384;
                size_t tb1 = (((size_t)(b1i * NH + h)) * 16 + (n1i >> 7)) * 16384;
                int lr0 = n0i & 127, lr1 = n1i & 127;
                uint32_t x0 = (lr0 & 7) << 4, x1 = (lr1 & 7) << 4;
#pragma unroll
                for (int nf = 0; nf < 8; nf++) {
                    int dd = nf * 8 + c2;
                    float2 wv = *(const float2*)(w + dd);
                    float v0 = acc[mf][nf][0] * r0 * wv.x;
                    float v1 = acc[mf][nf][1] * r0 * wv.y;
                    float v2 = acc[mf][nf][2] * r1 * wv.x;
                    float v3 = acc[mf][nf][3] * r1 * wv.y;
                    uint32_t o0 = (lr0 * 128 + dd * 2) ^ x0;
                    uint32_t o1 = (lr1 * 128 + dd * 2) ^ x1;
                    *(uint32_t*)(df + tb0 + o0) = pack2_f16(v0, v1);
                    *(uint32_t*)(df + tb1 + o1) = pack2_f16(v2, v3);
                }
            }
        }
    }
}

// ---------------- V transpose + fp16 convert ----------------
__global__ void __launch_bounds__(256)
vsplit_kernel()
{
    __shared__ float stg[64][65];
    const int kt = blockIdx.x, bh = blockIdx.y;
    const int tid = threadIdx.x;
    {
        int s = tid >> 2, d0 = (tid & 3) * 16;
        const float* vp = g_v + ((size_t)bh * NSEQ + kt * 64 + s) * HDIM + d0;
#pragma unroll
        for (int i = 0; i < 4; i++) {
            float4 v = *(const float4*)(vp + i * 4);
            stg[s][d0 + i * 4 + 0] = v.x;
            stg[s][d0 + i * 4 + 1] = v.y;
            stg[s][d0 + i * 4 + 2] = v.z;
            stg[s][d0 + i * 4 + 3] = v.w;
        }
    }
    __syncthreads();
    {
        int dR = tid >> 2, c0 = (tid & 3) * 16;
        uint32_t hw[8];
#pragma unroll
        for (int j = 0; j < 8; j++)
            hw[j] = pack2_f16(stg[c0 + 2 * j][dR], stg[c0 + 2 * j + 1][dR]);
        size_t tb = ((size_t)bh * 32 + kt) * 8192;
        uint32_t off0 = dR * 128 + c0 * 2;
        uint32_t x = (dR & 7) << 4;
        *(uint4*)((char*)gVtf + tb + (off0 ^ x))        = make_uint4(hw[0], hw[1], hw[2], hw[3]);
        *(uint4*)((char*)gVtf + tb + ((off0 + 16) ^ x)) = make_uint4(hw[4], hw[5], hw[6], hw[7]);
    }
}

// ---------------- bias precompute ----------------
__global__ void __launch_bounds__(256)
bias_kernel(const float* __restrict__ cm, const float* __restrict__ im)
{
    int bq = blockIdx.x;
    int b = bq / NSEQ, q = bq % NSEQ;
    const float* cmb = cm + (size_t)b * NC * NSEQ;
    float c0 = cmb[q], c1 = cmb[NSEQ + q], c2 = cmb[2 * NSEQ + q], c3 = cmb[3 * NSEQ + q];

    float mx = 0.f;
    for (int k = threadIdx.x; k < NSEQ; k += 256) {
        float s = c0 * cmb[k] + c1 * cmb[NSEQ + k] + c2 * cmb[2 * NSEQ + k] + c3 * cmb[3 * NSEQ + k];
        mx = fmaxf(mx, s);
    }
    __shared__ float red[8];
#pragma unroll
    for (int o = 16; o > 0; o >>= 1) mx = fmaxf(mx, __shfl_xor_sync(0xffffffffu, mx, o));
    if ((threadIdx.x & 31) == 0) red[threadIdx.x >> 5] = mx;
    __syncthreads();
    if (threadIdx.x == 0) {
        float m = red[0];
#pragma unroll
        for (int wN = 1; wN < 8; wN++) m = fmaxf(m, red[wN]);
        red[0] = fmaxf(m, 1e-6f);
    }
    __syncthreads();
    float inv = 1.f / red[0];
    const float* imr = im + (size_t)bq * NSEQ;
    float* br = g_bias + (size_t)bq * NSEQ;
    for (int k = threadIdx.x; k < NSEQ; k += 256) {
        float s = c0 * cmb[k] + c1 * cmb[NSEQ + k] + c2 * cmb[2 * NSEQ + k] + c3 * cmb[3 * NSEQ + k];
        br[k] = 2.f * s * inv - 1.f + 0.3f * imr[k];
    }
}

// ---------------- fp16 HMMA flash attention (round-13 version, kept) ----------------
// 128 threads, 4 warps, warp tile 32q x 64k.
// smem: Qf 16KB | KVbuf0 16KB | KVbuf1 16KB = 48KB.
// Softmax: ex2.approx.f16x2 on packed P pairs; row sums via ones-vector MMA.
#define ATTN2_SMEM (16384 + 2 * 16384)

__global__ void __launch_bounds__(128, 2)
attn2_kernel(const float* __restrict__ gate)
{
    extern __shared__ char smraw[];
    const uint32_t S = smem_u32(smraw);
    const uint32_t BUF0 = S + 16384;
    const int tid = threadIdx.x, lane = tid & 31, warp = tid >> 5;
    const int bh = blockIdx.y, b = bh >> 4, h = bh & 15;
    const int qt = blockIdx.x, q0 = qt * 128;
    const float LOG2E = 1.44269504f;
    const float g32 = 3.f * fminf(fmaxf(gate[h], 0.f), 1.f) * LOG2E;
    const float SC = 0.125f * LOG2E;
    const int lrow = lane & 15, cb = (lane >> 4) << 4;
    const int wrow = warp * 32;

    // prologue: Qf -> S, KV0 -> BUF0
    {
        size_t qoff = ((size_t)(bh * 16 + qt)) * 16384 + tid * 16;
        uint32_t dq = S + tid * 16;
#pragma unroll
        for (int i = 0; i < 8; i++)
            CP_ASYNC16(dq + i * 2048, (const char*)gQf + qoff + i * 2048);
        size_t koff = ((size_t)(bh * 16)) * 16384 + tid * 16;
        size_t voff = ((size_t)(bh * 32)) * 8192 + tid * 16;
        uint32_t dk = BUF0 + tid * 16;
#pragma unroll
        for (int i = 0; i < 4; i++) {
            CP_ASYNC16(dk + i * 2048,        (const char*)gKf  + koff + i * 2048);
            CP_ASYNC16(dk + 8192 + i * 2048, (const char*)gVtf + voff + i * 2048);
        }
        CP_COMMIT();
    }

    CP_WAIT0();
    __syncthreads();

    uint32_t qf[2][4][4];
#pragma unroll
    for (int mf = 0; mf < 2; mf++) {
        int qrow = wrow + mf * 16 + lrow;
        uint32_t qswz = (uint32_t)((qrow & 7) << 4);
#pragma unroll
        for (int ks = 0; ks < 4; ks++) {
            uint32_t sw = (uint32_t)(qrow * 128 + ks * 32 + cb) ^ qswz;
            LDMX4(qf[mf][ks], S + sw);
        }
    }

    float o[2][8][4];
#pragma unroll
    for (int mf = 0; mf < 2; mf++)
#pragma unroll
        for (int nf = 0; nf < 8; nf++)
#pragma unroll
            for (int t = 0; t < 4; t++) o[mf][nf][t] = 0.f;
    float mr[4] = {-1e30f, -1e30f, -1e30f, -1e30f};
    float lr[4] = {0.f, 0.f, 0.f, 0.f};

    const int r0l = lane >> 2;
    const float* biasP[4];
#pragma unroll
    for (int rr = 0; rr < 4; rr++)
        biasP[rr] = g_bias + ((size_t)(b * NSEQ + q0 + wrow + (rr >> 1) * 16 + (rr & 1) * 8 + r0l)) * NSEQ;

    for (int kt = 0; kt < 32; kt++) {
        __syncthreads();
        if (kt + 1 < 32) {
            int k2 = kt + 1;
            size_t koff = ((size_t)(bh * 16 + (k2 >> 1))) * 16384 + (size_t)(k2 & 1) * 8192 + tid * 16;
            size_t voff = ((size_t)(bh * 32 + k2)) * 8192 + tid * 16;
            uint32_t d = BUF0 + (k2 & 1) * 16384 + tid * 16;
#pragma unroll
            for (int i = 0; i < 4; i++) {
                CP_ASYNC16(d + i * 2048,        (const char*)gKf  + koff + i * 2048);
                CP_ASYNC16(d + 8192 + i * 2048, (const char*)gVtf + voff + i * 2048);
            }
            CP_COMMIT();
            CP_WAIT1();
        } else {
            CP_WAIT0();
        }
        __syncthreads();

        uint32_t buf = BUF0 + (kt & 1) * 16384;

        // --- S = Q K^T ---
        float sf[2][8][4];
#pragma unroll
        for (int mf = 0; mf < 2; mf++)
#pragma unroll
            for (int nf = 0; nf < 8; nf++)
#pragma unroll
                for (int t = 0; t < 4; t++) sf[mf][nf][t] = 0.f;

#pragma unroll
        for (int ks = 0; ks < 4; ks++) {
#pragma unroll
            for (int nf2 = 0; nf2 < 4; nf2++) {
                int row = nf2 * 16 + lrow;
                uint32_t sw = (uint32_t)(row * 128 + ks * 32 + cb) ^ ((row & 7) << 4);
                uint32_t kf[4];
                LDMX4(kf, buf + sw);
#pragma unroll
                for (int mf = 0; mf < 2; mf++) {
                    mma_f16(sf[mf][2 * nf2],     qf[mf][ks][0], qf[mf][ks][1], qf[mf][ks][2], qf[mf][ks][3], kf[0], kf[2]);
                    mma_f16(sf[mf][2 * nf2 + 1], qf[mf][ks][0], qf[mf][ks][1], qf[mf][ks][2], qf[mf][ks][3], kf[1], kf[3]);
                }
            }
        }

        // --- scale + gated bias + online softmax (log2 domain, fp16x2 exp, MMA row-sum) ---
        int colbase = kt * 64 + 2 * (lane & 3);
        uint32_t pf[2][4][4];
#pragma unroll
        for (int mf = 0; mf < 2; mf++) {
            float rm0 = -1e30f, rm1 = -1e30f;
#pragma unroll
            for (int nf = 0; nf < 8; nf++) {
                float2 bb0 = *(const float2*)(biasP[2 * mf]     + colbase + nf * 8);
                float2 bb1 = *(const float2*)(biasP[2 * mf + 1] + colbase + nf * 8);
                sf[mf][nf][0] = fmaf(sf[mf][nf][0], SC, g32 * bb0.x);
                sf[mf][nf][1] = fmaf(sf[mf][nf][1], SC, g32 * bb0.y);
                sf[mf][nf][2] = fmaf(sf[mf][nf][2], SC, g32 * bb1.x);
                sf[mf][nf][3] = fmaf(sf[mf][nf][3], SC, g32 * bb1.y);
                rm0 = fmaxf(rm0, fmaxf(sf[mf][nf][0], sf[mf][nf][1]));
                rm1 = fmaxf(rm1, fmaxf(sf[mf][nf][2], sf[mf][nf][3]));
            }
            rm0 = fmaxf(rm0, __shfl_xor_sync(0xffffffffu, rm0, 1));
            rm0 = fmaxf(rm0, __shfl_xor_sync(0xffffffffu, rm0, 2));
            rm1 = fmaxf(rm1, __shfl_xor_sync(0xffffffffu, rm1, 1));
            rm1 = fmaxf(rm1, __shfl_xor_sync(0xffffffffu, rm1, 2));

            float mn0 = fmaxf(mr[2 * mf], rm0), mn1 = fmaxf(mr[2 * mf + 1], rm1);
            float al0 = ex2f(mr[2 * mf] - mn0), al1 = ex2f(mr[2 * mf + 1] - mn1);
            mr[2 * mf] = mn0; mr[2 * mf + 1] = mn1;

            float rsd[4] = {0.f, 0.f, 0.f, 0.f};
#pragma unroll
            for (int kk = 0; kk < 4; kk++) {
                const int na = 2 * kk, nb = 2 * kk + 1;
                pf[mf][kk][0] = ex2_f16x2(pack2_f16(sf[mf][na][0] - mn0, sf[mf][na][1] - mn0));
                pf[mf][kk][1] = ex2_f16x2(pack2_f16(sf[mf][na][2] - mn1, sf[mf][na][3] - mn1));
                pf[mf][kk][2] = ex2_f16x2(pack2_f16(sf[mf][nb][0] - mn0, sf[mf][nb][1] - mn0));
                pf[mf][kk][3] = ex2_f16x2(pack2_f16(sf[mf][nb][2] - mn1, sf[mf][nb][3] - mn1));
                mma_f16(rsd, pf[mf][kk][0], pf[mf][kk][1], pf[mf][kk][2], pf[mf][kk][3], ONES2, ONES2);
            }
            lr[2 * mf]     = lr[2 * mf] * al0 + rsd[0];
            lr[2 * mf + 1] = lr[2 * mf + 1] * al1 + rsd[2];
#pragma unroll
            for (int nf = 0; nf < 8; nf++) {
                o[mf][nf][0] *= al0; o[mf][nf][1] *= al0;
                o[mf][nf][2] *= al1; o[mf][nf][3] *= al1;
            }
        }

        // --- O += P V ---
        const uint32_t vFs = buf + 8192;
#pragma unroll
        for (int kk = 0; kk < 4; kk++) {
#pragma unroll
            for (int nf2 = 0; nf2 < 4; nf2++) {
                int row = nf2 * 16 + lrow;
                uint32_t sw = (uint32_t)(row * 128 + kk * 32 + cb) ^ ((row & 7) << 4);
                uint32_t vf[4];
                LDMX4(vf, vFs + sw);
#pragma unroll
                for (int mf = 0; mf < 2; mf++) {
                    mma_f16(o[mf][2 * nf2],     pf[mf][kk][0], pf[mf][kk][1], pf[mf][kk][2], pf[mf][kk][3], vf[0], vf[2]);
                    mma_f16(o[mf][2 * nf2 + 1], pf[mf][kk][0], pf[mf][kk][1], pf[mf][kk][2], pf[mf][kk][3], vf[1], vf[3]);
                }
            }
        }
    }

    // epilogue: normalize + write fp16 swizzled A-tile for the out-projection
    size_t tb = (((size_t)(b * 16 + qt)) * 16 + h) * 16384;
#pragma unroll
    for (int mf = 0; mf < 2; mf++) {
        float i0 = 1.f / lr[2 * mf], i1 = 1.f / lr[2 * mf + 1];
        int lr0 = wrow + mf * 16 + r0l, lr1 = lr0 + 8;
        uint32_t x0 = (lr0 & 7) << 4, x1 = (lr1 & 7) << 4;
#pragma unroll
        for (int nf = 0; nf < 8; nf++) {
            int dd = nf * 8 + 2 * (lane & 3);
            uint32_t o0 = (lr0 * 128 + dd * 2) ^ x0;
            uint32_t o1 = (lr1 * 128 + dd * 2) ^ x1;
            *(uint32_t*)((char*)gAf + tb + o0) = pack2_f16(o[mf][nf][0] * i0, o[mf][nf][1] * i0);
            *(uint32_t*)((char*)gAf + tb + o1) = pack2_f16(o[mf][nf][2] * i1, o[mf][nf][3] * i1);
        }
    }
}

// ---------------- launch ----------------
extern "C" void kernel_launch(void* const* d_in, const int* in_sizes, int n_in,
                              void* d_out, int out_size)
{
    (void)in_sizes; (void)n_in; (void)out_size;
    const float* x    = (const float*)d_in[0];
    const float* cm   = (const float*)d_in[1];
    const float* im   = (const float*)d_in[2];
    const float* wqkv = (const float*)d_in[3];
    const float* wout = (const float*)d_in[4];
    const float* qnw  = (const float*)d_in[5];
    const float* knw  = (const float*)d_in[6];
    const float* gate = (const float*)d_in[7];
    float* out = (float*)d_out;

    void *xf, *wqf, *wof, *af;
    cudaGetSymbolAddress(&xf, gXf);
    cudaGetSymbolAddress(&wqf, gWqf);
    cudaGetSymbolAddress(&wof, gWof);
    cudaGetSymbolAddress(&af, gAf);

    cudaFuncSetAttribute(attn2_kernel, cudaFuncAttributeMaxDynamicSharedMemorySize, ATTN2_SMEM);
    cudaFuncSetAttribute(gemm_f16<0>, cudaFuncAttributeMaxDynamicSharedMemorySize, GEMM_SMEM);
    cudaFuncSetAttribute(gemm_f16<1>, cudaFuncAttributeMaxDynamicSharedMemorySize, GEMM_SMEM);

    const int M = BB * NSEQ;   // 4096

    // 1) convert inputs to fp16 swizzled tiles
    conv_f16_kernel<<<(4096 * 1024 / 8) / 256, 256>>>(x,    (__half*)xf,  1024);
    conv_f16_kernel<<<(3072 * 1024 / 8) / 256, 256>>>(wqkv, (__half*)wqf, 1024);
    conv_f16_kernel<<<(1024 * 1024 / 8) / 256, 256>>>(wout, (__half*)wof, 1024);

    // 2) QKV projection (fp16 HMMA, 4 CTAs/SM) with fused RMSNorm + fp16 q/k epilogue
    gemm_f16<1><<<dim3(3 * DMOD / 64, M / 128), 128, GEMM_SMEM>>>(
        (const char*)xf, (const char*)wqf, nullptr, 1024 / 64, 3 * DMOD, qnw, knw);

    // 3) V -> transposed fp16 tiles
    vsplit_kernel<<<dim3(NSEQ / 64, BH), 256>>>();

    // 4) bias precompute
    bias_kernel<<<BB * NSEQ, 256>>>(cm, im);

    // 5) fp16 HMMA flash attention (writes fp16 A-tiles for out-proj)
    attn2_kernel<<<dim3(NSEQ / 128, BH), 128, ATTN2_SMEM>>>(gate);

    // 6) out-projection (fp16 HMMA) straight into d_out
    gemm_f16<0><<<dim3(DMOD / 64, M / 128), 128, GEMM_SMEM>>>(
        (const char*)af, (const char*)wof, out, 1024 / 64, DMOD, nullptr, nullptr);
}

// round 16
// speedup vs baseline: 4.3063x; 1.1444x over previous
#include <cuda_runtime.h>
#include <cuda_fp16.h>
#include <math.h>
#include <stdint.h>

#define BB   2
#define NSEQ 2048
#define DMOD 1024
#define NH   16
#define HDIM 64
#define NC   4
#define BH   (BB * NH)

// ---------------- scratch (device globals; no allocation allowed) ----------------
__device__ float g_v[(size_t)BB * NH * NSEQ * HDIM];
__device__ float g_bias[(size_t)BB * NSEQ * NSEQ];
__device__ float g_bmax[(size_t)BB * NSEQ];

// fp16 operands, pre-swizzled 128x64 SW128 tiles (16KB each)
__device__ __half gXf[(size_t)4096 * 1024];
__device__ __half gWqf[(size_t)3072 * 1024];
__device__ __half gWof[(size_t)1024 * 1024];
__device__ __half gAf[(size_t)4096 * 1024];

// attention operands: single fp16, pre-swizzled tiles
__device__ __half gQf[(size_t)BH * NSEQ * HDIM];
__device__ __half gKf[(size_t)BH * NSEQ * HDIM];
__device__ __half gVtf[(size_t)BH * NSEQ * HDIM];

// ---------------- PTX helpers (base sm_103-legal only) ----------------
__device__ __forceinline__ uint32_t smem_u32(const void* p) {
    uint32_t a;
    asm("{ .reg .u64 t; cvta.to.shared.u64 t, %1; cvt.u32.u64 %0, t; }" : "=r"(a) : "l"(p));
    return a;
}

#define CP_ASYNC16(dst, src) \
    asm volatile("cp.async.cg.shared.global [%0], [%1], 16;" :: "r"(dst), "l"(src) : "memory")
#define CP_COMMIT() asm volatile("cp.async.commit_group;" ::: "memory")
#define CP_WAIT0()  asm volatile("cp.async.wait_group 0;" ::: "memory")
#define CP_WAIT1()  asm volatile("cp.async.wait_group 1;" ::: "memory")

#define LDMX4(r, a) \
    asm volatile("ldmatrix.sync.aligned.m8n8.x4.shared.b16 {%0,%1,%2,%3}, [%4];" \
        : "=r"((r)[0]), "=r"((r)[1]), "=r"((r)[2]), "=r"((r)[3]) : "r"(a))

__device__ __forceinline__ void mma_f16(float* d, uint32_t a0, uint32_t a1,
                                        uint32_t a2, uint32_t a3,
                                        uint32_t b0, uint32_t b1) {
    asm volatile(
        "mma.sync.aligned.m16n8k16.row.col.f32.f16.f16.f32 "
        "{%0,%1,%2,%3},{%4,%5,%6,%7},{%8,%9},{%0,%1,%2,%3};"
        : "+f"(d[0]), "+f"(d[1]), "+f"(d[2]), "+f"(d[3])
        : "r"(a0), "r"(a1), "r"(a2), "r"(a3), "r"(b0), "r"(b1));
}

// fp16x2 pack: first arg -> lower half
__device__ __forceinline__ uint32_t pack2_f16(float lo, float hi) {
    uint32_t r;
    asm("cvt.rn.f16x2.f32 %0, %1, %2;" : "=r"(r) : "f"(hi), "f"(lo));
    return r;
}
__device__ __forceinline__ uint32_t ex2_f16x2(uint32_t x) {
    uint32_t r;
    asm("ex2.approx.f16x2 %0, %1;" : "=r"(r) : "r"(x));
    return r;
}

#define ONES2 0x3C003C00u   // fp16x2 {1.0, 1.0}

// ---------------- merged conversion: x, wqkv, wout -> blocked swizzled fp16 tiles ----------------
__global__ void __launch_bounds__(256)
conv3_kernel(const float* __restrict__ x, const float* __restrict__ wq,
             const float* __restrict__ wo)
{
    int bI = blockIdx.x;
    const float* src;
    __half* dst;
    if (bI < 2048)      { src = x;  dst = gXf; }
    else if (bI < 3584) { src = wq; dst = gWqf; bI -= 2048; }
    else                { src = wo; dst = gWof; bI -= 3584; }

    size_t idx = ((size_t)bI * 256 + threadIdx.x) * 8;
    int r  = (int)(idx >> 10);        // K = 1024
    int c0 = (int)(idx & 1023);
    float4 v0 = *(const float4*)(src + idx);
    float4 v1 = *(const float4*)(src + idx + 4);
    uint4 w;
    w.x = pack2_f16(v0.x, v0.y);
    w.y = pack2_f16(v0.z, v0.w);
    w.z = pack2_f16(v1.x, v1.y);
    w.w = pack2_f16(v1.z, v1.w);
    int rt = r >> 7, lr = r & 127, ch = c0 >> 6, lc = c0 & 63;
    size_t tile = (size_t)rt * 16 + ch;
    uint32_t off = lr * 128 + lc * 2;
    uint32_t sw = off ^ ((off >> 3) & 0x70);
    *(uint4*)((char*)dst + tile * 16384 + sw) = w;
}

// ---------------- fp16 HMMA GEMM (round-12 config, measured 74us) ----------------
#define GEMM_SMEM (2 * 24 * 1024)

template <int MODE>
__global__ void __launch_bounds__(128, 4)
gemm_f16(const char* __restrict__ Af, const char* __restrict__ Bf,
         float* __restrict__ Cout, int KC, int Nt,
         const float* __restrict__ qw, const float* __restrict__ kw)
{
    extern __shared__ char smraw[];
    const uint32_t smemS = smem_u32(smraw);
    const int tid  = threadIdx.x;
    const int lane = tid & 31;
    const int warp = tid >> 5;
    const int jcol = blockIdx.x;

    const size_t tA0 = (size_t)blockIdx.y * KC * 16384;
    const size_t tB0 = ((size_t)(jcol >> 1) * KC) * 16384 + (size_t)(jcol & 1) * 8192;

    float acc[2][8][4];
#pragma unroll
    for (int m = 0; m < 2; m++)
#pragma unroll
        for (int j = 0; j < 8; j++)
#pragma unroll
            for (int t = 0; t < 4; t++) acc[m][j][t] = 0.f;

    const int lrow = lane & 15;
    const int cb   = (lane >> 4) << 4;

    {
        const char* sA = Af + tA0 + tid * 16;
        const char* sB = Bf + tB0 + tid * 16;
        uint32_t d0 = smemS + tid * 16;
#pragma unroll
        for (int i = 0; i < 8; i++) CP_ASYNC16(d0 + i * 2048, sA + i * 2048);
#pragma unroll
        for (int i = 0; i < 4; i++) CP_ASYNC16(d0 + 16384 + i * 2048, sB + i * 2048);
        CP_COMMIT();
    }

    for (int kc = 0; kc < KC; kc++) {
        __syncthreads();
        if (kc + 1 < KC) {
            const char* sA = Af + tA0 + (size_t)(kc + 1) * 16384 + tid * 16;
            const char* sB = Bf + tB0 + (size_t)(kc + 1) * 16384 + tid * 16;
            uint32_t d0 = smemS + ((kc + 1) & 1) * 24576 + tid * 16;
#pragma unroll
            for (int i = 0; i < 8; i++) CP_ASYNC16(d0 + i * 2048, sA + i * 2048);
#pragma unroll
            for (int i = 0; i < 4; i++) CP_ASYNC16(d0 + 16384 + i * 2048, sB + i * 2048);
            CP_COMMIT();
            CP_WAIT1();
        } else {
            CP_WAIT0();
        }
        __syncthreads();

        uint32_t buf = smemS + (kc & 1) * 24576;
        const uint32_t aS = buf, bS = buf + 16384;

#pragma unroll
        for (int ks = 0; ks < 4; ks++) {
            uint32_t af[2][4];
#pragma unroll
            for (int mf = 0; mf < 2; mf++) {
                int row = warp * 32 + mf * 16 + lrow;
                uint32_t sw = (uint32_t)(row * 128 + ks * 32 + cb) ^ ((row & 7) << 4);
                LDMX4(af[mf], aS + sw);
            }
#pragma unroll
            for (int nf2 = 0; nf2 < 4; nf2++) {
                int row = nf2 * 16 + lrow;
                uint32_t sw = (uint32_t)(row * 128 + ks * 32 + cb) ^ ((row & 7) << 4);
                uint32_t bfr[4];
                LDMX4(bfr, bS + sw);
#pragma unroll
                for (int mf = 0; mf < 2; mf++) {
                    mma_f16(acc[mf][2 * nf2],     af[mf][0], af[mf][1], af[mf][2], af[mf][3], bfr[0], bfr[2]);
                    mma_f16(acc[mf][2 * nf2 + 1], af[mf][0], af[mf][1], af[mf][2], af[mf][3], bfr[1], bfr[3]);
                }
            }
        }
    }

    const int r0l = lane >> 2;
    const int c2  = (lane & 3) * 2;

    if (MODE == 0) {
        const int n0 = jcol * 64;
#pragma unroll
        for (int mf = 0; mf < 2; mf++) {
            const int m0 = blockIdx.y * 128 + warp * 32 + mf * 16 + r0l;
#pragma unroll
            for (int nf = 0; nf < 8; nf++) {
                int n = n0 + nf * 8 + c2;
                *(float2*)(Cout + (size_t)m0 * Nt + n)       = make_float2(acc[mf][nf][0], acc[mf][nf][1]);
                *(float2*)(Cout + (size_t)(m0 + 8) * Nt + n) = make_float2(acc[mf][nf][2], acc[mf][nf][3]);
            }
        }
    } else {
        const int which = jcol >> 4;     // 0:q 1:k 2:v
        const int h = jcol & 15;
#pragma unroll
        for (int mf = 0; mf < 2; mf++) {
            const int m0 = blockIdx.y * 128 + warp * 32 + mf * 16 + r0l;
            const int m1 = m0 + 8;
            const int b0i = m0 >> 11, n0i = m0 & 2047;
            const int b1i = m1 >> 11, n1i = m1 & 2047;

            if (which == 2) {
                float* vb = g_v;
#pragma unroll
                for (int nf = 0; nf < 8; nf++) {
                    int dd = nf * 8 + c2;
                    *(float2*)&vb[(((size_t)(b0i * NH + h)) * NSEQ + n0i) * HDIM + dd] =
                        make_float2(acc[mf][nf][0], acc[mf][nf][1]);
                    *(float2*)&vb[(((size_t)(b1i * NH + h)) * NSEQ + n1i) * HDIM + dd] =
                        make_float2(acc[mf][nf][2], acc[mf][nf][3]);
                }
            } else {
                const float* w = (which == 0) ? qw : kw;
                char* df = (which == 0) ? (char*)gQf : (char*)gKf;
                float ss0 = 0.f, ss1 = 0.f;
#pragma unroll
                for (int nf = 0; nf < 8; nf++) {
                    ss0 += acc[mf][nf][0] * acc[mf][nf][0] + acc[mf][nf][1] * acc[mf][nf][1];
                    ss1 += acc[mf][nf][2] * acc[mf][nf][2] + acc[mf][nf][3] * acc[mf][nf][3];
                }
                ss0 += __shfl_xor_sync(0xffffffffu, ss0, 1);
                ss0 += __shfl_xor_sync(0xffffffffu, ss0, 2);
                ss1 += __shfl_xor_sync(0xffffffffu, ss1, 1);
                ss1 += __shfl_xor_sync(0xffffffffu, ss1, 2);
                float r0 = rsqrtf(ss0 * (1.0f / HDIM) + 1e-6f);
                float r1 = rsqrtf(ss1 * (1.0f / HDIM) + 1e-6f);

                size_t tb0 = (((size_t)(b0i * NH + h)) * 16 + (n0i >> 7)) * 16384;
                size_t tb1 = (((size_t)(b1i * NH + h)) * 16 + (n1i >> 7)) * 16384;
                int lr0 = n0i & 127, lr1 = n1i & 127;
                uint32_t x0 = (lr0 & 7) << 4, x1 = (lr1 & 7) << 4;
#pragma unroll
                for (int nf = 0; nf < 8; nf++) {
                    int dd = nf * 8 + c2;
                    float2 wv = *(const float2*)(w + dd);
                    float v0 = acc[mf][nf][0] * r0 * wv.x;
                    float v1 = acc[mf][nf][1] * r0 * wv.y;
                    float v2 = acc[mf][nf][2] * r1 * wv.x;
                    float v3 = acc[mf][nf][3] * r1 * wv.y;
                    uint32_t o0 = (lr0 * 128 + dd * 2) ^ x0;
                    uint32_t o1 = (lr1 * 128 + dd * 2) ^ x1;
                    *(uint32_t*)(df + tb0 + o0) = pack2_f16(v0, v1);
                    *(uint32_t*)(df + tb1 + o1) = pack2_f16(v2, v3);
                }
            }
        }
    }
}

// ---------------- V transpose + fp16 convert ----------------
__global__ void __launch_bounds__(256)
vsplit_kernel()
{
    __shared__ float stg[64][65];
    const int kt = blockIdx.x, bh = blockIdx.y;
    const int tid = threadIdx.x;
    {
        int s = tid >> 2, d0 = (tid & 3) * 16;
        const float* vp = g_v + ((size_t)bh * NSEQ + kt * 64 + s) * HDIM + d0;
#pragma unroll
        for (int i = 0; i < 4; i++) {
            float4 v = *(const float4*)(vp + i * 4);
            stg[s][d0 + i * 4 + 0] = v.x;
            stg[s][d0 + i * 4 + 1] = v.y;
            stg[s][d0 + i * 4 + 2] = v.z;
            stg[s][d0 + i * 4 + 3] = v.w;
        }
    }
    __syncthreads();
    {
        int dR = tid >> 2, c0 = (tid & 3) * 16;
        uint32_t hw[8];
#pragma unroll
        for (int j = 0; j < 8; j++)
            hw[j] = pack2_f16(stg[c0 + 2 * j][dR], stg[c0 + 2 * j + 1][dR]);
        size_t tb = ((size_t)bh * 32 + kt) * 8192;
        uint32_t off0 = dR * 128 + c0 * 2;
        uint32_t x = (dR & 7) << 4;
        *(uint4*)((char*)gVtf + tb + (off0 ^ x))        = make_uint4(hw[0], hw[1], hw[2], hw[3]);
        *(uint4*)((char*)gVtf + tb + ((off0 + 16) ^ x)) = make_uint4(hw[4], hw[5], hw[6], hw[7]);
    }
}

// ---------------- bias precompute (register-cached dot products + row max output) ----------------
__global__ void __launch_bounds__(256)
bias_kernel(const float* __restrict__ cm, const float* __restrict__ im)
{
    int bq = blockIdx.x;
    int b = bq / NSEQ, q = bq % NSEQ;
    const float* cmb = cm + (size_t)b * NC * NSEQ;
    float c0 = cmb[q], c1 = cmb[NSEQ + q], c2 = cmb[2 * NSEQ + q], c3 = cmb[3 * NSEQ + q];

    float sv[8];
    float mx = 0.f;
#pragma unroll
    for (int i = 0; i < 8; i++) {
        int k = threadIdx.x + i * 256;
        float s = c0 * cmb[k] + c1 * cmb[NSEQ + k] + c2 * cmb[2 * NSEQ + k] + c3 * cmb[3 * NSEQ + k];
        sv[i] = s;
        mx = fmaxf(mx, s);
    }
    __shared__ float red[8];
#pragma unroll
    for (int o = 16; o > 0; o >>= 1) mx = fmaxf(mx, __shfl_xor_sync(0xffffffffu, mx, o));
    if ((threadIdx.x & 31) == 0) red[threadIdx.x >> 5] = mx;
    __syncthreads();
    if (threadIdx.x == 0) {
        float m = red[0];
#pragma unroll
        for (int wN = 1; wN < 8; wN++) m = fmaxf(m, red[wN]);
        red[0] = fmaxf(m, 1e-6f);
    }
    __syncthreads();
    float inv = 1.f / red[0];
    const float* imr = im + (size_t)bq * NSEQ;
    float* br = g_bias + (size_t)bq * NSEQ;
    float wmax = -1e30f;
#pragma unroll
    for (int i = 0; i < 8; i++) {
        int k = threadIdx.x + i * 256;
        float v = 2.f * sv[i] * inv - 1.f + 0.3f * imr[k];
        br[k] = v;
        wmax = fmaxf(wmax, v);
    }
    __syncthreads();
#pragma unroll
    for (int o = 16; o > 0; o >>= 1) wmax = fmaxf(wmax, __shfl_xor_sync(0xffffffffu, wmax, o));
    if ((threadIdx.x & 31) == 0) red[threadIdx.x >> 5] = wmax;
    __syncthreads();
    if (threadIdx.x == 0) {
        float m = red[0];
#pragma unroll
        for (int wN = 1; wN < 8; wN++) m = fmaxf(m, red[wN]);
        g_bmax[bq] = m;
    }
}

// ---------------- fp16 HMMA flash attention — fixed-bound softmax (no online max) ----------------
// Per-row bound: M = 8*0.125*LOG2E + g32*bmax[q]  >= every logit (|S|<=|q||k|=8 after RMSNorm).
// l accumulates in a persistent ones-vector MMA accumulator; O accumulates un-rescaled.
#define ATTN2_SMEM (16384 + 2 * 16384)

__global__ void __launch_bounds__(128, 2)
attn2_kernel(const float* __restrict__ gate)
{
    extern __shared__ char smraw[];
    const uint32_t S = smem_u32(smraw);
    const uint32_t BUF0 = S + 16384;
    const int tid = threadIdx.x, lane = tid & 31, warp = tid >> 5;
    const int bh = blockIdx.y, b = bh >> 4, h = bh & 15;
    const int qt = blockIdx.x, q0 = qt * 128;
    const float LOG2E = 1.44269504f;
    const float g32 = 3.f * fminf(fmaxf(gate[h], 0.f), 1.f) * LOG2E;
    const float SC = 0.125f * LOG2E;
    const int lrow = lane & 15, cb = (lane >> 4) << 4;
    const int wrow = warp * 32;

    // prologue: Qf -> S, KV0 -> BUF0
    {
        size_t qoff = ((size_t)(bh * 16 + qt)) * 16384 + tid * 16;
        uint32_t dq = S + tid * 16;
#pragma unroll
        for (int i = 0; i < 8; i++)
            CP_ASYNC16(dq + i * 2048, (const char*)gQf + qoff + i * 2048);
        size_t koff = ((size_t)(bh * 16)) * 16384 + tid * 16;
        size_t voff = ((size_t)(bh * 32)) * 8192 + tid * 16;
        uint32_t dk = BUF0 + tid * 16;
#pragma unroll
        for (int i = 0; i < 4; i++) {
            CP_ASYNC16(dk + i * 2048,        (const char*)gKf  + koff + i * 2048);
            CP_ASYNC16(dk + 8192 + i * 2048, (const char*)gVtf + voff + i * 2048);
        }
        CP_COMMIT();
    }

    const int r0l = lane >> 2;
    // per-thread row bounds (log2 domain) and bias row pointers
    float Mrow[4];
    const float* biasP[4];
#pragma unroll
    for (int rr = 0; rr < 4; rr++) {
        int qrow = q0 + wrow + (rr >> 1) * 16 + (rr & 1) * 8 + r0l;
        biasP[rr] = g_bias + ((size_t)(b * NSEQ + qrow)) * NSEQ;
        Mrow[rr] = 8.f * SC + g32 * g_bmax[b * NSEQ + qrow];
    }

    CP_WAIT0();
    __syncthreads();

    uint32_t qf[2][4][4];
#pragma unroll
    for (int mf = 0; mf < 2; mf++) {
        int qrow = wrow + mf * 16 + lrow;
        uint32_t qswz = (uint32_t)((qrow & 7) << 4);
#pragma unroll
        for (int ks = 0; ks < 4; ks++) {
            uint32_t sw = (uint32_t)(qrow * 128 + ks * 32 + cb) ^ qswz;
            LDMX4(qf[mf][ks], S + sw);
        }
    }

    float o[2][8][4];
    float lacc[2][4];
#pragma unroll
    for (int mf = 0; mf < 2; mf++) {
#pragma unroll
        for (int nf = 0; nf < 8; nf++)
#pragma unroll
            for (int t = 0; t < 4; t++) o[mf][nf][t] = 0.f;
#pragma unroll
        for (int t = 0; t < 4; t++) lacc[mf][t] = 0.f;
    }

    for (int kt = 0; kt < 32; kt++) {
        __syncthreads();
        if (kt + 1 < 32) {
            int k2 = kt + 1;
            size_t koff = ((size_t)(bh * 16 + (k2 >> 1))) * 16384 + (size_t)(k2 & 1) * 8192 + tid * 16;
            size_t voff = ((size_t)(bh * 32 + k2)) * 8192 + tid * 16;
            uint32_t d = BUF0 + (k2 & 1) * 16384 + tid * 16;
#pragma unroll
            for (int i = 0; i < 4; i++) {
                CP_ASYNC16(d + i * 2048,        (const char*)gKf  + koff + i * 2048);
                CP_ASYNC16(d + 8192 + i * 2048, (const char*)gVtf + voff + i * 2048);
            }
            CP_COMMIT();
            CP_WAIT1();
        } else {
            CP_WAIT0();
        }
        __syncthreads();

        uint32_t buf = BUF0 + (kt & 1) * 16384;

        // --- S = Q K^T ---
        float sf[2][8][4];
#pragma unroll
        for (int mf = 0; mf < 2; mf++)
#pragma unroll
            for (int nf = 0; nf < 8; nf++)
#pragma unroll
                for (int t = 0; t < 4; t++) sf[mf][nf][t] = 0.f;

#pragma unroll
        for (int ks = 0; ks < 4; ks++) {
#pragma unroll
            for (int nf2 = 0; nf2 < 4; nf2++) {
                int row = nf2 * 16 + lrow;
                uint32_t sw = (uint32_t)(row * 128 + ks * 32 + cb) ^ ((row & 7) << 4);
                uint32_t kf[4];
                LDMX4(kf, buf + sw);
#pragma unroll
                for (int mf = 0; mf < 2; mf++) {
                    mma_f16(sf[mf][2 * nf2],     qf[mf][ks][0], qf[mf][ks][1], qf[mf][ks][2], qf[mf][ks][3], kf[0], kf[2]);
                    mma_f16(sf[mf][2 * nf2 + 1], qf[mf][ks][0], qf[mf][ks][1], qf[mf][ks][2], qf[mf][ks][3], kf[1], kf[3]);
                }
            }
        }

        // --- fixed-bound softmax: P = 2^(S*SC + g32*bias - M); l via ones-MMA ---
        int colbase = kt * 64 + 2 * (lane & 3);
        uint32_t pf[2][4][4];
#pragma unroll
        for (int mf = 0; mf < 2; mf++) {
            const float M0 = Mrow[2 * mf], M1 = Mrow[2 * mf + 1];
#pragma unroll
            for (int kk = 0; kk < 4; kk++) {
                const int na = 2 * kk, nb = 2 * kk + 1;
                float2 ba0 = *(const float2*)(biasP[2 * mf]     + colbase + na * 8);
                float2 ba1 = *(const float2*)(biasP[2 * mf + 1] + colbase + na * 8);
                float2 bb0 = *(const float2*)(biasP[2 * mf]     + colbase + nb * 8);
                float2 bb1 = *(const float2*)(biasP[2 * mf + 1] + colbase + nb * 8);
                float t0 = fmaf(sf[mf][na][0], SC, fmaf(g32, ba0.x, -M0));
                float t1 = fmaf(sf[mf][na][1], SC, fmaf(g32, ba0.y, -M0));
                float t2 = fmaf(sf[mf][na][2], SC, fmaf(g32, ba1.x, -M1));
                float t3 = fmaf(sf[mf][na][3], SC, fmaf(g32, ba1.y, -M1));
                float u0 = fmaf(sf[mf][nb][0], SC, fmaf(g32, bb0.x, -M0));
                float u1 = fmaf(sf[mf][nb][1], SC, fmaf(g32, bb0.y, -M0));
                float u2 = fmaf(sf[mf][nb][2], SC, fmaf(g32, bb1.x, -M1));
                float u3 = fmaf(sf[mf][nb][3], SC, fmaf(g32, bb1.y, -M1));
                pf[mf][kk][0] = ex2_f16x2(pack2_f16(t0, t1));
                pf[mf][kk][1] = ex2_f16x2(pack2_f16(t2, t3));
                pf[mf][kk][2] = ex2_f16x2(pack2_f16(u0, u1));
                pf[mf][kk][3] = ex2_f16x2(pack2_f16(u2, u3));
                mma_f16(lacc[mf], pf[mf][kk][0], pf[mf][kk][1], pf[mf][kk][2], pf[mf][kk][3], ONES2, ONES2);
            }
        }

        // --- O += P V (no rescale) ---
        const uint32_t vFs = buf + 8192;
#pragma unroll
        for (int kk = 0; kk < 4; kk++) {
#pragma unroll
            for (int nf2 = 0; nf2 < 4; nf2++) {
                int row = nf2 * 16 + lrow;
                uint32_t sw = (uint32_t)(row * 128 + kk * 32 + cb) ^ ((row & 7) << 4);
                uint32_t vf[4];
                LDMX4(vf, vFs + sw);
#pragma unroll
                for (int mf = 0; mf < 2; mf++) {
                    mma_f16(o[mf][2 * nf2],     pf[mf][kk][0], pf[mf][kk][1], pf[mf][kk][2], pf[mf][kk][3], vf[0], vf[2]);
                    mma_f16(o[mf][2 * nf2 + 1], pf[mf][kk][0], pf[mf][kk][1], pf[mf][kk][2], pf[mf][kk][3], vf[1], vf[3]);
                }
            }
        }
    }

    // epilogue: normalize + write fp16 swizzled A-tile for the out-projection
    size_t tb = (((size_t)(b * 16 + qt)) * 16 + h) * 16384;
#pragma unroll
    for (int mf = 0; mf < 2; mf++) {
        float i0 = 1.f / lacc[mf][0], i1 = 1.f / lacc[mf][2];
        int lr0 = wrow + mf * 16 + r0l, lr1 = lr0 + 8;
        uint32_t x0 = (lr0 & 7) << 4, x1 = (lr1 & 7) << 4;
#pragma unroll
        for (int nf = 0; nf < 8; nf++) {
            int dd = nf * 8 + 2 * (lane & 3);
            uint32_t o0 = (lr0 * 128 + dd * 2) ^ x0;
            uint32_t o1 = (lr1 * 128 + dd * 2) ^ x1;
            *(uint32_t*)((char*)gAf + tb + o0) = pack2_f16(o[mf][nf][0] * i0, o[mf][nf][1] * i0);
            *(uint32_t*)((char*)gAf + tb + o1) = pack2_f16(o[mf][nf][2] * i1, o[mf][nf][3] * i1);
        }
    }
}

// ---------------- launch ----------------
extern "C" void kernel_launch(void* const* d_in, const int* in_sizes, int n_in,
                              void* d_out, int out_size)
{
    (void)in_sizes; (void)n_in; (void)out_size;
    const float* x    = (const float*)d_in[0];
    const float* cm   = (const float*)d_in[1];
    const float* im   = (const float*)d_in[2];
    const float* wqkv = (const float*)d_in[3];
    const float* wout = (const float*)d_in[4];
    const float* qnw  = (const float*)d_in[5];
    const float* knw  = (const float*)d_in[6];
    const float* gate = (const float*)d_in[7];
    float* out = (float*)d_out;

    void *xf, *wqf, *wof, *af;
    cudaGetSymbolAddress(&xf, gXf);
    cudaGetSymbolAddress(&wqf, gWqf);
    cudaGetSymbolAddress(&wof, gWof);
    cudaGetSymbolAddress(&af, gAf);

    cudaFuncSetAttribute(attn2_kernel, cudaFuncAttributeMaxDynamicSharedMemorySize, ATTN2_SMEM);
    cudaFuncSetAttribute(gemm_f16<0>, cudaFuncAttributeMaxDynamicSharedMemorySize, GEMM_SMEM);
    cudaFuncSetAttribute(gemm_f16<1>, cudaFuncAttributeMaxDynamicSharedMemorySize, GEMM_SMEM);

    const int M = BB * NSEQ;   // 4096

    // 1) convert all fp32 operands to fp16 swizzled tiles (one launch)
    conv3_kernel<<<4096, 256>>>(x, wqkv, wout);

    // 2) QKV projection (fp16 HMMA) with fused RMSNorm + fp16 q/k epilogue
    gemm_f16<1><<<dim3(3 * DMOD / 64, M / 128), 128, GEMM_SMEM>>>(
        (const char*)xf, (const char*)wqf, nullptr, 1024 / 64, 3 * DMOD, qnw, knw);

    // 3) V -> transposed fp16 tiles
    vsplit_kernel<<<dim3(NSEQ / 64, BH), 256>>>();

    // 4) bias precompute (+ per-row max for the fixed softmax bound)
    bias_kernel<<<BB * NSEQ, 256>>>(cm, im);

    // 5) fp16 HMMA flash attention (fixed-bound softmax; writes fp16 A-tiles)
    attn2_kernel<<<dim3(NSEQ / 128, BH), 128, ATTN2_SMEM>>>(gate);

    // 6) out-projection (fp16 HMMA) straight into d_out
    gemm_f16<0><<<dim3(DMOD / 64, M / 128), 128, GEMM_SMEM>>>(
        (const char*)af, (const char*)wof, out, 1024 / 64, DMOD, nullptr, nullptr);
}